// round 9
// baseline (speedup 1.0000x reference)
#include <cuda_runtime.h>
#include <cuda_bf16.h>
#include <math.h>
#include <stdint.h>

// ---------------- problem dims ----------------
#define NB 32
#define NC 512
#define NT 1024
#define NE 512
#define ND 2048
#define NH 8
#define HD 64
#define NSTEP 50
#define NOUT 1000
#define NA_ 512
#define NO_ 512

#define PRED_ELEMS (NB*NOUT*NSTEP)
#define CERT_BASE  PRED_ELEMS
#define SYNC_BASE  (CERT_BASE + NB*2*NSTEP)

typedef __nv_bfloat16 bf16;
typedef __nv_bfloat162 bf162;

// ---------------- device scratch ----------------
__device__ float buf_kv   [NB*NT*NE];
__device__ bf16  buf_Kh   [NB*NT*NE];   // K^T head-major bf16: [b][h][d][n]
__device__ bf16  buf_Vh   [NB*NT*NE];   // V head-major bf16: [b][h][n][d]
__device__ float buf_act  [NB*ND];
__device__ float buf_aA   [2*NB*NA_];
__device__ float buf_bA   [2*NB*NA_];
__device__ float buf_aO   [2*NB*NO_];
__device__ float buf_bO   [2*NB*NO_];
__device__ float buf_attno[NB*NE];
__device__ float buf_hpm  [NB*ND];
__device__ float buf_Wqq  [NE*NE];
__device__ float buf_bqq  [NE];
// split-K partials
__device__ float buf_qpart    [8*32*NE];
__device__ float buf_attnopart[8*32*NE];
__device__ float buf_hpart    [8*32*2*ND];
__device__ float buf_w1part   [4*32*ND];
__device__ float buf_w2part   [4*32*ND];
__device__ float buf_predpart [4*32*NOUT];
// attention partials
__device__ float buf_pv[NB*NH*8*HD];
__device__ float buf_pm[NB*NH*8];
__device__ float buf_ps[NB*NH*8];

// ---------------- cp.async helpers ----------------
__device__ __forceinline__ void cp16(void* smem, const void* gmem) {
    uint32_t s = (uint32_t)__cvta_generic_to_shared(smem);
    asm volatile("cp.async.cg.shared.global [%0], [%1], 16;\n" :: "r"(s), "l"(gmem));
}
#define CP_COMMIT() asm volatile("cp.async.commit_group;\n" ::: "memory")
#define CP_WAIT2()  asm volatile("cp.async.wait_group 2;\n" ::: "memory")
#define CP_WAIT1()  asm volatile("cp.async.wait_group 1;\n" ::: "memory")

// ---------------- tf32 mma helpers ----------------
__device__ __forceinline__ uint32_t f2tf(float x) {
    uint32_t r;
    asm("cvt.rna.tf32.f32 %0, %1;" : "=r"(r) : "f"(x));
    return r;
}
__device__ __forceinline__ void mma_tf32(float* c, const uint32_t* a, const uint32_t* b) {
    asm volatile(
        "mma.sync.aligned.m16n8k8.row.col.f32.tf32.tf32.f32 "
        "{%0,%1,%2,%3},{%4,%5,%6,%7},{%8,%9},{%0,%1,%2,%3};"
        : "+f"(c[0]), "+f"(c[1]), "+f"(c[2]), "+f"(c[3])
        : "r"(a[0]), "r"(a[1]), "r"(a[2]), "r"(a[3]), "r"(b[0]), "r"(b[1]));
}

// ---------------- block reductions ----------------
__device__ __forceinline__ float blockReduceSum(float v) {
    __shared__ float shs[32];
    int lane = threadIdx.x & 31, w = threadIdx.x >> 5;
    #pragma unroll
    for (int o = 16; o; o >>= 1) v += __shfl_xor_sync(0xffffffffu, v, o);
    if (lane == 0) shs[w] = v;
    __syncthreads();
    float r = 0.f;
    int nw = (blockDim.x + 31) >> 5;
    if (threadIdx.x < nw) r = shs[threadIdx.x];
    if (w == 0) {
        #pragma unroll
        for (int o = 16; o; o >>= 1) r += __shfl_xor_sync(0xffffffffu, r, o);
        if (lane == 0) shs[0] = r;
    }
    __syncthreads();
    float out = shs[0];
    __syncthreads();
    return out;
}
__device__ __forceinline__ float blockReduceMax(float v) {
    __shared__ float shm[32];
    int lane = threadIdx.x & 31, w = threadIdx.x >> 5;
    #pragma unroll
    for (int o = 16; o; o >>= 1) v = fmaxf(v, __shfl_xor_sync(0xffffffffu, v, o));
    if (lane == 0) shm[w] = v;
    __syncthreads();
    float r = -1e30f;
    int nw = (blockDim.x + 31) >> 5;
    if (threadIdx.x < nw) r = shm[threadIdx.x];
    if (w == 0) {
        #pragma unroll
        for (int o = 16; o; o >>= 1) r = fmaxf(r, __shfl_xor_sync(0xffffffffu, r, o));
        if (lane == 0) shm[0] = r;
    }
    __syncthreads();
    float out = shm[0];
    __syncthreads();
    return out;
}

// ======================================================================
// tf32 GEMM, A transposed in gmem (fuses (B,C,N)->(B,N,C) transpose)
// ======================================================================
__global__ void gemm_at_tf32(const float* __restrict__ X,
                             const float* __restrict__ B, int ldb,
                             const float* __restrict__ bias,
                             float* __restrict__ C, int ldc, int K) {
    __shared__ float As2[2][16][136];
    __shared__ float Bs[2][16][68];
    const int tid = threadIdx.x;
    const int wid = tid >> 5, lane = tid & 31;
    const int g = lane >> 2, tg = lane & 3;
    const int warp_m = wid >> 1, warp_n = wid & 1;
    const int row0 = blockIdx.y * 128;
    const int col0 = blockIdx.x * 64;
    const int bb_ = row0 >> 10, n0 = row0 & 1023;
    const float* Xb = X + (size_t)bb_ * NC * NT;

    const int la_k = tid >> 4;
    const int la_n = (tid & 15) * 8;
    const int lb_r = tid >> 4;
    const int lb_c = (tid & 15) * 4;

    float acc[2][4][4];
    #pragma unroll
    for (int mi = 0; mi < 2; mi++)
        #pragma unroll
        for (int ni = 0; ni < 4; ni++)
            #pragma unroll
            for (int j = 0; j < 4; j++) acc[mi][ni][j] = 0.f;

    const int ntiles = K >> 4;
    {
        const float* ap = Xb + (size_t)la_k * NT + n0 + la_n;
        cp16(&As2[0][la_k][la_n], ap);
        cp16(&As2[0][la_k][la_n + 4], ap + 4);
        cp16(&Bs[0][lb_r][lb_c], B + (size_t)lb_r * ldb + col0 + lb_c);
    }
    CP_COMMIT();

    for (int ct = 0; ct < ntiles; ct++) {
        if (ct + 1 < ntiles) {
            int k0 = (ct + 1) << 4;
            int st = (ct + 1) & 1;
            const float* ap = Xb + (size_t)(k0 + la_k) * NT + n0 + la_n;
            cp16(&As2[st][la_k][la_n], ap);
            cp16(&As2[st][la_k][la_n + 4], ap + 4);
            cp16(&Bs[st][lb_r][lb_c], B + (size_t)(k0 + lb_r) * ldb + col0 + lb_c);
        }
        CP_COMMIT();
        CP_WAIT1();
        __syncthreads();
        const int st = ct & 1;
        #pragma unroll
        for (int ks = 0; ks < 2; ks++) {
            const int k8 = ks * 8;
            uint32_t a[2][4], bf[4][2];
            #pragma unroll
            for (int mi = 0; mi < 2; mi++) {
                int r = warp_m * 32 + mi * 16 + g;
                a[mi][0] = f2tf(As2[st][k8 + tg][r]);
                a[mi][1] = f2tf(As2[st][k8 + tg][r + 8]);
                a[mi][2] = f2tf(As2[st][k8 + tg + 4][r]);
                a[mi][3] = f2tf(As2[st][k8 + tg + 4][r + 8]);
            }
            #pragma unroll
            for (int ni = 0; ni < 4; ni++) {
                int c = warp_n * 32 + ni * 8 + g;
                bf[ni][0] = f2tf(Bs[st][k8 + tg][c]);
                bf[ni][1] = f2tf(Bs[st][k8 + tg + 4][c]);
            }
            #pragma unroll
            for (int mi = 0; mi < 2; mi++)
                #pragma unroll
                for (int ni = 0; ni < 4; ni++)
                    mma_tf32(acc[mi][ni], a[mi], bf[ni]);
        }
        __syncthreads();
    }

    #pragma unroll
    for (int mi = 0; mi < 2; mi++)
        #pragma unroll
        for (int ni = 0; ni < 4; ni++) {
            int r = row0 + warp_m * 32 + mi * 16 + g;
            int c = col0 + warp_n * 32 + ni * 8 + 2 * tg;
            float b0 = bias ? bias[c] : 0.f;
            float b1 = bias ? bias[c + 1] : 0.f;
            C[(size_t)r * ldc + c] = acc[mi][ni][0] + b0;
            C[(size_t)r * ldc + c + 1] = acc[mi][ni][1] + b1;
            C[(size_t)(r + 8) * ldc + c] = acc[mi][ni][2] + b0;
            C[(size_t)(r + 8) * ldc + c + 1] = acc[mi][ni][3] + b1;
        }
}

// ---------------- tf32 GEMM row-major A --------------------------------
// kvmode: 0 plain fp32; 1 K^T bf16 scatter [b][h][d][n]; 2 V bf16 scatter
__global__ void gemm_tf32(const float* __restrict__ A, int lda,
                          const float* __restrict__ B, int ldb,
                          const float* __restrict__ bias,
                          float* __restrict__ C, bf16* __restrict__ Ch,
                          int ldc, int K, int kvmode) {
    __shared__ float As[2][128][20];
    __shared__ float Bs[2][16][68];
    const int tid = threadIdx.x;
    const int wid = tid >> 5, lane = tid & 31;
    const int g = lane >> 2, tg = lane & 3;
    const int warp_m = wid >> 1, warp_n = wid & 1;
    const int row0 = blockIdx.y * 128;
    const int col0 = blockIdx.x * 64;

    const int la_r = tid >> 1;
    const int la_c = (tid & 1) * 8;
    const int lb_r = tid >> 4;
    const int lb_c = (tid & 15) * 4;

    float acc[2][4][4];
    #pragma unroll
    for (int mi = 0; mi < 2; mi++)
        #pragma unroll
        for (int ni = 0; ni < 4; ni++)
            #pragma unroll
            for (int j = 0; j < 4; j++) acc[mi][ni][j] = 0.f;

    const int ntiles = K >> 4;
    {
        const float* ap = A + (size_t)(row0 + la_r) * lda + la_c;
        cp16(&As[0][la_r][la_c], ap);
        cp16(&As[0][la_r][la_c + 4], ap + 4);
        cp16(&Bs[0][lb_r][lb_c], B + (size_t)lb_r * ldb + col0 + lb_c);
    }
    CP_COMMIT();

    for (int ct = 0; ct < ntiles; ct++) {
        if (ct + 1 < ntiles) {
            int k0 = (ct + 1) << 4;
            int st = (ct + 1) & 1;
            const float* ap = A + (size_t)(row0 + la_r) * lda + k0 + la_c;
            cp16(&As[st][la_r][la_c], ap);
            cp16(&As[st][la_r][la_c + 4], ap + 4);
            cp16(&Bs[st][lb_r][lb_c], B + (size_t)(k0 + lb_r) * ldb + col0 + lb_c);
        }
        CP_COMMIT();
        CP_WAIT1();
        __syncthreads();
        const int st = ct & 1;
        #pragma unroll
        for (int ks = 0; ks < 2; ks++) {
            const int k8 = ks * 8;
            uint32_t a[2][4], bf[4][2];
            #pragma unroll
            for (int mi = 0; mi < 2; mi++) {
                int r = warp_m * 32 + mi * 16 + g;
                a[mi][0] = f2tf(As[st][r][k8 + tg]);
                a[mi][1] = f2tf(As[st][r + 8][k8 + tg]);
                a[mi][2] = f2tf(As[st][r][k8 + tg + 4]);
                a[mi][3] = f2tf(As[st][r + 8][k8 + tg + 4]);
            }
            #pragma unroll
            for (int ni = 0; ni < 4; ni++) {
                int c = warp_n * 32 + ni * 8 + g;
                bf[ni][0] = f2tf(Bs[st][k8 + tg][c]);
                bf[ni][1] = f2tf(Bs[st][k8 + tg + 4][c]);
            }
            #pragma unroll
            for (int mi = 0; mi < 2; mi++)
                #pragma unroll
                for (int ni = 0; ni < 4; ni++)
                    mma_tf32(acc[mi][ni], a[mi], bf[ni]);
        }
        __syncthreads();
    }

    #pragma unroll
    for (int mi = 0; mi < 2; mi++) {
        #pragma unroll
        for (int ni = 0; ni < 4; ni++) {
            int r = row0 + warp_m * 32 + mi * 16 + g;
            int c = col0 + warp_n * 32 + ni * 8 + 2 * tg;
            float b0 = bias ? bias[c] : 0.f;
            float b1 = bias ? bias[c + 1] : 0.f;
            float v00 = acc[mi][ni][0] + b0, v01 = acc[mi][ni][1] + b1;
            float v10 = acc[mi][ni][2] + b0, v11 = acc[mi][ni][3] + b1;
            #pragma unroll
            for (int rr = 0; rr < 2; rr++) {
                int row = r + rr * 8;
                float va = rr ? v10 : v00;
                float vb = rr ? v11 : v01;
                if (kvmode == 0) {
                    C[(size_t)row * ldc + c] = va;
                    C[(size_t)row * ldc + c + 1] = vb;
                } else if (kvmode == 1) {
                    int b = row >> 10, n = row & 1023;
                    int h0 = c >> 6, d0 = c & 63;
                    int h1 = (c + 1) >> 6, d1 = (c + 1) & 63;
                    Ch[(((size_t)(b * NH + h0)) * HD + d0) * NT + n] = __float2bfloat16(va);
                    Ch[(((size_t)(b * NH + h1)) * HD + d1) * NT + n] = __float2bfloat16(vb);
                } else {
                    int b = row >> 10, n = row & 1023;
                    int h0 = c >> 6, d0 = c & 63;
                    int h1 = (c + 1) >> 6, d1 = (c + 1) & 63;
                    Ch[((((size_t)b * NH + h0) << 10) + n) * HD + d0] = __float2bfloat16(va);
                    Ch[((((size_t)b * NH + h1) << 10) + n) * HD + d1] = __float2bfloat16(vb);
                }
            }
        }
    }
}

// ---------------- row LayerNorm ----------------
__global__ void ln_rows(float* __restrict__ X, int L,
                        const float* __restrict__ g, const float* __restrict__ b) {
    int row = blockIdx.x;
    float* xp = X + (size_t)row * L;
    float s = 0.f;
    for (int i = threadIdx.x; i < L; i += blockDim.x) s += xp[i];
    s = blockReduceSum(s);
    float m = s / L;
    float v = 0.f;
    for (int i = threadIdx.x; i < L; i += blockDim.x) { float d = xp[i] - m; v += d * d; }
    v = blockReduceSum(v);
    float inv = rsqrtf(v / L + 1e-5f);
    for (int i = threadIdx.x; i < L; i += blockDim.x)
        xp[i] = (xp[i] - m) * inv * g[i] + b[i];
}

__global__ void make_bqq(const float* __restrict__ b_q, const float* __restrict__ W_in,
                         const float* __restrict__ b_in) {
    int j = blockIdx.x * blockDim.x + threadIdx.x;
    if (j >= NE) return;
    float s = b_in[j];
    for (int k = 0; k < NE; k++) s += b_q[k] * W_in[(size_t)k * (3 * NE) + j];
    buf_bqq[j] = s;
}

__global__ void init_state(const float* __restrict__ start) {
    int i = blockIdx.x * blockDim.x + threadIdx.x;
    if (i < NB * ND) buf_act[i] = start[i & (ND - 1)];
    if (i < NB * NA_) {
        buf_aA[i] = 0.f; buf_bA[i] = 0.f;
        buf_aO[i] = 0.f; buf_bO[i] = 0.f;
    }
}

// ======================================================================
// Fused light skinny GEMM (fp32 B).
// modes: 1 = syncA update (gather act)
//        2 = attention softmax-combine (head = kstart>>6, Kper=64)
//        6 = syncO update from gather-reduce of w2part (+rbias, relu)
// ======================================================================
#define SKS 4
__global__ void skinny_fused(int mode,
                             const float* __restrict__ A0, int lda,
                             const int* __restrict__ idx, const float* __restrict__ decay,
                             const float* __restrict__ st_a_in, const float* __restrict__ st_b_in,
                             float* __restrict__ st_a_out, float* __restrict__ st_b_out,
                             float* __restrict__ sync_final,
                             const float* __restrict__ rbias,
                             const float* __restrict__ B, int ldb,
                             float* __restrict__ partout, int Nout, int Kper) {
    __shared__ float As[32][129];
    __shared__ float Bs[SKS][16][64];
    __shared__ float wno[32][8];
    __shared__ float Tinv[32];
    const int tid = threadIdx.x;
    const int col0 = blockIdx.x * 64;
    const int kstart = blockIdx.y * Kper;
    const int ntiles = Kper >> 4;
    const int kshift = (Kper == 64) ? 6 : 7;

    const int bkk = tid >> 4, bc = (tid & 15) * 4;
    int bcol = col0 + bc;
    if (bcol > Nout - 4) bcol = Nout - 4;
    #pragma unroll
    for (int pt = 0; pt < SKS - 1; pt++) {
        if (pt < ntiles)
            cp16(&Bs[pt][bkk][bc], B + (size_t)(kstart + pt * 16 + bkk) * ldb + bcol);
        CP_COMMIT();
    }

    if (mode == 2) {
        if (tid < 32) {
            int h = kstart >> 6, b = tid;
            float M = -1e30f;
            #pragma unroll
            for (int c = 0; c < 8; c++) M = fmaxf(M, buf_pm[(b * NH + h) * 8 + c]);
            float T = 0.f;
            #pragma unroll
            for (int c = 0; c < 8; c++) {
                float w = expf(buf_pm[(b * NH + h) * 8 + c] - M);
                wno[b][c] = w;
                T += buf_ps[(b * NH + h) * 8 + c] * w;
            }
            Tinv[b] = 1.f / T;
        }
        __syncthreads();
    }

    // ---- A build ----
    for (int e = tid; e < 32 * Kper; e += 256) {
        int r = e >> kshift;
        int j = e & (Kper - 1);
        int k = kstart + j;
        float v;
        if (mode == 2) {
            int h = kstart >> 6;
            const float* pvp = buf_pv + ((size_t)(r * NH + h) * 8) * HD + j;
            float acc = 0.f;
            #pragma unroll
            for (int c = 0; c < 8; c++) acc += pvp[c * HD] * wno[r][c];
            v = acc * Tinv[r];
        } else if (mode == 6) {
            int jj = idx[k];
            float av = rbias[jj];
            #pragma unroll
            for (int s = 0; s < 4; s++)
                av += A0[((size_t)s * 32 + r) * lda + jj];
            float sel = fmaxf(av, 0.f);
            float rr = expf(-fminf(fmaxf(decay[k], 0.f), 15.f));
            float a = rr * st_a_in[r * 512 + k] + sel * sel;
            float bb = rr * st_b_in[r * 512 + k] + 1.f;
            st_a_out[r * 512 + k] = a;
            st_b_out[r * 512 + k] = bb;
            v = a * rsqrtf(bb);
            if (sync_final) sync_final[r * 512 + k] = v;
        } else { // mode 1
            float rr = expf(-fminf(fmaxf(decay[k], 0.f), 15.f));
            float sel = A0[(size_t)r * lda + idx[k]];
            float a = rr * st_a_in[r * 512 + k] + sel * sel;
            float bb = rr * st_b_in[r * 512 + k] + 1.f;
            st_a_out[r * 512 + k] = a;
            st_b_out[r * 512 + k] = bb;
            v = a * rsqrtf(bb);
            if (sync_final) sync_final[r * 512 + k] = v;
        }
        As[r][j] = v;
    }
    __syncthreads();

    // ---- B streaming + FMA ----
    const int c4 = (tid & 15) * 4;
    const int r0 = (tid >> 4) * 2;
    float acc0[4] = {0.f, 0.f, 0.f, 0.f};
    float acc1[4] = {0.f, 0.f, 0.f, 0.f};

    for (int ct = 0; ct < ntiles; ct++) {
        CP_WAIT2();
        __syncthreads();
        const int st = ct & (SKS - 1);
        const float* a0p = &As[r0][ct * 16];
        const float* a1p = &As[r0 + 1][ct * 16];
        #pragma unroll
        for (int kk = 0; kk < 16; kk++) {
            float4 bv = *(const float4*)&Bs[st][kk][c4];
            float a0 = a0p[kk], a1 = a1p[kk];
            acc0[0] += a0 * bv.x; acc0[1] += a0 * bv.y;
            acc0[2] += a0 * bv.z; acc0[3] += a0 * bv.w;
            acc1[0] += a1 * bv.x; acc1[1] += a1 * bv.y;
            acc1[2] += a1 * bv.z; acc1[3] += a1 * bv.w;
        }
        __syncthreads();
        int nt = ct + SKS - 1;
        if (nt < ntiles)
            cp16(&Bs[nt & (SKS - 1)][bkk][bc], B + (size_t)(kstart + nt * 16 + bkk) * ldb + bcol);
        CP_COMMIT();
    }

    float* po = partout + ((size_t)blockIdx.y * 32 + r0) * Nout;
    #pragma unroll
    for (int j = 0; j < 4; j++) {
        int c = col0 + c4 + j;
        if (c < Nout) {
            po[c] = acc0[j];
            po[Nout + c] = acc1[j];
        }
    }
}

// ---------------- pipelined split-K skinny GEMM (fp32 B, plain/concat A) --
__global__ void skinny_gemm(const float* __restrict__ A0, int K0,
                            const float* __restrict__ A1, int K1,
                            const float* __restrict__ B, int ldb,
                            float* __restrict__ part, int Nout, int Kper) {
    __shared__ float As[SKS][32][16];
    __shared__ float Bs[SKS][16][64];
    const int tid = threadIdx.x;
    const int col0 = blockIdx.x * 64;
    const int kstart = blockIdx.y * Kper;
    const int ntiles = Kper >> 4;

    const int b_kk = tid >> 4;
    const int b_c  = (tid & 15) * 4;
    const int a_r  = tid >> 2;
    const int a_kc = (tid & 3) * 4;
    int bcol = col0 + b_c;
    if (bcol > Nout - 4) bcol = Nout - 4;

    const int c4 = (tid & 15) * 4;
    const int r0 = (tid >> 4) * 2;

    float acc0[4] = {0.f, 0.f, 0.f, 0.f};
    float acc1[4] = {0.f, 0.f, 0.f, 0.f};

    #pragma unroll
    for (int pt = 0; pt < SKS - 1; pt++) {
        if (pt < ntiles) {
            int kb = kstart + pt * 16;
            cp16(&Bs[pt][b_kk][b_c], B + (size_t)(kb + b_kk) * ldb + bcol);
            if (tid < 128) {
                int k = kb + a_kc;
                const float* src = (k < K0) ? (A0 + (size_t)a_r * K0 + k)
                                            : (A1 + (size_t)a_r * K1 + (k - K0));
                cp16(&As[pt][a_r][a_kc], src);
            }
        }
        CP_COMMIT();
    }

    for (int ct = 0; ct < ntiles; ct++) {
        CP_WAIT2();
        __syncthreads();
        const int st = ct & (SKS - 1);
        #pragma unroll
        for (int kk = 0; kk < 16; kk++) {
            float4 bv = *(const float4*)&Bs[st][kk][c4];
            float a0 = As[st][r0][kk];
            float a1 = As[st][r0 + 1][kk];
            acc0[0] += a0 * bv.x; acc0[1] += a0 * bv.y;
            acc0[2] += a0 * bv.z; acc0[3] += a0 * bv.w;
            acc1[0] += a1 * bv.x; acc1[1] += a1 * bv.y;
            acc1[2] += a1 * bv.z; acc1[3] += a1 * bv.w;
        }
        __syncthreads();
        int nt = ct + SKS - 1;
        if (nt < ntiles) {
            int kb = kstart + nt * 16;
            int st2 = nt & (SKS - 1);
            cp16(&Bs[st2][b_kk][b_c], B + (size_t)(kb + b_kk) * ldb + bcol);
            if (tid < 128) {
                int k = kb + a_kc;
                const float* src = (k < K0) ? (A0 + (size_t)a_r * K0 + k)
                                            : (A1 + (size_t)a_r * K1 + (k - K0));
                cp16(&As[st2][a_r][a_kc], src);
            }
        }
        CP_COMMIT();
    }

    float* po = part + ((size_t)blockIdx.y * 32 + r0) * Nout;
    #pragma unroll
    for (int j = 0; j < 4; j++) {
        int c = col0 + c4 + j;
        if (c < Nout) {
            po[c] = acc0[j];
            po[Nout + c] = acc1[j];
        }
    }
}

// ======================================================================
// skinny GEMM with fused A = relu(abias + sum of 4 partials), pipelined.
// 3-stage: partial A tiles staged via cp.async alongside B tiles.
// ======================================================================
#define RKS 3
__global__ void skinny_gemm_red(const float* __restrict__ part, int ldp,
                                const float* __restrict__ abias,
                                const float* __restrict__ B, int ldb,
                                float* __restrict__ partout, int Nout, int Kper) {
    __shared__ float Ap[RKS][4][32][16];
    __shared__ float As[32][17];
    __shared__ float Bs[RKS][16][64];
    const int tid = threadIdx.x;
    const int col0 = blockIdx.x * 64;
    const int kstart = blockIdx.y * Kper;
    const int ntiles = Kper >> 4;

    // B loader mapping
    const int b_kk = tid >> 4, b_c = (tid & 15) * 4;
    int bcol = col0 + b_c;
    if (bcol > Nout - 4) bcol = Nout - 4;
    // A-partial loader mapping: e = tid + i*256, i<2
    // q = e&3 (16B quarter), r = (e>>2)&31, s = e>>7
    const int aq = (tid & 3) * 4;
    const int ar = (tid >> 2) & 31;
    const int as0 = tid >> 7;          // 0 or 1; +2 for second elem

    const int c4 = (tid & 15) * 4;
    const int r0 = (tid >> 4) * 2;

    float acc0[4] = {0.f, 0.f, 0.f, 0.f};
    float acc1[4] = {0.f, 0.f, 0.f, 0.f};

    // prologue: 2 tiles
    #pragma unroll
    for (int pt = 0; pt < RKS - 1; pt++) {
        if (pt < ntiles) {
            int kb = kstart + pt * 16;
            cp16(&Bs[pt][b_kk][b_c], B + (size_t)(kb + b_kk) * ldb + bcol);
            cp16(&Ap[pt][as0][ar][aq], part + ((size_t)as0 * 32 + ar) * ldp + kb + aq);
            cp16(&Ap[pt][as0 + 2][ar][aq], part + ((size_t)(as0 + 2) * 32 + ar) * ldp + kb + aq);
        }
        CP_COMMIT();
    }

    for (int ct = 0; ct < ntiles; ct++) {
        CP_WAIT1();
        __syncthreads();
        const int st = ct % RKS;
        // reduce A tile: 512 elems, 2 per thread
        {
            int k0 = kstart + ct * 16;
            #pragma unroll
            for (int i = 0; i < 2; i++) {
                int o = tid + i * 256;
                int rr = o >> 4, kk = o & 15;
                float v = abias[k0 + kk]
                        + Ap[st][0][rr][kk] + Ap[st][1][rr][kk]
                        + Ap[st][2][rr][kk] + Ap[st][3][rr][kk];
                As[rr][kk] = fmaxf(v, 0.f);
            }
        }
        __syncthreads();
        #pragma unroll
        for (int kk = 0; kk < 16; kk++) {
            float4 bv = *(const float4*)&Bs[st][kk][c4];
            float a0 = As[r0][kk];
            float a1 = As[r0 + 1][kk];
            acc0[0] += a0 * bv.x; acc0[1] += a0 * bv.y;
            acc0[2] += a0 * bv.z; acc0[3] += a0 * bv.w;
            acc1[0] += a1 * bv.x; acc1[1] += a1 * bv.y;
            acc1[2] += a1 * bv.z; acc1[3] += a1 * bv.w;
        }
        __syncthreads();
        int nt = ct + RKS - 1;
        if (nt < ntiles) {
            int kb = kstart + nt * 16;
            int st2 = nt % RKS;
            cp16(&Bs[st2][b_kk][b_c], B + (size_t)(kb + b_kk) * ldb + bcol);
            cp16(&Ap[st2][as0][ar][aq], part + ((size_t)as0 * 32 + ar) * ldp + kb + aq);
            cp16(&Ap[st2][as0 + 2][ar][aq], part + ((size_t)(as0 + 2) * 32 + ar) * ldp + kb + aq);
        }
        CP_COMMIT();
    }

    float* po = partout + ((size_t)blockIdx.y * 32 + r0) * Nout;
    #pragma unroll
    for (int j = 0; j < 4; j++) {
        int c = col0 + c4 + j;
        if (c < Nout) {
            po[c] = acc0[j];
            po[Nout + c] = acc1[j];
        }
    }
}

// ---------------- split-K reduce (attno only) ----------------
__global__ void reduce_rows(const float* __restrict__ part, const float* __restrict__ bias,
                            float* __restrict__ out, int Nout, int nsplit, int relu) {
    int i = blockIdx.x * 256 + threadIdx.x;
    if (i >= 32 * Nout) return;
    int r = i / Nout, c = i - r * Nout;
    float s = bias[c];
    for (int k = 0; k < nsplit; k++) s += part[((size_t)k * 32 + r) * Nout + c];
    out[i] = relu ? fmaxf(s, 0.f) : s;
}

// ---------------- attention partial (vectorized bf162) ----------------
__global__ void attn_partial() {
    const int bh = blockIdx.x >> 3;
    const int chunk = blockIdx.x & 7;
    const int b = bh >> 3, h = bh & 7;
    const int tid = threadIdx.x;
    __shared__ float qs[64];
    __shared__ float sc4[4][128];
    __shared__ float ev[128];
    __shared__ float red[8][64];

    if (tid < 64) {
        float q = buf_bqq[h * HD + tid];
        #pragma unroll
        for (int s = 0; s < 8; s++) q += buf_qpart[((size_t)s * 32 + b) * NE + h * HD + tid];
        qs[tid] = q;
    }
    __syncthreads();

    // K pass: thread -> 2 adjacent tokens, 4 d-groups of 16
    {
        const int n0 = (tid & 63) * 2;
        const int dh = tid >> 6;        // 0..3
        const bf16* KT = buf_Kh + ((size_t)bh * HD + dh * 16) * NT + (chunk << 7) + n0;
        float px = 0.f, py = 0.f;
        #pragma unroll
        for (int d = 0; d < 16; d++) {
            float2 kf = __bfloat1622float2(*(const bf162*)(KT + (size_t)d * NT));
            float qv = qs[dh * 16 + d];
            px += qv * kf.x;
            py += qv * kf.y;
        }
        sc4[dh][n0] = px;
        sc4[dh][n0 + 1] = py;
    }
    __syncthreads();

    const int n = tid & 127;
    float score = (tid < 128)
        ? (sc4[0][n] + sc4[1][n] + sc4[2][n] + sc4[3][n]) * 0.125f
        : -1e30f;
    float m = blockReduceMax(score);
    float e = (tid < 128) ? expf(score - m) : 0.f;
    float s = blockReduceSum(e);
    if (tid < 128) ev[n] = e;
    __syncthreads();

    // V pass: thread -> 2 adjacent dims, 8 token-groups of 16
    {
        const int d0 = (tid & 31) * 2;
        const int grp = tid >> 5;       // 0..7
        const bf16* Vb = buf_Vh + (((size_t)bh << 10) + (chunk << 7) + grp * 16) * HD + d0;
        float ax = 0.f, ay = 0.f;
        #pragma unroll
        for (int nn = 0; nn < 16; nn++) {
            float2 vf = __bfloat1622float2(*(const bf162*)(Vb + (size_t)nn * HD));
            float w = ev[grp * 16 + nn];
            ax += w * vf.x;
            ay += w * vf.y;
        }
        red[grp][d0] = ax;
        red[grp][d0 + 1] = ay;
    }
    __syncthreads();
    if (tid < 64) {
        float v = 0.f;
        #pragma unroll
        for (int g = 0; g < 8; g++) v += red[g][tid];
        buf_pv[(size_t)blockIdx.x * HD + tid] = v;
        if (tid == 0) { buf_pm[blockIdx.x] = m; buf_ps[blockIdx.x] = s; }
    }
}

// ---------------- fused 8-split reduce + GLU + double LN ----------------
__global__ void glu_ln_ln(const float* __restrict__ b_syn,
                          const float* __restrict__ g_syn, const float* __restrict__ be_syn,
                          const float* __restrict__ g_pm, const float* __restrict__ be_pm) {
    int b = blockIdx.x, tid = threadIdx.x;
    float v[8];
    #pragma unroll
    for (int j = 0; j < 8; j++) {
        int d = tid + j * 256;
        float a = b_syn[d], gg = b_syn[ND + d];
        #pragma unroll
        for (int s = 0; s < 8; s++) {
            const float* hp = buf_hpart + ((size_t)s * 32 + b) * (2 * ND);
            a += hp[d];
            gg += hp[ND + d];
        }
        v[j] = a * (1.f / (1.f + expf(-gg)));
    }
    float s = 0.f;
    #pragma unroll
    for (int j = 0; j < 8; j++) s += v[j];
    s = blockReduceSum(s);
    float m = s / ND;
    float var = 0.f;
    #pragma unroll
    for (int j = 0; j < 8; j++) { float d = v[j] - m; var += d * d; }
    var = blockReduceSum(var);
    float inv = rsqrtf(var / ND + 1e-5f);
    #pragma unroll
    for (int j = 0; j < 8; j++) {
        int d = tid + j * 256;
        v[j] = (v[j] - m) * inv * g_syn[d] + be_syn[d];
    }
    s = 0.f;
    #pragma unroll
    for (int j = 0; j < 8; j++) s += v[j];
    s = blockReduceSum(s);
    float m2 = s / ND;
    var = 0.f;
    #pragma unroll
    for (int j = 0; j < 8; j++) { float d = v[j] - m2; var += d * d; }
    var = blockReduceSum(var);
    float inv2 = rsqrtf(var / ND + 1e-5f);
    #pragma unroll
    for (int j = 0; j < 8; j++) {
        int d = tid + j * 256;
        buf_hpm[(size_t)b * ND + d] = (v[j] - m2) * inv2 * g_pm[d] + be_pm[d];
    }
}

// -------- act materialize + pred reduce + entropy + writes --------
__global__ void entropy_write(const float* __restrict__ b_out, const float* __restrict__ b2,
                              float* __restrict__ dout, int t) {
    int b = blockIdx.x, tid = threadIdx.x;
    // materialize act[b] = relu(b2 + sum w2part) for next step's consumers
    for (int i = tid; i < ND; i += 256) {
        float v = b2[i];
        #pragma unroll
        for (int s = 0; s < 4; s++) v += buf_w2part[((size_t)s * 32 + b) * ND + i];
        buf_act[(size_t)b * ND + i] = fmaxf(v, 0.f);
    }
    __shared__ float sp[NOUT];
    for (int i = tid; i < NOUT; i += 256) {
        float v = b_out[i];
        #pragma unroll
        for (int s = 0; s < 4; s++) v += buf_predpart[((size_t)s * 32 + b) * NOUT + i];
        sp[i] = v;
    }
    __syncthreads();
    float m = -1e30f;
    for (int i = tid; i < NOUT; i += 256) m = fmaxf(m, sp[i]);
    m = blockReduceMax(m);
    float s = 0.f;
    for (int i = tid; i < NOUT; i += 256) s += expf(sp[i] - m);
    s = blockReduceSum(s);
    float lse = m + logf(s);
    float ent = 0.f;
    for (int i = tid; i < NOUT; i += 256) {
        float pv = sp[i];
        float lp = pv - lse;
        ent += expf(lp) * lp;
        dout[(size_t)b * NOUT * NSTEP + (size_t)i * NSTEP + t] = pv;
    }
    ent = blockReduceSum(ent);
    if (tid == 0) {
        float ne = -ent / logf((float)NOUT);
        dout[CERT_BASE + b * (2 * NSTEP) + t] = ne;
        dout[CERT_BASE + b * (2 * NSTEP) + NSTEP + t] = 1.f - ne;
    }
}

// ---------------- launch ----------------
extern "C" void kernel_launch(void* const* d_in, const int* in_sizes, int n_in,
                              void* d_out, int out_size) {
    const float* x     = (const float*)d_in[0];
    const float* W_kv  = (const float*)d_in[1];
    const float* b_kv  = (const float*)d_in[2];
    const float* g_kv  = (const float*)d_in[3];
    const float* be_kv = (const float*)d_in[4];
    const float* W_q   = (const float*)d_in[5];
    const float* b_q   = (const float*)d_in[6];
    const float* W_in  = (const float*)d_in[7];
    const float* b_in  = (const float*)d_in[8];
    const float* W_ao  = (const float*)d_in[9];
    const float* b_ao  = (const float*)d_in[10];
    const float* W_syn = (const float*)d_in[11];
    const float* b_syn = (const float*)d_in[12];
    const float* g_syn = (const float*)d_in[13];
    const float* be_syn= (const float*)d_in[14];
    const float* g_pm  = (const float*)d_in[15];
    const float* be_pm = (const float*)d_in[16];
    const float* W1    = (const float*)d_in[17];
    const float* b1    = (const float*)d_in[18];
    const float* W2    = (const float*)d_in[19];
    const float* b2    = (const float*)d_in[20];
    const float* start = (const float*)d_in[21];
    const float* dec_a = (const float*)d_in[22];
    const float* dec_o = (const float*)d_in[23];
    const float* W_out = (const float*)d_in[24];
    const float* b_out = (const float*)d_in[25];
    const int*   idx_a = (const int*)d_in[26];
    const int*   idx_o = (const int*)d_in[27];
    float* out = (float*)d_out;

    float *p_kv, *p_Wqq, *p_act, *p_hpm, *p_attno;
    bf16 *p_Kh, *p_Vh;
    float *p_aA, *p_bA, *p_aO, *p_bO;
    float *p_qpart, *p_attnopart, *p_hpart, *p_w1part, *p_w2part, *p_predpart;
    cudaGetSymbolAddress((void**)&p_kv,    buf_kv);
    cudaGetSymbolAddress((void**)&p_Kh,    buf_Kh);
    cudaGetSymbolAddress((void**)&p_Vh,    buf_Vh);
    cudaGetSymbolAddress((void**)&p_Wqq,   buf_Wqq);
    cudaGetSymbolAddress((void**)&p_act,   buf_act);
    cudaGetSymbolAddress((void**)&p_hpm,   buf_hpm);
    cudaGetSymbolAddress((void**)&p_attno, buf_attno);
    cudaGetSymbolAddress((void**)&p_aA,    buf_aA);
    cudaGetSymbolAddress((void**)&p_bA,    buf_bA);
    cudaGetSymbolAddress((void**)&p_aO,    buf_aO);
    cudaGetSymbolAddress((void**)&p_bO,    buf_bO);
    cudaGetSymbolAddress((void**)&p_qpart,     buf_qpart);
    cudaGetSymbolAddress((void**)&p_attnopart, buf_attnopart);
    cudaGetSymbolAddress((void**)&p_hpart,     buf_hpart);
    cudaGetSymbolAddress((void**)&p_w1part,    buf_w1part);
    cudaGetSymbolAddress((void**)&p_w2part,    buf_w2part);
    cudaGetSymbolAddress((void**)&p_predpart,  buf_predpart);

    // ---- precompute ----
    gemm_at_tf32<<<dim3(NE / 64, (NB * NT) / 128), 256>>>(x, W_kv, NE, b_kv, p_kv, NE, NC);
    ln_rows<<<NB * NT, 256>>>(p_kv, NE, g_kv, be_kv);
    gemm_tf32<<<dim3(NE / 64, (NB * NT) / 128), 256>>>(p_kv, NE, W_in + NE,     3 * NE, b_in + NE,
                                                       (float*)0, p_Kh, NE, NE, 1);
    gemm_tf32<<<dim3(NE / 64, (NB * NT) / 128), 256>>>(p_kv, NE, W_in + 2 * NE, 3 * NE, b_in + 2 * NE,
                                                       (float*)0, p_Vh, NE, NE, 2);
    gemm_tf32<<<dim3(NE / 64, NE / 128), 256>>>(W_q, NE, W_in, 3 * NE, (const float*)0,
                                                p_Wqq, (bf16*)0, NE, NE, 0);
    make_bqq<<<2, 256>>>(b_q, W_in, b_in);
    init_state<<<(NB * ND + 255) / 256, 256>>>(start);

    // ---- recurrent loop: 10 nodes/step ----
    for (int t = 0; t < NSTEP; t++) {
        const int pi = (t & 1) * NB * 512, po = ((t + 1) & 1) * NB * 512;
        // 1. q partials (fused syncA)
        skinny_fused<<<dim3(8, 8), 256>>>(1, p_act, ND, idx_a, dec_a,
                                          p_aA + pi, p_bA + pi, p_aA + po, p_bA + po,
                                          (float*)0, (const float*)0,
                                          p_Wqq, NE, p_qpart, NE, 64);
        // 2. attention partials (vectorized)
        attn_partial<<<NB * NH * 8, 256>>>();
        // 3. attno partials (fused combine)
        skinny_fused<<<dim3(8, 8), 256>>>(2, (const float*)0, 0, (const int*)0, (const float*)0,
                                          (const float*)0, (const float*)0, (float*)0, (float*)0,
                                          (float*)0, (const float*)0,
                                          W_ao, NE, p_attnopart, NE, 64);
        // 4. attno reduce
        reduce_rows<<<(32 * NE + 255) / 256, 256>>>(p_attnopart, b_ao, p_attno, NE, 8, 0);
        // 5. h partials: [attno|act] @ W_syn
        skinny_gemm<<<dim3((2 * ND) / 64, 8), 256>>>(p_attno, NE, p_act, ND,
                                                     W_syn, 2 * ND, p_hpart, 2 * ND, (NE + ND) / 8);
        // 6. GLU + double LN
        glu_ln_ln<<<NB, 256>>>(b_syn, g_syn, be_syn, g_pm, be_pm);
        // 7. W1 partials
        skinny_gemm<<<dim3(ND / 64, 4), 256>>>(p_hpm, ND, (const float*)0, 0,
                                               W1, ND, p_w1part, ND, ND / 4);
        // 8. W2 partials with fused W1-reduce+bias+relu in A
        skinny_gemm_red<<<dim3(ND / 64, 4), 256>>>(p_w1part, ND, b1,
                                                   W2, ND, p_w2part, ND, ND / 4);
        // 9. pred partials (fused syncO + w2 gather-reduce)
        skinny_fused<<<dim3(16, 4), 256>>>(6, p_w2part, ND, idx_o, dec_o,
                                           p_aO + pi, p_bO + pi, p_aO + po, p_bO + po,
                                           (t == NSTEP - 1) ? (out + SYNC_BASE) : (float*)0, b2,
                                           W_out, NOUT, p_predpart, NOUT, 128);
        // 10. entropy + prediction writes + act materialize
        entropy_write<<<NB, 256>>>(b_out, b2, out, t);
    }
}

// round 10
// speedup vs baseline: 1.1919x; 1.1919x over previous
#include <cuda_runtime.h>
#include <cuda_bf16.h>
#include <math.h>
#include <stdint.h>

// ---------------- problem dims ----------------
#define NB 32
#define NC 512
#define NT 1024
#define NE 512
#define ND 2048
#define NH 8
#define HD 64
#define NSTEP 50
#define NOUT 1000
#define NA_ 512
#define NO_ 512

#define PRED_ELEMS (NB*NOUT*NSTEP)
#define CERT_BASE  PRED_ELEMS
#define SYNC_BASE  (CERT_BASE + NB*2*NSTEP)

typedef __nv_bfloat16 bf16;
typedef __nv_bfloat162 bf162;

// ---------------- device scratch ----------------
__device__ float buf_kv   [NB*NT*NE];
__device__ bf16  buf_Kh   [NB*NT*NE];   // K^T head-major bf16: [b][h][d][n]
__device__ bf16  buf_Vh   [NB*NT*NE];   // V head-major bf16: [b][h][n][d]
__device__ float buf_act  [NB*ND];
__device__ float buf_aA   [2*NB*NA_];
__device__ float buf_bA   [2*NB*NA_];
__device__ float buf_aO   [2*NB*NO_];
__device__ float buf_bO   [2*NB*NO_];
__device__ float buf_attno[NB*NE];
__device__ float buf_hpm  [NB*ND];
__device__ float buf_t1   [NB*ND];
__device__ float buf_Wqq  [NE*NE];
__device__ float buf_bqq  [NE];
// split-K partials
__device__ float buf_qpart    [8*32*NE];
__device__ float buf_attnopart[8*32*NE];
__device__ float buf_hpart    [8*32*2*ND];
__device__ float buf_w1part   [4*32*ND];
__device__ float buf_w2part   [4*32*ND];
__device__ float buf_predpart [4*32*NOUT];
// attention partials
__device__ float buf_pv[NB*NH*8*HD];
__device__ float buf_pm[NB*NH*8];
__device__ float buf_ps[NB*NH*8];

// ---------------- cp.async helpers ----------------
__device__ __forceinline__ void cp16(void* smem, const void* gmem) {
    uint32_t s = (uint32_t)__cvta_generic_to_shared(smem);
    asm volatile("cp.async.cg.shared.global [%0], [%1], 16;\n" :: "r"(s), "l"(gmem));
}
#define CP_COMMIT() asm volatile("cp.async.commit_group;\n" ::: "memory")
#define CP_WAIT2()  asm volatile("cp.async.wait_group 2;\n" ::: "memory")
#define CP_WAIT1()  asm volatile("cp.async.wait_group 1;\n" ::: "memory")

// ---------------- tf32 mma helpers ----------------
__device__ __forceinline__ uint32_t f2tf(float x) {
    uint32_t r;
    asm("cvt.rna.tf32.f32 %0, %1;" : "=r"(r) : "f"(x));
    return r;
}
__device__ __forceinline__ void mma_tf32(float* c, const uint32_t* a, const uint32_t* b) {
    asm volatile(
        "mma.sync.aligned.m16n8k8.row.col.f32.tf32.tf32.f32 "
        "{%0,%1,%2,%3},{%4,%5,%6,%7},{%8,%9},{%0,%1,%2,%3};"
        : "+f"(c[0]), "+f"(c[1]), "+f"(c[2]), "+f"(c[3])
        : "r"(a[0]), "r"(a[1]), "r"(a[2]), "r"(a[3]), "r"(b[0]), "r"(b[1]));
}

// ---------------- block reductions ----------------
__device__ __forceinline__ float blockReduceSum(float v) {
    __shared__ float shs[32];
    int lane = threadIdx.x & 31, w = threadIdx.x >> 5;
    #pragma unroll
    for (int o = 16; o; o >>= 1) v += __shfl_xor_sync(0xffffffffu, v, o);
    if (lane == 0) shs[w] = v;
    __syncthreads();
    float r = 0.f;
    int nw = (blockDim.x + 31) >> 5;
    if (threadIdx.x < nw) r = shs[threadIdx.x];
    if (w == 0) {
        #pragma unroll
        for (int o = 16; o; o >>= 1) r += __shfl_xor_sync(0xffffffffu, r, o);
        if (lane == 0) shs[0] = r;
    }
    __syncthreads();
    float out = shs[0];
    __syncthreads();
    return out;
}
__device__ __forceinline__ float blockReduceMax(float v) {
    __shared__ float shm[32];
    int lane = threadIdx.x & 31, w = threadIdx.x >> 5;
    #pragma unroll
    for (int o = 16; o; o >>= 1) v = fmaxf(v, __shfl_xor_sync(0xffffffffu, v, o));
    if (lane == 0) shm[w] = v;
    __syncthreads();
    float r = -1e30f;
    int nw = (blockDim.x + 31) >> 5;
    if (threadIdx.x < nw) r = shm[threadIdx.x];
    if (w == 0) {
        #pragma unroll
        for (int o = 16; o; o >>= 1) r = fmaxf(r, __shfl_xor_sync(0xffffffffu, r, o));
        if (lane == 0) shm[0] = r;
    }
    __syncthreads();
    float out = shm[0];
    __syncthreads();
    return out;
}

// ======================================================================
// tf32 GEMM, A transposed in gmem (fuses (B,C,N)->(B,N,C) transpose)
// ======================================================================
__global__ void gemm_at_tf32(const float* __restrict__ X,
                             const float* __restrict__ B, int ldb,
                             const float* __restrict__ bias,
                             float* __restrict__ C, int ldc, int K) {
    __shared__ float As2[2][16][136];
    __shared__ float Bs[2][16][68];
    const int tid = threadIdx.x;
    const int wid = tid >> 5, lane = tid & 31;
    const int g = lane >> 2, tg = lane & 3;
    const int warp_m = wid >> 1, warp_n = wid & 1;
    const int row0 = blockIdx.y * 128;
    const int col0 = blockIdx.x * 64;
    const int bb_ = row0 >> 10, n0 = row0 & 1023;
    const float* Xb = X + (size_t)bb_ * NC * NT;

    const int la_k = tid >> 4;
    const int la_n = (tid & 15) * 8;
    const int lb_r = tid >> 4;
    const int lb_c = (tid & 15) * 4;

    float acc[2][4][4];
    #pragma unroll
    for (int mi = 0; mi < 2; mi++)
        #pragma unroll
        for (int ni = 0; ni < 4; ni++)
            #pragma unroll
            for (int j = 0; j < 4; j++) acc[mi][ni][j] = 0.f;

    const int ntiles = K >> 4;
    {
        const float* ap = Xb + (size_t)la_k * NT + n0 + la_n;
        cp16(&As2[0][la_k][la_n], ap);
        cp16(&As2[0][la_k][la_n + 4], ap + 4);
        cp16(&Bs[0][lb_r][lb_c], B + (size_t)lb_r * ldb + col0 + lb_c);
    }
    CP_COMMIT();

    for (int ct = 0; ct < ntiles; ct++) {
        if (ct + 1 < ntiles) {
            int k0 = (ct + 1) << 4;
            int st = (ct + 1) & 1;
            const float* ap = Xb + (size_t)(k0 + la_k) * NT + n0 + la_n;
            cp16(&As2[st][la_k][la_n], ap);
            cp16(&As2[st][la_k][la_n + 4], ap + 4);
            cp16(&Bs[st][lb_r][lb_c], B + (size_t)(k0 + lb_r) * ldb + col0 + lb_c);
        }
        CP_COMMIT();
        CP_WAIT1();
        __syncthreads();
        const int st = ct & 1;
        #pragma unroll
        for (int ks = 0; ks < 2; ks++) {
            const int k8 = ks * 8;
            uint32_t a[2][4], bf[4][2];
            #pragma unroll
            for (int mi = 0; mi < 2; mi++) {
                int r = warp_m * 32 + mi * 16 + g;
                a[mi][0] = f2tf(As2[st][k8 + tg][r]);
                a[mi][1] = f2tf(As2[st][k8 + tg][r + 8]);
                a[mi][2] = f2tf(As2[st][k8 + tg + 4][r]);
                a[mi][3] = f2tf(As2[st][k8 + tg + 4][r + 8]);
            }
            #pragma unroll
            for (int ni = 0; ni < 4; ni++) {
                int c = warp_n * 32 + ni * 8 + g;
                bf[ni][0] = f2tf(Bs[st][k8 + tg][c]);
                bf[ni][1] = f2tf(Bs[st][k8 + tg + 4][c]);
            }
            #pragma unroll
            for (int mi = 0; mi < 2; mi++)
                #pragma unroll
                for (int ni = 0; ni < 4; ni++)
                    mma_tf32(acc[mi][ni], a[mi], bf[ni]);
        }
        __syncthreads();
    }

    #pragma unroll
    for (int mi = 0; mi < 2; mi++)
        #pragma unroll
        for (int ni = 0; ni < 4; ni++) {
            int r = row0 + warp_m * 32 + mi * 16 + g;
            int c = col0 + warp_n * 32 + ni * 8 + 2 * tg;
            float b0 = bias ? bias[c] : 0.f;
            float b1 = bias ? bias[c + 1] : 0.f;
            C[(size_t)r * ldc + c] = acc[mi][ni][0] + b0;
            C[(size_t)r * ldc + c + 1] = acc[mi][ni][1] + b1;
            C[(size_t)(r + 8) * ldc + c] = acc[mi][ni][2] + b0;
            C[(size_t)(r + 8) * ldc + c + 1] = acc[mi][ni][3] + b1;
        }
}

// ---------------- tf32 GEMM row-major A --------------------------------
// kvmode: 0 plain fp32; 1 K^T bf16 scatter [b][h][d][n]; 2 V bf16 scatter
__global__ void gemm_tf32(const float* __restrict__ A, int lda,
                          const float* __restrict__ B, int ldb,
                          const float* __restrict__ bias,
                          float* __restrict__ C, bf16* __restrict__ Ch,
                          int ldc, int K, int kvmode) {
    __shared__ float As[2][128][20];
    __shared__ float Bs[2][16][68];
    const int tid = threadIdx.x;
    const int wid = tid >> 5, lane = tid & 31;
    const int g = lane >> 2, tg = lane & 3;
    const int warp_m = wid >> 1, warp_n = wid & 1;
    const int row0 = blockIdx.y * 128;
    const int col0 = blockIdx.x * 64;

    const int la_r = tid >> 1;
    const int la_c = (tid & 1) * 8;
    const int lb_r = tid >> 4;
    const int lb_c = (tid & 15) * 4;

    float acc[2][4][4];
    #pragma unroll
    for (int mi = 0; mi < 2; mi++)
        #pragma unroll
        for (int ni = 0; ni < 4; ni++)
            #pragma unroll
            for (int j = 0; j < 4; j++) acc[mi][ni][j] = 0.f;

    const int ntiles = K >> 4;
    {
        const float* ap = A + (size_t)(row0 + la_r) * lda + la_c;
        cp16(&As[0][la_r][la_c], ap);
        cp16(&As[0][la_r][la_c + 4], ap + 4);
        cp16(&Bs[0][lb_r][lb_c], B + (size_t)lb_r * ldb + col0 + lb_c);
    }
    CP_COMMIT();

    for (int ct = 0; ct < ntiles; ct++) {
        if (ct + 1 < ntiles) {
            int k0 = (ct + 1) << 4;
            int st = (ct + 1) & 1;
            const float* ap = A + (size_t)(row0 + la_r) * lda + k0 + la_c;
            cp16(&As[st][la_r][la_c], ap);
            cp16(&As[st][la_r][la_c + 4], ap + 4);
            cp16(&Bs[st][lb_r][lb_c], B + (size_t)(k0 + lb_r) * ldb + col0 + lb_c);
        }
        CP_COMMIT();
        CP_WAIT1();
        __syncthreads();
        const int st = ct & 1;
        #pragma unroll
        for (int ks = 0; ks < 2; ks++) {
            const int k8 = ks * 8;
            uint32_t a[2][4], bf[4][2];
            #pragma unroll
            for (int mi = 0; mi < 2; mi++) {
                int r = warp_m * 32 + mi * 16 + g;
                a[mi][0] = f2tf(As[st][r][k8 + tg]);
                a[mi][1] = f2tf(As[st][r + 8][k8 + tg]);
                a[mi][2] = f2tf(As[st][r][k8 + tg + 4]);
                a[mi][3] = f2tf(As[st][r + 8][k8 + tg + 4]);
            }
            #pragma unroll
            for (int ni = 0; ni < 4; ni++) {
                int c = warp_n * 32 + ni * 8 + g;
                bf[ni][0] = f2tf(Bs[st][k8 + tg][c]);
                bf[ni][1] = f2tf(Bs[st][k8 + tg + 4][c]);
            }
            #pragma unroll
            for (int mi = 0; mi < 2; mi++)
                #pragma unroll
                for (int ni = 0; ni < 4; ni++)
                    mma_tf32(acc[mi][ni], a[mi], bf[ni]);
        }
        __syncthreads();
    }

    #pragma unroll
    for (int mi = 0; mi < 2; mi++) {
        #pragma unroll
        for (int ni = 0; ni < 4; ni++) {
            int r = row0 + warp_m * 32 + mi * 16 + g;
            int c = col0 + warp_n * 32 + ni * 8 + 2 * tg;
            float b0 = bias ? bias[c] : 0.f;
            float b1 = bias ? bias[c + 1] : 0.f;
            float v00 = acc[mi][ni][0] + b0, v01 = acc[mi][ni][1] + b1;
            float v10 = acc[mi][ni][2] + b0, v11 = acc[mi][ni][3] + b1;
            #pragma unroll
            for (int rr = 0; rr < 2; rr++) {
                int row = r + rr * 8;
                float va = rr ? v10 : v00;
                float vb = rr ? v11 : v01;
                if (kvmode == 0) {
                    C[(size_t)row * ldc + c] = va;
                    C[(size_t)row * ldc + c + 1] = vb;
                } else if (kvmode == 1) {
                    int b = row >> 10, n = row & 1023;
                    int h0 = c >> 6, d0 = c & 63;
                    int h1 = (c + 1) >> 6, d1 = (c + 1) & 63;
                    Ch[(((size_t)(b * NH + h0)) * HD + d0) * NT + n] = __float2bfloat16(va);
                    Ch[(((size_t)(b * NH + h1)) * HD + d1) * NT + n] = __float2bfloat16(vb);
                } else {
                    int b = row >> 10, n = row & 1023;
                    int h0 = c >> 6, d0 = c & 63;
                    int h1 = (c + 1) >> 6, d1 = (c + 1) & 63;
                    Ch[((((size_t)b * NH + h0) << 10) + n) * HD + d0] = __float2bfloat16(va);
                    Ch[((((size_t)b * NH + h1) << 10) + n) * HD + d1] = __float2bfloat16(vb);
                }
            }
        }
    }
}

// ---------------- row LayerNorm ----------------
__global__ void ln_rows(float* __restrict__ X, int L,
                        const float* __restrict__ g, const float* __restrict__ b) {
    int row = blockIdx.x;
    float* xp = X + (size_t)row * L;
    float s = 0.f;
    for (int i = threadIdx.x; i < L; i += blockDim.x) s += xp[i];
    s = blockReduceSum(s);
    float m = s / L;
    float v = 0.f;
    for (int i = threadIdx.x; i < L; i += blockDim.x) { float d = xp[i] - m; v += d * d; }
    v = blockReduceSum(v);
    float inv = rsqrtf(v / L + 1e-5f);
    for (int i = threadIdx.x; i < L; i += blockDim.x)
        xp[i] = (xp[i] - m) * inv * g[i] + b[i];
}

__global__ void make_bqq(const float* __restrict__ b_q, const float* __restrict__ W_in,
                         const float* __restrict__ b_in) {
    int j = blockIdx.x * blockDim.x + threadIdx.x;
    if (j >= NE) return;
    float s = b_in[j];
    for (int k = 0; k < NE; k++) s += b_q[k] * W_in[(size_t)k * (3 * NE) + j];
    buf_bqq[j] = s;
}

__global__ void init_state(const float* __restrict__ start) {
    int i = blockIdx.x * blockDim.x + threadIdx.x;
    if (i < NB * ND) buf_act[i] = start[i & (ND - 1)];
    if (i < NB * NA_) {
        buf_aA[i] = 0.f; buf_bA[i] = 0.f;
        buf_aO[i] = 0.f; buf_bO[i] = 0.f;
    }
}

// ======================================================================
// Fused light skinny GEMM (fp32 B).
// modes: 1 = syncA update; 2 = attention combine; 5 = syncO update
// ======================================================================
#define SKS 4
__global__ void skinny_fused(int mode,
                             const float* __restrict__ A0, int lda,
                             const int* __restrict__ idx, const float* __restrict__ decay,
                             const float* __restrict__ st_a_in, const float* __restrict__ st_b_in,
                             float* __restrict__ st_a_out, float* __restrict__ st_b_out,
                             float* __restrict__ sync_final,
                             const float* __restrict__ B, int ldb,
                             float* __restrict__ partout, int Nout, int Kper) {
    __shared__ float As[32][129];
    __shared__ float Bs[SKS][16][64];
    __shared__ float wno[32][8];
    __shared__ float Tinv[32];
    const int tid = threadIdx.x;
    const int col0 = blockIdx.x * 64;
    const int kstart = blockIdx.y * Kper;
    const int ntiles = Kper >> 4;
    const int kshift = (Kper == 64) ? 6 : 7;

    const int bkk = tid >> 4, bc = (tid & 15) * 4;
    int bcol = col0 + bc;
    if (bcol > Nout - 4) bcol = Nout - 4;
    #pragma unroll
    for (int pt = 0; pt < SKS - 1; pt++) {
        if (pt < ntiles)
            cp16(&Bs[pt][bkk][bc], B + (size_t)(kstart + pt * 16 + bkk) * ldb + bcol);
        CP_COMMIT();
    }

    if (mode == 2) {
        if (tid < 32) {
            int h = kstart >> 6, b = tid;
            float M = -1e30f;
            #pragma unroll
            for (int c = 0; c < 8; c++) M = fmaxf(M, buf_pm[(b * NH + h) * 8 + c]);
            float T = 0.f;
            #pragma unroll
            for (int c = 0; c < 8; c++) {
                float w = expf(buf_pm[(b * NH + h) * 8 + c] - M);
                wno[b][c] = w;
                T += buf_ps[(b * NH + h) * 8 + c] * w;
            }
            Tinv[b] = 1.f / T;
        }
        __syncthreads();
    }

    // ---- A build ----
    for (int e = tid; e < 32 * Kper; e += 256) {
        int r = e >> kshift;
        int j = e & (Kper - 1);
        int k = kstart + j;
        float v;
        if (mode == 2) {
            int h = kstart >> 6;
            const float* pvp = buf_pv + ((size_t)(r * NH + h) * 8) * HD + j;
            float acc = 0.f;
            #pragma unroll
            for (int c = 0; c < 8; c++) acc += pvp[c * HD] * wno[r][c];
            v = acc * Tinv[r];
        } else {
            float rr = expf(-fminf(fmaxf(decay[k], 0.f), 15.f));
            float sel = A0[(size_t)r * lda + idx[k]];
            float a = rr * st_a_in[r * 512 + k] + sel * sel;
            float bb = rr * st_b_in[r * 512 + k] + 1.f;
            st_a_out[r * 512 + k] = a;
            st_b_out[r * 512 + k] = bb;
            v = a * rsqrtf(bb);
            if (sync_final) sync_final[r * 512 + k] = v;
        }
        As[r][j] = v;
    }
    __syncthreads();

    // ---- B streaming + FMA ----
    const int c4 = (tid & 15) * 4;
    const int r0 = (tid >> 4) * 2;
    float acc0[4] = {0.f, 0.f, 0.f, 0.f};
    float acc1[4] = {0.f, 0.f, 0.f, 0.f};

    for (int ct = 0; ct < ntiles; ct++) {
        CP_WAIT2();
        __syncthreads();
        const int st = ct & (SKS - 1);
        const float* a0p = &As[r0][ct * 16];
        const float* a1p = &As[r0 + 1][ct * 16];
        #pragma unroll
        for (int kk = 0; kk < 16; kk++) {
            float4 bv = *(const float4*)&Bs[st][kk][c4];
            float a0 = a0p[kk], a1 = a1p[kk];
            acc0[0] += a0 * bv.x; acc0[1] += a0 * bv.y;
            acc0[2] += a0 * bv.z; acc0[3] += a0 * bv.w;
            acc1[0] += a1 * bv.x; acc1[1] += a1 * bv.y;
            acc1[2] += a1 * bv.z; acc1[3] += a1 * bv.w;
        }
        __syncthreads();
        int nt = ct + SKS - 1;
        if (nt < ntiles)
            cp16(&Bs[nt & (SKS - 1)][bkk][bc], B + (size_t)(kstart + nt * 16 + bkk) * ldb + bcol);
        CP_COMMIT();
    }

    float* po = partout + ((size_t)blockIdx.y * 32 + r0) * Nout;
    #pragma unroll
    for (int j = 0; j < 4; j++) {
        int c = col0 + c4 + j;
        if (c < Nout) {
            po[c] = acc0[j];
            po[Nout + c] = acc1[j];
        }
    }
}

// ---------------- pipelined split-K skinny GEMM (fp32 B) ------------------
__global__ void skinny_gemm(const float* __restrict__ A0, int K0,
                            const float* __restrict__ A1, int K1,
                            const float* __restrict__ B, int ldb,
                            float* __restrict__ part, int Nout, int Kper) {
    __shared__ float As[SKS][32][16];
    __shared__ float Bs[SKS][16][64];
    const int tid = threadIdx.x;
    const int col0 = blockIdx.x * 64;
    const int kstart = blockIdx.y * Kper;
    const int ntiles = Kper >> 4;

    const int b_kk = tid >> 4;
    const int b_c  = (tid & 15) * 4;
    const int a_r  = tid >> 2;
    const int a_kc = (tid & 3) * 4;
    int bcol = col0 + b_c;
    if (bcol > Nout - 4) bcol = Nout - 4;

    const int c4 = (tid & 15) * 4;
    const int r0 = (tid >> 4) * 2;

    float acc0[4] = {0.f, 0.f, 0.f, 0.f};
    float acc1[4] = {0.f, 0.f, 0.f, 0.f};

    #pragma unroll
    for (int pt = 0; pt < SKS - 1; pt++) {
        if (pt < ntiles) {
            int kb = kstart + pt * 16;
            cp16(&Bs[pt][b_kk][b_c], B + (size_t)(kb + b_kk) * ldb + bcol);
            if (tid < 128) {
                int k = kb + a_kc;
                const float* src = (k < K0) ? (A0 + (size_t)a_r * K0 + k)
                                            : (A1 + (size_t)a_r * K1 + (k - K0));
                cp16(&As[pt][a_r][a_kc], src);
            }
        }
        CP_COMMIT();
    }

    for (int ct = 0; ct < ntiles; ct++) {
        CP_WAIT2();
        __syncthreads();
        const int st = ct & (SKS - 1);
        #pragma unroll
        for (int kk = 0; kk < 16; kk++) {
            float4 bv = *(const float4*)&Bs[st][kk][c4];
            float a0 = As[st][r0][kk];
            float a1 = As[st][r0 + 1][kk];
            acc0[0] += a0 * bv.x; acc0[1] += a0 * bv.y;
            acc0[2] += a0 * bv.z; acc0[3] += a0 * bv.w;
            acc1[0] += a1 * bv.x; acc1[1] += a1 * bv.y;
            acc1[2] += a1 * bv.z; acc1[3] += a1 * bv.w;
        }
        __syncthreads();
        int nt = ct + SKS - 1;
        if (nt < ntiles) {
            int kb = kstart + nt * 16;
            int st2 = nt & (SKS - 1);
            cp16(&Bs[st2][b_kk][b_c], B + (size_t)(kb + b_kk) * ldb + bcol);
            if (tid < 128) {
                int k = kb + a_kc;
                const float* src = (k < K0) ? (A0 + (size_t)a_r * K0 + k)
                                            : (A1 + (size_t)a_r * K1 + (k - K0));
                cp16(&As[st2][a_r][a_kc], src);
            }
        }
        CP_COMMIT();
    }

    float* po = part + ((size_t)blockIdx.y * 32 + r0) * Nout;
    #pragma unroll
    for (int j = 0; j < 4; j++) {
        int c = col0 + c4 + j;
        if (c < Nout) {
            po[c] = acc0[j];
            po[Nout + c] = acc1[j];
        }
    }
}

// ---------------- split-K reduce ----------------
__global__ void reduce_rows(const float* __restrict__ part, const float* __restrict__ bias,
                            float* __restrict__ out, int Nout, int nsplit, int relu) {
    int i = blockIdx.x * 256 + threadIdx.x;
    if (i >= 32 * Nout) return;
    int r = i / Nout, c = i - r * Nout;
    float s = bias[c];
    for (int k = 0; k < nsplit; k++) s += part[((size_t)k * 32 + r) * Nout + c];
    out[i] = relu ? fmaxf(s, 0.f) : s;
}

// ---------------- attention partial (vectorized bf162 K and V) ----------
__global__ void attn_partial() {
    const int bh = blockIdx.x >> 3;
    const int chunk = blockIdx.x & 7;
    const int b = bh >> 3, h = bh & 7;
    const int tid = threadIdx.x;
    __shared__ float qs[64];
    __shared__ float sc4[4][128];
    __shared__ float ev[128];
    __shared__ float red[8][64];

    if (tid < 64) {
        float q = buf_bqq[h * HD + tid];
        #pragma unroll
        for (int s = 0; s < 8; s++) q += buf_qpart[((size_t)s * 32 + b) * NE + h * HD + tid];
        qs[tid] = q;
    }
    __syncthreads();

    // K pass: thread -> 2 adjacent tokens (bf162), 4 d-groups of 16
    {
        const int n0 = (tid & 63) * 2;
        const int dh = tid >> 6;        // 0..3
        const bf16* KT = buf_Kh + ((size_t)bh * HD + dh * 16) * NT + (chunk << 7) + n0;
        float px = 0.f, py = 0.f;
        #pragma unroll
        for (int d = 0; d < 16; d++) {
            float2 kf = __bfloat1622float2(*(const bf162*)(KT + (size_t)d * NT));
            float qv = qs[dh * 16 + d];
            px += qv * kf.x;
            py += qv * kf.y;
        }
        sc4[dh][n0] = px;
        sc4[dh][n0 + 1] = py;
    }
    __syncthreads();

    const int n = tid & 127;
    float score = (tid < 128)
        ? (sc4[0][n] + sc4[1][n] + sc4[2][n] + sc4[3][n]) * 0.125f
        : -1e30f;
    float m = blockReduceMax(score);
    float e = (tid < 128) ? expf(score - m) : 0.f;
    float s = blockReduceSum(e);
    if (tid < 128) ev[n] = e;
    __syncthreads();

    // V pass: thread -> 2 adjacent dims (bf162), 8 token-groups of 16
    {
        const int d0 = (tid & 31) * 2;
        const int grp = tid >> 5;       // 0..7
        const bf16* Vb = buf_Vh + (((size_t)bh << 10) + (chunk << 7) + grp * 16) * HD + d0;
        float ax = 0.f, ay = 0.f;
        #pragma unroll
        for (int nn = 0; nn < 16; nn++) {
            float2 vf = __bfloat1622float2(*(const bf162*)(Vb + (size_t)nn * HD));
            float w = ev[grp * 16 + nn];
            ax += w * vf.x;
            ay += w * vf.y;
        }
        red[grp][d0] = ax;
        red[grp][d0 + 1] = ay;
    }
    __syncthreads();
    if (tid < 64) {
        float v = 0.f;
        #pragma unroll
        for (int g = 0; g < 8; g++) v += red[g][tid];
        buf_pv[(size_t)blockIdx.x * HD + tid] = v;
        if (tid == 0) { buf_pm[blockIdx.x] = m; buf_ps[blockIdx.x] = s; }
    }
}

// ---------------- fused 8-split reduce + GLU + double LN ----------------
__global__ void glu_ln_ln(const float* __restrict__ b_syn,
                          const float* __restrict__ g_syn, const float* __restrict__ be_syn,
                          const float* __restrict__ g_pm, const float* __restrict__ be_pm) {
    int b = blockIdx.x, tid = threadIdx.x;
    float v[8];
    #pragma unroll
    for (int j = 0; j < 8; j++) {
        int d = tid + j * 256;
        float a = b_syn[d], gg = b_syn[ND + d];
        #pragma unroll
        for (int s = 0; s < 8; s++) {
            const float* hp = buf_hpart + ((size_t)s * 32 + b) * (2 * ND);
            a += hp[d];
            gg += hp[ND + d];
        }
        v[j] = a * (1.f / (1.f + expf(-gg)));
    }
    float s = 0.f;
    #pragma unroll
    for (int j = 0; j < 8; j++) s += v[j];
    s = blockReduceSum(s);
    float m = s / ND;
    float var = 0.f;
    #pragma unroll
    for (int j = 0; j < 8; j++) { float d = v[j] - m; var += d * d; }
    var = blockReduceSum(var);
    float inv = rsqrtf(var / ND + 1e-5f);
    #pragma unroll
    for (int j = 0; j < 8; j++) {
        int d = tid + j * 256;
        v[j] = (v[j] - m) * inv * g_syn[d] + be_syn[d];
    }
    s = 0.f;
    #pragma unroll
    for (int j = 0; j < 8; j++) s += v[j];
    s = blockReduceSum(s);
    float m2 = s / ND;
    var = 0.f;
    #pragma unroll
    for (int j = 0; j < 8; j++) { float d = v[j] - m2; var += d * d; }
    var = blockReduceSum(var);
    float inv2 = rsqrtf(var / ND + 1e-5f);
    #pragma unroll
    for (int j = 0; j < 8; j++) {
        int d = tid + j * 256;
        buf_hpm[(size_t)b * ND + d] = (v[j] - m2) * inv2 * g_pm[d] + be_pm[d];
    }
}

// ---------------- pred reduce + entropy + writes ----------------
__global__ void entropy_write(const float* __restrict__ b_out, float* __restrict__ dout, int t) {
    int b = blockIdx.x, tid = threadIdx.x;
    __shared__ float sp[NOUT];
    for (int i = tid; i < NOUT; i += 256) {
        float v = b_out[i];
        #pragma unroll
        for (int s = 0; s < 4; s++) v += buf_predpart[((size_t)s * 32 + b) * NOUT + i];
        sp[i] = v;
    }
    __syncthreads();
    float m = -1e30f;
    for (int i = tid; i < NOUT; i += 256) m = fmaxf(m, sp[i]);
    m = blockReduceMax(m);
    float s = 0.f;
    for (int i = tid; i < NOUT; i += 256) s += expf(sp[i] - m);
    s = blockReduceSum(s);
    float lse = m + logf(s);
    float ent = 0.f;
    for (int i = tid; i < NOUT; i += 256) {
        float pv = sp[i];
        float lp = pv - lse;
        ent += expf(lp) * lp;
        dout[(size_t)b * NOUT * NSTEP + (size_t)i * NSTEP + t] = pv;
    }
    ent = blockReduceSum(ent);
    if (tid == 0) {
        float ne = -ent / logf((float)NOUT);
        dout[CERT_BASE + b * (2 * NSTEP) + t] = ne;
        dout[CERT_BASE + b * (2 * NSTEP) + NSTEP + t] = 1.f - ne;
    }
}

// ---------------- launch ----------------
extern "C" void kernel_launch(void* const* d_in, const int* in_sizes, int n_in,
                              void* d_out, int out_size) {
    const float* x     = (const float*)d_in[0];
    const float* W_kv  = (const float*)d_in[1];
    const float* b_kv  = (const float*)d_in[2];
    const float* g_kv  = (const float*)d_in[3];
    const float* be_kv = (const float*)d_in[4];
    const float* W_q   = (const float*)d_in[5];
    const float* b_q   = (const float*)d_in[6];
    const float* W_in  = (const float*)d_in[7];
    const float* b_in  = (const float*)d_in[8];
    const float* W_ao  = (const float*)d_in[9];
    const float* b_ao  = (const float*)d_in[10];
    const float* W_syn = (const float*)d_in[11];
    const float* b_syn = (const float*)d_in[12];
    const float* g_syn = (const float*)d_in[13];
    const float* be_syn= (const float*)d_in[14];
    const float* g_pm  = (const float*)d_in[15];
    const float* be_pm = (const float*)d_in[16];
    const float* W1    = (const float*)d_in[17];
    const float* b1    = (const float*)d_in[18];
    const float* W2    = (const float*)d_in[19];
    const float* b2    = (const float*)d_in[20];
    const float* start = (const float*)d_in[21];
    const float* dec_a = (const float*)d_in[22];
    const float* dec_o = (const float*)d_in[23];
    const float* W_out = (const float*)d_in[24];
    const float* b_out = (const float*)d_in[25];
    const int*   idx_a = (const int*)d_in[26];
    const int*   idx_o = (const int*)d_in[27];
    float* out = (float*)d_out;

    float *p_kv, *p_Wqq, *p_act, *p_hpm, *p_t1, *p_attno;
    bf16 *p_Kh, *p_Vh;
    float *p_aA, *p_bA, *p_aO, *p_bO;
    float *p_qpart, *p_attnopart, *p_hpart, *p_w1part, *p_w2part, *p_predpart;
    cudaGetSymbolAddress((void**)&p_kv,    buf_kv);
    cudaGetSymbolAddress((void**)&p_Kh,    buf_Kh);
    cudaGetSymbolAddress((void**)&p_Vh,    buf_Vh);
    cudaGetSymbolAddress((void**)&p_Wqq,   buf_Wqq);
    cudaGetSymbolAddress((void**)&p_act,   buf_act);
    cudaGetSymbolAddress((void**)&p_hpm,   buf_hpm);
    cudaGetSymbolAddress((void**)&p_t1,    buf_t1);
    cudaGetSymbolAddress((void**)&p_attno, buf_attno);
    cudaGetSymbolAddress((void**)&p_aA,    buf_aA);
    cudaGetSymbolAddress((void**)&p_bA,    buf_bA);
    cudaGetSymbolAddress((void**)&p_aO,    buf_aO);
    cudaGetSymbolAddress((void**)&p_bO,    buf_bO);
    cudaGetSymbolAddress((void**)&p_qpart,     buf_qpart);
    cudaGetSymbolAddress((void**)&p_attnopart, buf_attnopart);
    cudaGetSymbolAddress((void**)&p_hpart,     buf_hpart);
    cudaGetSymbolAddress((void**)&p_w1part,    buf_w1part);
    cudaGetSymbolAddress((void**)&p_w2part,    buf_w2part);
    cudaGetSymbolAddress((void**)&p_predpart,  buf_predpart);

    // ---- precompute ----
    gemm_at_tf32<<<dim3(NE / 64, (NB * NT) / 128), 256>>>(x, W_kv, NE, b_kv, p_kv, NE, NC);
    ln_rows<<<NB * NT, 256>>>(p_kv, NE, g_kv, be_kv);
    gemm_tf32<<<dim3(NE / 64, (NB * NT) / 128), 256>>>(p_kv, NE, W_in + NE,     3 * NE, b_in + NE,
                                                       (float*)0, p_Kh, NE, NE, 1);
    gemm_tf32<<<dim3(NE / 64, (NB * NT) / 128), 256>>>(p_kv, NE, W_in + 2 * NE, 3 * NE, b_in + 2 * NE,
                                                       (float*)0, p_Vh, NE, NE, 2);
    gemm_tf32<<<dim3(NE / 64, NE / 128), 256>>>(W_q, NE, W_in, 3 * NE, (const float*)0,
                                                p_Wqq, (bf16*)0, NE, NE, 0);
    make_bqq<<<2, 256>>>(b_q, W_in, b_in);
    init_state<<<(NB * ND + 255) / 256, 256>>>(start);

    // ---- recurrent loop: 12 nodes/step ----
    for (int t = 0; t < NSTEP; t++) {
        const int pi = (t & 1) * NB * 512, po = ((t + 1) & 1) * NB * 512;
        // 1. q partials (fused syncA)
        skinny_fused<<<dim3(8, 8), 256>>>(1, p_act, ND, idx_a, dec_a,
                                          p_aA + pi, p_bA + pi, p_aA + po, p_bA + po,
                                          (float*)0, p_Wqq, NE, p_qpart, NE, 64);
        // 2. attention partials (vectorized bf162)
        attn_partial<<<NB * NH * 8, 256>>>();
        // 3. attno partials (fused combine)
        skinny_fused<<<dim3(8, 8), 256>>>(2, (const float*)0, 0, (const int*)0, (const float*)0,
                                          (const float*)0, (const float*)0, (float*)0, (float*)0,
                                          (float*)0, W_ao, NE, p_attnopart, NE, 64);
        // 4. attno reduce
        reduce_rows<<<(32 * NE + 255) / 256, 256>>>(p_attnopart, b_ao, p_attno, NE, 8, 0);
        // 5. h partials: [attno|act] @ W_syn
        skinny_gemm<<<dim3((2 * ND) / 64, 8), 256>>>(p_attno, NE, p_act, ND,
                                                     W_syn, 2 * ND, p_hpart, 2 * ND, (NE + ND) / 8);
        // 6. GLU + double LN
        glu_ln_ln<<<NB, 256>>>(b_syn, g_syn, be_syn, g_pm, be_pm);
        // 7. W1 partials
        skinny_gemm<<<dim3(ND / 64, 4), 256>>>(p_hpm, ND, (const float*)0, 0,
                                               W1, ND, p_w1part, ND, ND / 4);
        // 8. W1 reduce + relu
        reduce_rows<<<(32 * ND + 255) / 256, 256>>>(p_w1part, b1, p_t1, ND, 4, 1);
        // 9. W2 partials
        skinny_gemm<<<dim3(ND / 64, 4), 256>>>(p_t1, ND, (const float*)0, 0,
                                               W2, ND, p_w2part, ND, ND / 4);
        // 10. W2 reduce + relu -> act
        reduce_rows<<<(32 * ND + 255) / 256, 256>>>(p_w2part, b2, p_act, ND, 4, 1);
        // 11. pred partials (fused syncO)
        skinny_fused<<<dim3(16, 4), 256>>>(5, p_act, ND, idx_o, dec_o,
                                           p_aO + pi, p_bO + pi, p_aO + po, p_bO + po,
                                           (t == NSTEP - 1) ? (out + SYNC_BASE) : (float*)0,
                                           W_out, NOUT, p_predpart, NOUT, 128);
        // 12. entropy + prediction writes
        entropy_write<<<NB, 256>>>(b_out, out, t);
    }
}

// round 11
// speedup vs baseline: 1.3082x; 1.0976x over previous
#include <cuda_runtime.h>
#include <cuda_bf16.h>
#include <math.h>
#include <stdint.h>

// ---------------- problem dims ----------------
#define NB 32
#define NC 512
#define NT 1024
#define NE 512
#define ND 2048
#define NH 8
#define HD 64
#define NSTEP 50
#define NOUT 1000
#define NA_ 512
#define NO_ 512

#define PRED_ELEMS (NB*NOUT*NSTEP)
#define CERT_BASE  PRED_ELEMS
#define SYNC_BASE  (CERT_BASE + NB*2*NSTEP)

typedef __nv_bfloat16 bf16;
typedef __nv_bfloat162 bf162;

// ---------------- device scratch ----------------
__device__ float buf_kv   [NB*NT*NE];
__device__ bf16  buf_Kh   [NB*NT*NE];   // K^T head-major bf16: [b][h][d][n]
__device__ bf16  buf_Vh   [NB*NT*NE];   // V head-major bf16: [b][h][n][d]
__device__ float buf_act  [NB*ND];
__device__ float buf_aA   [2*NB*NA_];
__device__ float buf_bA   [2*NB*NA_];
__device__ float buf_aO   [2*NB*NO_];
__device__ float buf_bO   [2*NB*NO_];
__device__ float buf_attno[NB*NE];
__device__ float buf_hpm  [NB*ND];
__device__ float buf_t1   [NB*ND];
__device__ float buf_Wqq  [NE*NE];
__device__ float buf_bqq  [NE];
// bf16x2 (hi/lo) packed weight planes: [K/2][N] of bf162 (k-pairs packed)
__device__ bf162 w_syn_hi[((NE+ND)/2)*(2*ND)];
__device__ bf162 w_syn_lo[((NE+ND)/2)*(2*ND)];
__device__ bf162 w_1_hi  [(ND/2)*ND];
__device__ bf162 w_1_lo  [(ND/2)*ND];
__device__ bf162 w_2_hi  [(ND/2)*ND];
__device__ bf162 w_2_lo  [(ND/2)*ND];
// split-K partials
__device__ float buf_qpart    [8*32*NE];
__device__ float buf_attnopart[8*32*NE];
__device__ float buf_hpart    [10*32*2*ND];
__device__ float buf_w1part   [8*32*ND];
__device__ float buf_w2part   [8*32*ND];
__device__ float buf_predpart [4*32*NOUT];
// attention partials
__device__ float buf_pv[NB*NH*8*HD];
__device__ float buf_pm[NB*NH*8];
__device__ float buf_ps[NB*NH*8];

// ---------------- cp.async helpers ----------------
__device__ __forceinline__ void cp16(void* smem, const void* gmem) {
    uint32_t s = (uint32_t)__cvta_generic_to_shared(smem);
    asm volatile("cp.async.cg.shared.global [%0], [%1], 16;\n" :: "r"(s), "l"(gmem));
}
#define CP_COMMIT() asm volatile("cp.async.commit_group;\n" ::: "memory")
#define CP_WAIT2()  asm volatile("cp.async.wait_group 2;\n" ::: "memory")
#define CP_WAIT1()  asm volatile("cp.async.wait_group 1;\n" ::: "memory")

// ---------------- mma helpers ----------------
__device__ __forceinline__ uint32_t f2tf(float x) {
    uint32_t r;
    asm("cvt.rna.tf32.f32 %0, %1;" : "=r"(r) : "f"(x));
    return r;
}
__device__ __forceinline__ void mma_tf32(float* c, const uint32_t* a, const uint32_t* b) {
    asm volatile(
        "mma.sync.aligned.m16n8k8.row.col.f32.tf32.tf32.f32 "
        "{%0,%1,%2,%3},{%4,%5,%6,%7},{%8,%9},{%0,%1,%2,%3};"
        : "+f"(c[0]), "+f"(c[1]), "+f"(c[2]), "+f"(c[3])
        : "r"(a[0]), "r"(a[1]), "r"(a[2]), "r"(a[3]), "r"(b[0]), "r"(b[1]));
}
__device__ __forceinline__ void mma_bf16(float* c, const uint32_t* a, const uint32_t* b) {
    asm volatile(
        "mma.sync.aligned.m16n8k16.row.col.f32.bf16.bf16.f32 "
        "{%0,%1,%2,%3},{%4,%5,%6,%7},{%8,%9},{%0,%1,%2,%3};"
        : "+f"(c[0]), "+f"(c[1]), "+f"(c[2]), "+f"(c[3])
        : "r"(a[0]), "r"(a[1]), "r"(a[2]), "r"(a[3]), "r"(b[0]), "r"(b[1]));
}

// ---------------- block reductions ----------------
__device__ __forceinline__ float blockReduceSum(float v) {
    __shared__ float shs[32];
    int lane = threadIdx.x & 31, w = threadIdx.x >> 5;
    #pragma unroll
    for (int o = 16; o; o >>= 1) v += __shfl_xor_sync(0xffffffffu, v, o);
    if (lane == 0) shs[w] = v;
    __syncthreads();
    float r = 0.f;
    int nw = (blockDim.x + 31) >> 5;
    if (threadIdx.x < nw) r = shs[threadIdx.x];
    if (w == 0) {
        #pragma unroll
        for (int o = 16; o; o >>= 1) r += __shfl_xor_sync(0xffffffffu, r, o);
        if (lane == 0) shs[0] = r;
    }
    __syncthreads();
    float out = shs[0];
    __syncthreads();
    return out;
}
__device__ __forceinline__ float blockReduceMax(float v) {
    __shared__ float shm[32];
    int lane = threadIdx.x & 31, w = threadIdx.x >> 5;
    #pragma unroll
    for (int o = 16; o; o >>= 1) v = fmaxf(v, __shfl_xor_sync(0xffffffffu, v, o));
    if (lane == 0) shm[w] = v;
    __syncthreads();
    float r = -1e30f;
    int nw = (blockDim.x + 31) >> 5;
    if (threadIdx.x < nw) r = shm[threadIdx.x];
    if (w == 0) {
        #pragma unroll
        for (int o = 16; o; o >>= 1) r = fmaxf(r, __shfl_xor_sync(0xffffffffu, r, o));
        if (lane == 0) shm[0] = r;
    }
    __syncthreads();
    float out = shm[0];
    __syncthreads();
    return out;
}

// ======================================================================
// tf32 GEMM, A transposed in gmem (fuses (B,C,N)->(B,N,C) transpose)
// ======================================================================
__global__ void gemm_at_tf32(const float* __restrict__ X,
                             const float* __restrict__ B, int ldb,
                             const float* __restrict__ bias,
                             float* __restrict__ C, int ldc, int K) {
    __shared__ float As2[2][16][136];
    __shared__ float Bs[2][16][68];
    const int tid = threadIdx.x;
    const int wid = tid >> 5, lane = tid & 31;
    const int g = lane >> 2, tg = lane & 3;
    const int warp_m = wid >> 1, warp_n = wid & 1;
    const int row0 = blockIdx.y * 128;
    const int col0 = blockIdx.x * 64;
    const int bb_ = row0 >> 10, n0 = row0 & 1023;
    const float* Xb = X + (size_t)bb_ * NC * NT;

    const int la_k = tid >> 4;
    const int la_n = (tid & 15) * 8;
    const int lb_r = tid >> 4;
    const int lb_c = (tid & 15) * 4;

    float acc[2][4][4];
    #pragma unroll
    for (int mi = 0; mi < 2; mi++)
        #pragma unroll
        for (int ni = 0; ni < 4; ni++)
            #pragma unroll
            for (int j = 0; j < 4; j++) acc[mi][ni][j] = 0.f;

    const int ntiles = K >> 4;
    {
        const float* ap = Xb + (size_t)la_k * NT + n0 + la_n;
        cp16(&As2[0][la_k][la_n], ap);
        cp16(&As2[0][la_k][la_n + 4], ap + 4);
        cp16(&Bs[0][lb_r][lb_c], B + (size_t)lb_r * ldb + col0 + lb_c);
    }
    CP_COMMIT();

    for (int ct = 0; ct < ntiles; ct++) {
        if (ct + 1 < ntiles) {
            int k0 = (ct + 1) << 4;
            int st = (ct + 1) & 1;
            const float* ap = Xb + (size_t)(k0 + la_k) * NT + n0 + la_n;
            cp16(&As2[st][la_k][la_n], ap);
            cp16(&As2[st][la_k][la_n + 4], ap + 4);
            cp16(&Bs[st][lb_r][lb_c], B + (size_t)(k0 + lb_r) * ldb + col0 + lb_c);
        }
        CP_COMMIT();
        CP_WAIT1();
        __syncthreads();
        const int st = ct & 1;
        #pragma unroll
        for (int ks = 0; ks < 2; ks++) {
            const int k8 = ks * 8;
            uint32_t a[2][4], bf[4][2];
            #pragma unroll
            for (int mi = 0; mi < 2; mi++) {
                int r = warp_m * 32 + mi * 16 + g;
                a[mi][0] = f2tf(As2[st][k8 + tg][r]);
                a[mi][1] = f2tf(As2[st][k8 + tg][r + 8]);
                a[mi][2] = f2tf(As2[st][k8 + tg + 4][r]);
                a[mi][3] = f2tf(As2[st][k8 + tg + 4][r + 8]);
            }
            #pragma unroll
            for (int ni = 0; ni < 4; ni++) {
                int c = warp_n * 32 + ni * 8 + g;
                bf[ni][0] = f2tf(Bs[st][k8 + tg][c]);
                bf[ni][1] = f2tf(Bs[st][k8 + tg + 4][c]);
            }
            #pragma unroll
            for (int mi = 0; mi < 2; mi++)
                #pragma unroll
                for (int ni = 0; ni < 4; ni++)
                    mma_tf32(acc[mi][ni], a[mi], bf[ni]);
        }
        __syncthreads();
    }

    #pragma unroll
    for (int mi = 0; mi < 2; mi++)
        #pragma unroll
        for (int ni = 0; ni < 4; ni++) {
            int r = row0 + warp_m * 32 + mi * 16 + g;
            int c = col0 + warp_n * 32 + ni * 8 + 2 * tg;
            float b0 = bias ? bias[c] : 0.f;
            float b1 = bias ? bias[c + 1] : 0.f;
            C[(size_t)r * ldc + c] = acc[mi][ni][0] + b0;
            C[(size_t)r * ldc + c + 1] = acc[mi][ni][1] + b1;
            C[(size_t)(r + 8) * ldc + c] = acc[mi][ni][2] + b0;
            C[(size_t)(r + 8) * ldc + c + 1] = acc[mi][ni][3] + b1;
        }
}

// ---------------- tf32 GEMM row-major A --------------------------------
// kvmode: 0 plain fp32; 1 K^T bf16 scatter [b][h][d][n]; 2 V bf16 scatter
__global__ void gemm_tf32(const float* __restrict__ A, int lda,
                          const float* __restrict__ B, int ldb,
                          const float* __restrict__ bias,
                          float* __restrict__ C, bf16* __restrict__ Ch,
                          int ldc, int K, int kvmode) {
    __shared__ float As[2][128][20];
    __shared__ float Bs[2][16][68];
    const int tid = threadIdx.x;
    const int wid = tid >> 5, lane = tid & 31;
    const int g = lane >> 2, tg = lane & 3;
    const int warp_m = wid >> 1, warp_n = wid & 1;
    const int row0 = blockIdx.y * 128;
    const int col0 = blockIdx.x * 64;

    const int la_r = tid >> 1;
    const int la_c = (tid & 1) * 8;
    const int lb_r = tid >> 4;
    const int lb_c = (tid & 15) * 4;

    float acc[2][4][4];
    #pragma unroll
    for (int mi = 0; mi < 2; mi++)
        #pragma unroll
        for (int ni = 0; ni < 4; ni++)
            #pragma unroll
            for (int j = 0; j < 4; j++) acc[mi][ni][j] = 0.f;

    const int ntiles = K >> 4;
    {
        const float* ap = A + (size_t)(row0 + la_r) * lda + la_c;
        cp16(&As[0][la_r][la_c], ap);
        cp16(&As[0][la_r][la_c + 4], ap + 4);
        cp16(&Bs[0][lb_r][lb_c], B + (size_t)lb_r * ldb + col0 + lb_c);
    }
    CP_COMMIT();

    for (int ct = 0; ct < ntiles; ct++) {
        if (ct + 1 < ntiles) {
            int k0 = (ct + 1) << 4;
            int st = (ct + 1) & 1;
            const float* ap = A + (size_t)(row0 + la_r) * lda + k0 + la_c;
            cp16(&As[st][la_r][la_c], ap);
            cp16(&As[st][la_r][la_c + 4], ap + 4);
            cp16(&Bs[st][lb_r][lb_c], B + (size_t)(k0 + lb_r) * ldb + col0 + lb_c);
        }
        CP_COMMIT();
        CP_WAIT1();
        __syncthreads();
        const int st = ct & 1;
        #pragma unroll
        for (int ks = 0; ks < 2; ks++) {
            const int k8 = ks * 8;
            uint32_t a[2][4], bf[4][2];
            #pragma unroll
            for (int mi = 0; mi < 2; mi++) {
                int r = warp_m * 32 + mi * 16 + g;
                a[mi][0] = f2tf(As[st][r][k8 + tg]);
                a[mi][1] = f2tf(As[st][r + 8][k8 + tg]);
                a[mi][2] = f2tf(As[st][r][k8 + tg + 4]);
                a[mi][3] = f2tf(As[st][r + 8][k8 + tg + 4]);
            }
            #pragma unroll
            for (int ni = 0; ni < 4; ni++) {
                int c = warp_n * 32 + ni * 8 + g;
                bf[ni][0] = f2tf(Bs[st][k8 + tg][c]);
                bf[ni][1] = f2tf(Bs[st][k8 + tg + 4][c]);
            }
            #pragma unroll
            for (int mi = 0; mi < 2; mi++)
                #pragma unroll
                for (int ni = 0; ni < 4; ni++)
                    mma_tf32(acc[mi][ni], a[mi], bf[ni]);
        }
        __syncthreads();
    }

    #pragma unroll
    for (int mi = 0; mi < 2; mi++) {
        #pragma unroll
        for (int ni = 0; ni < 4; ni++) {
            int r = row0 + warp_m * 32 + mi * 16 + g;
            int c = col0 + warp_n * 32 + ni * 8 + 2 * tg;
            float b0 = bias ? bias[c] : 0.f;
            float b1 = bias ? bias[c + 1] : 0.f;
            float v00 = acc[mi][ni][0] + b0, v01 = acc[mi][ni][1] + b1;
            float v10 = acc[mi][ni][2] + b0, v11 = acc[mi][ni][3] + b1;
            #pragma unroll
            for (int rr = 0; rr < 2; rr++) {
                int row = r + rr * 8;
                float va = rr ? v10 : v00;
                float vb = rr ? v11 : v01;
                if (kvmode == 0) {
                    C[(size_t)row * ldc + c] = va;
                    C[(size_t)row * ldc + c + 1] = vb;
                } else if (kvmode == 1) {
                    int b = row >> 10, n = row & 1023;
                    int h0 = c >> 6, d0 = c & 63;
                    int h1 = (c + 1) >> 6, d1 = (c + 1) & 63;
                    Ch[(((size_t)(b * NH + h0)) * HD + d0) * NT + n] = __float2bfloat16(va);
                    Ch[(((size_t)(b * NH + h1)) * HD + d1) * NT + n] = __float2bfloat16(vb);
                } else {
                    int b = row >> 10, n = row & 1023;
                    int h0 = c >> 6, d0 = c & 63;
                    int h1 = (c + 1) >> 6, d1 = (c + 1) & 63;
                    Ch[((((size_t)b * NH + h0) << 10) + n) * HD + d0] = __float2bfloat16(va);
                    Ch[((((size_t)b * NH + h1) << 10) + n) * HD + d1] = __float2bfloat16(vb);
                }
            }
        }
    }
}

// ---------------- row LayerNorm ----------------
__global__ void ln_rows(float* __restrict__ X, int L,
                        const float* __restrict__ g, const float* __restrict__ b) {
    int row = blockIdx.x;
    float* xp = X + (size_t)row * L;
    float s = 0.f;
    for (int i = threadIdx.x; i < L; i += blockDim.x) s += xp[i];
    s = blockReduceSum(s);
    float m = s / L;
    float v = 0.f;
    for (int i = threadIdx.x; i < L; i += blockDim.x) { float d = xp[i] - m; v += d * d; }
    v = blockReduceSum(v);
    float inv = rsqrtf(v / L + 1e-5f);
    for (int i = threadIdx.x; i < L; i += blockDim.x)
        xp[i] = (xp[i] - m) * inv * g[i] + b[i];
}

__global__ void make_bqq(const float* __restrict__ b_q, const float* __restrict__ W_in,
                         const float* __restrict__ b_in) {
    int j = blockIdx.x * blockDim.x + threadIdx.x;
    if (j >= NE) return;
    float s = b_in[j];
    for (int k = 0; k < NE; k++) s += b_q[k] * W_in[(size_t)k * (3 * NE) + j];
    buf_bqq[j] = s;
}

__global__ void init_state(const float* __restrict__ start) {
    int i = blockIdx.x * blockDim.x + threadIdx.x;
    if (i < NB * ND) buf_act[i] = start[i & (ND - 1)];
    if (i < NB * NA_) {
        buf_aA[i] = 0.f; buf_bA[i] = 0.f;
        buf_aO[i] = 0.f; buf_bO[i] = 0.f;
    }
}

// -------- one-time: split fp32 W[K][N] into hi/lo bf16 k-pair-packed -----
__global__ void split_w(const float* __restrict__ W, int N,
                        bf162* __restrict__ hi, bf162* __restrict__ lo, int totalPairs) {
    int i = blockIdx.x * 256 + threadIdx.x;
    if (i >= totalPairs) return;
    int kk = i / N, c = i - kk * N;
    float a0 = W[(size_t)(2 * kk) * N + c];
    float a1 = W[(size_t)(2 * kk + 1) * N + c];
    bf16 h0 = __float2bfloat16(a0);
    bf16 h1 = __float2bfloat16(a1);
    bf16 l0 = __float2bfloat16(a0 - __bfloat162float(h0));
    bf16 l1 = __float2bfloat16(a1 - __bfloat162float(h1));
    hi[i] = __halves2bfloat162(h0, h1);
    lo[i] = __halves2bfloat162(l0, l1);
}

// ======================================================================
// bf16x3 emulated-fp32 skinny GEMM on tensor cores.
// A = [A0 (K0) | A1 (K1)] fp32, split to bf16 hi/lo in smem.
// B given as precomputed hi/lo packed planes [K/2][N] bf162.
// Kper fixed 256. grid = (Nout/64, Ktotal/256), 256 threads (8 warps).
// partout[(by*32 + r)*Nout + c] = partial sum over this k-slice.
// ======================================================================
__global__ void skinny_mma(const float* __restrict__ A0, int K0,
                           const float* __restrict__ A1, int K1,
                           const bf162* __restrict__ Bhi, const bf162* __restrict__ Blo,
                           int ldb,
                           float* __restrict__ partout, int Nout) {
    __shared__ bf162 Ah[32][132];
    __shared__ bf162 Al[32][132];
    __shared__ bf162 Bs[3][2][8][68];
    const int tid = threadIdx.x;
    const int wid = tid >> 5, lane = tid & 31;
    const int g = lane >> 2, tg = lane & 3;
    const int col0 = blockIdx.x * 64;
    const int kstart = blockIdx.y * 256;
    const int khalf = kstart >> 1;
    const int ntiles = 16;

    // B prologue: 2 stages in flight during A build.
    const int bp = tid >> 7;            // plane 0=hi,1=lo
    const int br = (tid >> 4) & 7;      // k-pair row 0..7
    const int bc = (tid & 15) * 4;      // col, 4 bf162 per cp16
    const bf162* bsrc = bp ? Blo : Bhi;
    #pragma unroll
    for (int pt = 0; pt < 2; pt++) {
        cp16(&Bs[pt][bp][br][bc], bsrc + (size_t)(khalf + pt * 8 + br) * ldb + col0 + bc);
        CP_COMMIT();
    }

    // A build: 32 rows x 128 k-pairs, hi/lo split
    for (int e = tid; e < 32 * 128; e += 256) {
        int r = e >> 7, kk = e & 127;
        int k = kstart + 2 * kk;
        float a0, a1;
        if (k < K0) {
            a0 = A0[(size_t)r * K0 + k];
            a1 = A0[(size_t)r * K0 + k + 1];
        } else {
            a0 = A1[(size_t)r * K1 + (k - K0)];
            a1 = A1[(size_t)r * K1 + (k - K0) + 1];
        }
        bf16 h0 = __float2bfloat16(a0);
        bf16 h1 = __float2bfloat16(a1);
        bf16 l0 = __float2bfloat16(a0 - __bfloat162float(h0));
        bf16 l1 = __float2bfloat16(a1 - __bfloat162float(h1));
        Ah[r][kk] = __halves2bfloat162(h0, h1);
        Al[r][kk] = __halves2bfloat162(l0, l1);
    }
    __syncthreads();

    float acc[2][4];
    #pragma unroll
    for (int mt = 0; mt < 2; mt++)
        #pragma unroll
        for (int j = 0; j < 4; j++) acc[mt][j] = 0.f;

    const int cw = wid * 8 + g;   // column within 64-slice for B/C fragments

    for (int ct = 0; ct < ntiles; ct++) {
        CP_WAIT1();
        __syncthreads();
        const int st = ct % 3;
        const int base = ct * 8;  // k-pair base for this 16-k tile

        uint32_t ah[2][4], al[2][4], bh[2], bl[2];
        #pragma unroll
        for (int mt = 0; mt < 2; mt++) {
            int r = mt * 16 + g;
            ah[mt][0] = *(const uint32_t*)&Ah[r][base + tg];
            ah[mt][1] = *(const uint32_t*)&Ah[r + 8][base + tg];
            ah[mt][2] = *(const uint32_t*)&Ah[r][base + tg + 4];
            ah[mt][3] = *(const uint32_t*)&Ah[r + 8][base + tg + 4];
            al[mt][0] = *(const uint32_t*)&Al[r][base + tg];
            al[mt][1] = *(const uint32_t*)&Al[r + 8][base + tg];
            al[mt][2] = *(const uint32_t*)&Al[r][base + tg + 4];
            al[mt][3] = *(const uint32_t*)&Al[r + 8][base + tg + 4];
        }
        bh[0] = *(const uint32_t*)&Bs[st][0][tg][cw];
        bh[1] = *(const uint32_t*)&Bs[st][0][tg + 4][cw];
        bl[0] = *(const uint32_t*)&Bs[st][1][tg][cw];
        bl[1] = *(const uint32_t*)&Bs[st][1][tg + 4][cw];

        #pragma unroll
        for (int mt = 0; mt < 2; mt++) {
            mma_bf16(acc[mt], ah[mt], bh);
            mma_bf16(acc[mt], ah[mt], bl);
            mma_bf16(acc[mt], al[mt], bh);
        }

        int nt = ct + 2;
        if (nt < ntiles)
            cp16(&Bs[nt % 3][bp][br][bc], bsrc + (size_t)(khalf + nt * 8 + br) * ldb + col0 + bc);
        CP_COMMIT();
    }

    float* po = partout + ((size_t)blockIdx.y * 32) * Nout;
    #pragma unroll
    for (int mt = 0; mt < 2; mt++) {
        int r = mt * 16 + g;
        int c = col0 + wid * 8 + 2 * tg;
        po[(size_t)r * Nout + c]           = acc[mt][0];
        po[(size_t)r * Nout + c + 1]       = acc[mt][1];
        po[(size_t)(r + 8) * Nout + c]     = acc[mt][2];
        po[(size_t)(r + 8) * Nout + c + 1] = acc[mt][3];
    }
}

// ======================================================================
// Fused light skinny GEMM (fp32 B).
// modes: 1 = syncA update; 2 = attention combine; 5 = syncO update
// ======================================================================
#define SKS 4
__global__ void skinny_fused(int mode,
                             const float* __restrict__ A0, int lda,
                             const int* __restrict__ idx, const float* __restrict__ decay,
                             const float* __restrict__ st_a_in, const float* __restrict__ st_b_in,
                             float* __restrict__ st_a_out, float* __restrict__ st_b_out,
                             float* __restrict__ sync_final,
                             const float* __restrict__ B, int ldb,
                             float* __restrict__ partout, int Nout, int Kper) {
    __shared__ float As[32][129];
    __shared__ float Bs[SKS][16][64];
    __shared__ float wno[32][8];
    __shared__ float Tinv[32];
    const int tid = threadIdx.x;
    const int col0 = blockIdx.x * 64;
    const int kstart = blockIdx.y * Kper;
    const int ntiles = Kper >> 4;
    const int kshift = (Kper == 64) ? 6 : 7;

    const int bkk = tid >> 4, bc = (tid & 15) * 4;
    int bcol = col0 + bc;
    if (bcol > Nout - 4) bcol = Nout - 4;
    #pragma unroll
    for (int pt = 0; pt < SKS - 1; pt++) {
        if (pt < ntiles)
            cp16(&Bs[pt][bkk][bc], B + (size_t)(kstart + pt * 16 + bkk) * ldb + bcol);
        CP_COMMIT();
    }

    if (mode == 2) {
        if (tid < 32) {
            int h = kstart >> 6, b = tid;
            float M = -1e30f;
            #pragma unroll
            for (int c = 0; c < 8; c++) M = fmaxf(M, buf_pm[(b * NH + h) * 8 + c]);
            float T = 0.f;
            #pragma unroll
            for (int c = 0; c < 8; c++) {
                float w = expf(buf_pm[(b * NH + h) * 8 + c] - M);
                wno[b][c] = w;
                T += buf_ps[(b * NH + h) * 8 + c] * w;
            }
            Tinv[b] = 1.f / T;
        }
        __syncthreads();
    }

    // ---- A build ----
    for (int e = tid; e < 32 * Kper; e += 256) {
        int r = e >> kshift;
        int j = e & (Kper - 1);
        int k = kstart + j;
        float v;
        if (mode == 2) {
            int h = kstart >> 6;
            const float* pvp = buf_pv + ((size_t)(r * NH + h) * 8) * HD + j;
            float acc = 0.f;
            #pragma unroll
            for (int c = 0; c < 8; c++) acc += pvp[c * HD] * wno[r][c];
            v = acc * Tinv[r];
        } else {
            float rr = expf(-fminf(fmaxf(decay[k], 0.f), 15.f));
            float sel = A0[(size_t)r * lda + idx[k]];
            float a = rr * st_a_in[r * 512 + k] + sel * sel;
            float bb = rr * st_b_in[r * 512 + k] + 1.f;
            st_a_out[r * 512 + k] = a;
            st_b_out[r * 512 + k] = bb;
            v = a * rsqrtf(bb);
            if (sync_final) sync_final[r * 512 + k] = v;
        }
        As[r][j] = v;
    }
    __syncthreads();

    // ---- B streaming + FMA ----
    const int c4 = (tid & 15) * 4;
    const int r0 = (tid >> 4) * 2;
    float acc0[4] = {0.f, 0.f, 0.f, 0.f};
    float acc1[4] = {0.f, 0.f, 0.f, 0.f};

    for (int ct = 0; ct < ntiles; ct++) {
        CP_WAIT2();
        __syncthreads();
        const int st = ct & (SKS - 1);
        const float* a0p = &As[r0][ct * 16];
        const float* a1p = &As[r0 + 1][ct * 16];
        #pragma unroll
        for (int kk = 0; kk < 16; kk++) {
            float4 bv = *(const float4*)&Bs[st][kk][c4];
            float a0 = a0p[kk], a1 = a1p[kk];
            acc0[0] += a0 * bv.x; acc0[1] += a0 * bv.y;
            acc0[2] += a0 * bv.z; acc0[3] += a0 * bv.w;
            acc1[0] += a1 * bv.x; acc1[1] += a1 * bv.y;
            acc1[2] += a1 * bv.z; acc1[3] += a1 * bv.w;
        }
        __syncthreads();
        int nt = ct + SKS - 1;
        if (nt < ntiles)
            cp16(&Bs[nt & (SKS - 1)][bkk][bc], B + (size_t)(kstart + nt * 16 + bkk) * ldb + bcol);
        CP_COMMIT();
    }

    float* po = partout + ((size_t)blockIdx.y * 32 + r0) * Nout;
    #pragma unroll
    for (int j = 0; j < 4; j++) {
        int c = col0 + c4 + j;
        if (c < Nout) {
            po[c] = acc0[j];
            po[Nout + c] = acc1[j];
        }
    }
}

// ---------------- split-K reduce ----------------
__global__ void reduce_rows(const float* __restrict__ part, const float* __restrict__ bias,
                            float* __restrict__ out, int Nout, int nsplit, int relu) {
    int i = blockIdx.x * 256 + threadIdx.x;
    if (i >= 32 * Nout) return;
    int r = i / Nout, c = i - r * Nout;
    float s = bias[c];
    for (int k = 0; k < nsplit; k++) s += part[((size_t)k * 32 + r) * Nout + c];
    out[i] = relu ? fmaxf(s, 0.f) : s;
}

// ---------------- attention partial (vectorized bf162 K and V) ----------
__global__ void attn_partial() {
    const int bh = blockIdx.x >> 3;
    const int chunk = blockIdx.x & 7;
    const int b = bh >> 3, h = bh & 7;
    const int tid = threadIdx.x;
    __shared__ float qs[64];
    __shared__ float sc4[4][128];
    __shared__ float ev[128];
    __shared__ float red[8][64];

    if (tid < 64) {
        float q = buf_bqq[h * HD + tid];
        #pragma unroll
        for (int s = 0; s < 8; s++) q += buf_qpart[((size_t)s * 32 + b) * NE + h * HD + tid];
        qs[tid] = q;
    }
    __syncthreads();

    {
        const int n0 = (tid & 63) * 2;
        const int dh = tid >> 6;
        const bf16* KT = buf_Kh + ((size_t)bh * HD + dh * 16) * NT + (chunk << 7) + n0;
        float px = 0.f, py = 0.f;
        #pragma unroll
        for (int d = 0; d < 16; d++) {
            float2 kf = __bfloat1622float2(*(const bf162*)(KT + (size_t)d * NT));
            float qv = qs[dh * 16 + d];
            px += qv * kf.x;
            py += qv * kf.y;
        }
        sc4[dh][n0] = px;
        sc4[dh][n0 + 1] = py;
    }
    __syncthreads();

    const int n = tid & 127;
    float score = (tid < 128)
        ? (sc4[0][n] + sc4[1][n] + sc4[2][n] + sc4[3][n]) * 0.125f
        : -1e30f;
    float m = blockReduceMax(score);
    float e = (tid < 128) ? expf(score - m) : 0.f;
    float s = blockReduceSum(e);
    if (tid < 128) ev[n] = e;
    __syncthreads();

    {
        const int d0 = (tid & 31) * 2;
        const int grp = tid >> 5;
        const bf16* Vb = buf_Vh + (((size_t)bh << 10) + (chunk << 7) + grp * 16) * HD + d0;
        float ax = 0.f, ay = 0.f;
        #pragma unroll
        for (int nn = 0; nn < 16; nn++) {
            float2 vf = __bfloat1622float2(*(const bf162*)(Vb + (size_t)nn * HD));
            float w = ev[grp * 16 + nn];
            ax += w * vf.x;
            ay += w * vf.y;
        }
        red[grp][d0] = ax;
        red[grp][d0 + 1] = ay;
    }
    __syncthreads();
    if (tid < 64) {
        float v = 0.f;
        #pragma unroll
        for (int g = 0; g < 8; g++) v += red[g][tid];
        buf_pv[(size_t)blockIdx.x * HD + tid] = v;
        if (tid == 0) { buf_pm[blockIdx.x] = m; buf_ps[blockIdx.x] = s; }
    }
}

// ---------------- fused 10-split reduce + GLU + double LN ----------------
__global__ void glu_ln_ln(const float* __restrict__ b_syn,
                          const float* __restrict__ g_syn, const float* __restrict__ be_syn,
                          const float* __restrict__ g_pm, const float* __restrict__ be_pm) {
    int b = blockIdx.x, tid = threadIdx.x;
    float v[8];
    #pragma unroll
    for (int j = 0; j < 8; j++) {
        int d = tid + j * 256;
        float a = b_syn[d], gg = b_syn[ND + d];
        #pragma unroll
        for (int s = 0; s < 10; s++) {
            const float* hp = buf_hpart + ((size_t)s * 32 + b) * (2 * ND);
            a += hp[d];
            gg += hp[ND + d];
        }
        v[j] = a * (1.f / (1.f + expf(-gg)));
    }
    float s = 0.f;
    #pragma unroll
    for (int j = 0; j < 8; j++) s += v[j];
    s = blockReduceSum(s);
    float m = s / ND;
    float var = 0.f;
    #pragma unroll
    for (int j = 0; j < 8; j++) { float d = v[j] - m; var += d * d; }
    var = blockReduceSum(var);
    float inv = rsqrtf(var / ND + 1e-5f);
    #pragma unroll
    for (int j = 0; j < 8; j++) {
        int d = tid + j * 256;
        v[j] = (v[j] - m) * inv * g_syn[d] + be_syn[d];
    }
    s = 0.f;
    #pragma unroll
    for (int j = 0; j < 8; j++) s += v[j];
    s = blockReduceSum(s);
    float m2 = s / ND;
    var = 0.f;
    #pragma unroll
    for (int j = 0; j < 8; j++) { float d = v[j] - m2; var += d * d; }
    var = blockReduceSum(var);
    float inv2 = rsqrtf(var / ND + 1e-5f);
    #pragma unroll
    for (int j = 0; j < 8; j++) {
        int d = tid + j * 256;
        buf_hpm[(size_t)b * ND + d] = (v[j] - m2) * inv2 * g_pm[d] + be_pm[d];
    }
}

// ---------------- pred reduce + entropy + writes ----------------
__global__ void entropy_write(const float* __restrict__ b_out, float* __restrict__ dout, int t) {
    int b = blockIdx.x, tid = threadIdx.x;
    __shared__ float sp[NOUT];
    for (int i = tid; i < NOUT; i += 256) {
        float v = b_out[i];
        #pragma unroll
        for (int s = 0; s < 4; s++) v += buf_predpart[((size_t)s * 32 + b) * NOUT + i];
        sp[i] = v;
    }
    __syncthreads();
    float m = -1e30f;
    for (int i = tid; i < NOUT; i += 256) m = fmaxf(m, sp[i]);
    m = blockReduceMax(m);
    float s = 0.f;
    for (int i = tid; i < NOUT; i += 256) s += expf(sp[i] - m);
    s = blockReduceSum(s);
    float lse = m + logf(s);
    float ent = 0.f;
    for (int i = tid; i < NOUT; i += 256) {
        float pv = sp[i];
        float lp = pv - lse;
        ent += expf(lp) * lp;
        dout[(size_t)b * NOUT * NSTEP + (size_t)i * NSTEP + t] = pv;
    }
    ent = blockReduceSum(ent);
    if (tid == 0) {
        float ne = -ent / logf((float)NOUT);
        dout[CERT_BASE + b * (2 * NSTEP) + t] = ne;
        dout[CERT_BASE + b * (2 * NSTEP) + NSTEP + t] = 1.f - ne;
    }
}

// ---------------- launch ----------------
extern "C" void kernel_launch(void* const* d_in, const int* in_sizes, int n_in,
                              void* d_out, int out_size) {
    const float* x     = (const float*)d_in[0];
    const float* W_kv  = (const float*)d_in[1];
    const float* b_kv  = (const float*)d_in[2];
    const float* g_kv  = (const float*)d_in[3];
    const float* be_kv = (const float*)d_in[4];
    const float* W_q   = (const float*)d_in[5];
    const float* b_q   = (const float*)d_in[6];
    const float* W_in  = (const float*)d_in[7];
    const float* b_in  = (const float*)d_in[8];
    const float* W_ao  = (const float*)d_in[9];
    const float* b_ao  = (const float*)d_in[10];
    const float* W_syn = (const float*)d_in[11];
    const float* b_syn = (const float*)d_in[12];
    const float* g_syn = (const float*)d_in[13];
    const float* be_syn= (const float*)d_in[14];
    const float* g_pm  = (const float*)d_in[15];
    const float* be_pm = (const float*)d_in[16];
    const float* W1    = (const float*)d_in[17];
    const float* b1    = (const float*)d_in[18];
    const float* W2    = (const float*)d_in[19];
    const float* b2    = (const float*)d_in[20];
    const float* start = (const float*)d_in[21];
    const float* dec_a = (const float*)d_in[22];
    const float* dec_o = (const float*)d_in[23];
    const float* W_out = (const float*)d_in[24];
    const float* b_out = (const float*)d_in[25];
    const int*   idx_a = (const int*)d_in[26];
    const int*   idx_o = (const int*)d_in[27];
    float* out = (float*)d_out;

    float *p_kv, *p_Wqq, *p_act, *p_hpm, *p_t1, *p_attno;
    bf16 *p_Kh, *p_Vh;
    bf162 *p_syn_hi, *p_syn_lo, *p_w1_hi, *p_w1_lo, *p_w2_hi, *p_w2_lo;
    float *p_aA, *p_bA, *p_aO, *p_bO;
    float *p_qpart, *p_attnopart, *p_hpart, *p_w1part, *p_w2part, *p_predpart;
    cudaGetSymbolAddress((void**)&p_kv,    buf_kv);
    cudaGetSymbolAddress((void**)&p_Kh,    buf_Kh);
    cudaGetSymbolAddress((void**)&p_Vh,    buf_Vh);
    cudaGetSymbolAddress((void**)&p_Wqq,   buf_Wqq);
    cudaGetSymbolAddress((void**)&p_act,   buf_act);
    cudaGetSymbolAddress((void**)&p_hpm,   buf_hpm);
    cudaGetSymbolAddress((void**)&p_t1,    buf_t1);
    cudaGetSymbolAddress((void**)&p_attno, buf_attno);
    cudaGetSymbolAddress((void**)&p_aA,    buf_aA);
    cudaGetSymbolAddress((void**)&p_bA,    buf_bA);
    cudaGetSymbolAddress((void**)&p_aO,    buf_aO);
    cudaGetSymbolAddress((void**)&p_bO,    buf_bO);
    cudaGetSymbolAddress((void**)&p_syn_hi, w_syn_hi);
    cudaGetSymbolAddress((void**)&p_syn_lo, w_syn_lo);
    cudaGetSymbolAddress((void**)&p_w1_hi,  w_1_hi);
    cudaGetSymbolAddress((void**)&p_w1_lo,  w_1_lo);
    cudaGetSymbolAddress((void**)&p_w2_hi,  w_2_hi);
    cudaGetSymbolAddress((void**)&p_w2_lo,  w_2_lo);
    cudaGetSymbolAddress((void**)&p_qpart,     buf_qpart);
    cudaGetSymbolAddress((void**)&p_attnopart, buf_attnopart);
    cudaGetSymbolAddress((void**)&p_hpart,     buf_hpart);
    cudaGetSymbolAddress((void**)&p_w1part,    buf_w1part);
    cudaGetSymbolAddress((void**)&p_w2part,    buf_w2part);
    cudaGetSymbolAddress((void**)&p_predpart,  buf_predpart);

    // ---- precompute ----
    gemm_at_tf32<<<dim3(NE / 64, (NB * NT) / 128), 256>>>(x, W_kv, NE, b_kv, p_kv, NE, NC);
    ln_rows<<<NB * NT, 256>>>(p_kv, NE, g_kv, be_kv);
    gemm_tf32<<<dim3(NE / 64, (NB * NT) / 128), 256>>>(p_kv, NE, W_in + NE,     3 * NE, b_in + NE,
                                                       (float*)0, p_Kh, NE, NE, 1);
    gemm_tf32<<<dim3(NE / 64, (NB * NT) / 128), 256>>>(p_kv, NE, W_in + 2 * NE, 3 * NE, b_in + 2 * NE,
                                                       (float*)0, p_Vh, NE, NE, 2);
    gemm_tf32<<<dim3(NE / 64, NE / 128), 256>>>(W_q, NE, W_in, 3 * NE, (const float*)0,
                                                p_Wqq, (bf16*)0, NE, NE, 0);
    make_bqq<<<2, 256>>>(b_q, W_in, b_in);
    init_state<<<(NB * ND + 255) / 256, 256>>>(start);
    // one-time hi/lo weight splits
    {
        int n1 = ((NE + ND) / 2) * (2 * ND);
        split_w<<<(n1 + 255) / 256, 256>>>(W_syn, 2 * ND, p_syn_hi, p_syn_lo, n1);
        int n2 = (ND / 2) * ND;
        split_w<<<(n2 + 255) / 256, 256>>>(W1, ND, p_w1_hi, p_w1_lo, n2);
        split_w<<<(n2 + 255) / 256, 256>>>(W2, ND, p_w2_hi, p_w2_lo, n2);
    }

    // ---- recurrent loop: 12 nodes/step ----
    for (int t = 0; t < NSTEP; t++) {
        const int pi = (t & 1) * NB * 512, po = ((t + 1) & 1) * NB * 512;
        // 1. q partials (fused syncA)
        skinny_fused<<<dim3(8, 8), 256>>>(1, p_act, ND, idx_a, dec_a,
                                          p_aA + pi, p_bA + pi, p_aA + po, p_bA + po,
                                          (float*)0, p_Wqq, NE, p_qpart, NE, 64);
        // 2. attention partials (vectorized bf162)
        attn_partial<<<NB * NH * 8, 256>>>();
        // 3. attno partials (fused combine)
        skinny_fused<<<dim3(8, 8), 256>>>(2, (const float*)0, 0, (const int*)0, (const float*)0,
                                          (const float*)0, (const float*)0, (float*)0, (float*)0,
                                          (float*)0, W_ao, NE, p_attnopart, NE, 64);
        // 4. attno reduce
        reduce_rows<<<(32 * NE + 255) / 256, 256>>>(p_attnopart, b_ao, p_attno, NE, 8, 0);
        // 5. h partials: [attno|act] @ W_syn   (bf16x3 tensor-core, 10 splits)
        skinny_mma<<<dim3((2 * ND) / 64, 10), 256>>>(p_attno, NE, p_act, ND,
                                                     p_syn_hi, p_syn_lo, 2 * ND,
                                                     p_hpart, 2 * ND);
        // 6. GLU + double LN (10-way reduce)
        glu_ln_ln<<<NB, 256>>>(b_syn, g_syn, be_syn, g_pm, be_pm);
        // 7. W1 partials (bf16x3, 8 splits)
        skinny_mma<<<dim3(ND / 64, 8), 256>>>(p_hpm, ND, (const float*)0, 0,
                                              p_w1_hi, p_w1_lo, ND,
                                              p_w1part, ND);
        // 8. W1 reduce + relu
        reduce_rows<<<(32 * ND + 255) / 256, 256>>>(p_w1part, b1, p_t1, ND, 8, 1);
        // 9. W2 partials (bf16x3, 8 splits)
        skinny_mma<<<dim3(ND / 64, 8), 256>>>(p_t1, ND, (const float*)0, 0,
                                              p_w2_hi, p_w2_lo, ND,
                                              p_w2part, ND);
        // 10. W2 reduce + relu -> act
        reduce_rows<<<(32 * ND + 255) / 256, 256>>>(p_w2part, b2, p_act, ND, 8, 1);
        // 11. pred partials (fused syncO)
        skinny_fused<<<dim3(16, 4), 256>>>(5, p_act, ND, idx_o, dec_o,
                                           p_aO + pi, p_bO + pi, p_aO + po, p_bO + po,
                                           (t == NSTEP - 1) ? (out + SYNC_BASE) : (float*)0,
                                           W_out, NOUT, p_predpart, NOUT, 128);
        // 12. entropy + prediction writes
        entropy_write<<<NB, 256>>>(b_out, out, t);
    }
}

// round 14
// speedup vs baseline: 1.3143x; 1.0046x over previous
#include <cuda_runtime.h>
#include <cuda_bf16.h>
#include <math.h>
#include <stdint.h>

// ---------------- problem dims ----------------
#define NB 32
#define NC 512
#define NT 1024
#define NE 512
#define ND 2048
#define NH 8
#define HD 64
#define NSTEP 50
#define NOUT 1000
#define NA_ 512
#define NO_ 512

#define PRED_ELEMS (NB*NOUT*NSTEP)
#define CERT_BASE  PRED_ELEMS
#define SYNC_BASE  (CERT_BASE + NB*2*NSTEP)

typedef __nv_bfloat16 bf16;
typedef __nv_bfloat162 bf162;

// ---------------- device scratch ----------------
__device__ float buf_kv   [NB*NT*NE];
__device__ bf16  buf_Kh   [NB*NT*NE];   // K^T head-major bf16: [b][h][d][n]
__device__ bf16  buf_Vh   [NB*NT*NE];   // V head-major bf16: [b][h][n][d]
__device__ float buf_act  [NB*ND];
__device__ float buf_aA   [2*NB*NA_];
__device__ float buf_bA   [2*NB*NA_];
__device__ float buf_aO   [2*NB*NO_];
__device__ float buf_bO   [2*NB*NO_];
__device__ float buf_attno[NB*NE];
__device__ float buf_hpm  [NB*ND];
__device__ float buf_t1   [NB*ND];
__device__ float buf_Wqq  [NE*NE];
__device__ float buf_bqq  [NE];
// bf16x2 (hi/lo) packed weight planes: [K/2][N] of bf162 (k-pairs packed)
__device__ bf162 w_syn_hi[((NE+ND)/2)*(2*ND)];
__device__ bf162 w_syn_lo[((NE+ND)/2)*(2*ND)];
__device__ bf162 w_1_hi  [(ND/2)*ND];
__device__ bf162 w_1_lo  [(ND/2)*ND];
__device__ bf162 w_2_hi  [(ND/2)*ND];
__device__ bf162 w_2_lo  [(ND/2)*ND];
// split-K partials
__device__ float buf_qpart    [8*32*NE];
__device__ float buf_attnopart[8*32*NE];
__device__ float buf_hpart    [10*32*2*ND];
__device__ float buf_w1part   [8*32*ND];
__device__ float buf_w2part   [8*32*ND];
__device__ float buf_predpart [4*32*NOUT];
// attention partials
__device__ float buf_pv[NB*NH*8*HD];
__device__ float buf_pm[NB*NH*8];
__device__ float buf_ps[NB*NH*8];

// ---------------- cp.async helpers ----------------
__device__ __forceinline__ void cp16(void* smem, const void* gmem) {
    uint32_t s = (uint32_t)__cvta_generic_to_shared(smem);
    asm volatile("cp.async.cg.shared.global [%0], [%1], 16;\n" :: "r"(s), "l"(gmem));
}
#define CP_COMMIT() asm volatile("cp.async.commit_group;\n" ::: "memory")
#define CP_WAIT2()  asm volatile("cp.async.wait_group 2;\n" ::: "memory")
#define CP_WAIT1()  asm volatile("cp.async.wait_group 1;\n" ::: "memory")

// ---------------- mma helpers ----------------
// tf32 mma ignores the low 13 mantissa bits: pass raw fp32 bits (RZ rounding),
// deleting the cvt.rna.tf32 ALU op per operand-use.
__device__ __forceinline__ uint32_t f2tf(float x) {
    return __float_as_uint(x);
}
__device__ __forceinline__ void mma_tf32(float* c, const uint32_t* a, const uint32_t* b) {
    asm volatile(
        "mma.sync.aligned.m16n8k8.row.col.f32.tf32.tf32.f32 "
        "{%0,%1,%2,%3},{%4,%5,%6,%7},{%8,%9},{%0,%1,%2,%3};"
        : "+f"(c[0]), "+f"(c[1]), "+f"(c[2]), "+f"(c[3])
        : "r"(a[0]), "r"(a[1]), "r"(a[2]), "r"(a[3]), "r"(b[0]), "r"(b[1]));
}
__device__ __forceinline__ void mma_bf16(float* c, const uint32_t* a, const uint32_t* b) {
    asm volatile(
        "mma.sync.aligned.m16n8k16.row.col.f32.bf16.bf16.f32 "
        "{%0,%1,%2,%3},{%4,%5,%6,%7},{%8,%9},{%0,%1,%2,%3};"
        : "+f"(c[0]), "+f"(c[1]), "+f"(c[2]), "+f"(c[3])
        : "r"(a[0]), "r"(a[1]), "r"(a[2]), "r"(a[3]), "r"(b[0]), "r"(b[1]));
}

// ---------------- block reductions ----------------
__device__ __forceinline__ float blockReduceSum(float v) {
    __shared__ float shs[32];
    int lane = threadIdx.x & 31, w = threadIdx.x >> 5;
    #pragma unroll
    for (int o = 16; o; o >>= 1) v += __shfl_xor_sync(0xffffffffu, v, o);
    if (lane == 0) shs[w] = v;
    __syncthreads();
    float r = 0.f;
    int nw = (blockDim.x + 31) >> 5;
    if (threadIdx.x < nw) r = shs[threadIdx.x];
    if (w == 0) {
        #pragma unroll
        for (int o = 16; o; o >>= 1) r += __shfl_xor_sync(0xffffffffu, r, o);
        if (lane == 0) shs[0] = r;
    }
    __syncthreads();
    float out = shs[0];
    __syncthreads();
    return out;
}
__device__ __forceinline__ float blockReduceMax(float v) {
    __shared__ float shm[32];
    int lane = threadIdx.x & 31, w = threadIdx.x >> 5;
    #pragma unroll
    for (int o = 16; o; o >>= 1) v = fmaxf(v, __shfl_xor_sync(0xffffffffu, v, o));
    if (lane == 0) shm[w] = v;
    __syncthreads();
    float r = -1e30f;
    int nw = (blockDim.x + 31) >> 5;
    if (threadIdx.x < nw) r = shm[threadIdx.x];
    if (w == 0) {
        #pragma unroll
        for (int o = 16; o; o >>= 1) r = fmaxf(r, __shfl_xor_sync(0xffffffffu, r, o));
        if (lane == 0) shm[0] = r;
    }
    __syncthreads();
    float out = shm[0];
    __syncthreads();
    return out;
}

// ======================================================================
// tf32 GEMM, A transposed in gmem (fuses (B,C,N)->(B,N,C) transpose)
// ======================================================================
__global__ void gemm_at_tf32(const float* __restrict__ X,
                             const float* __restrict__ B, int ldb,
                             const float* __restrict__ bias,
                             float* __restrict__ C, int ldc, int K) {
    __shared__ float As2[2][16][136];
    __shared__ float Bs[2][16][68];
    const int tid = threadIdx.x;
    const int wid = tid >> 5, lane = tid & 31;
    const int g = lane >> 2, tg = lane & 3;
    const int warp_m = wid >> 1, warp_n = wid & 1;
    const int row0 = blockIdx.y * 128;
    const int col0 = blockIdx.x * 64;
    const int bb_ = row0 >> 10, n0 = row0 & 1023;
    const float* Xb = X + (size_t)bb_ * NC * NT;

    const int la_k = tid >> 4;
    const int la_n = (tid & 15) * 8;
    const int lb_r = tid >> 4;
    const int lb_c = (tid & 15) * 4;

    float acc[2][4][4];
    #pragma unroll
    for (int mi = 0; mi < 2; mi++)
        #pragma unroll
        for (int ni = 0; ni < 4; ni++)
            #pragma unroll
            for (int j = 0; j < 4; j++) acc[mi][ni][j] = 0.f;

    const int ntiles = K >> 4;
    {
        const float* ap = Xb + (size_t)la_k * NT + n0 + la_n;
        cp16(&As2[0][la_k][la_n], ap);
        cp16(&As2[0][la_k][la_n + 4], ap + 4);
        cp16(&Bs[0][lb_r][lb_c], B + (size_t)lb_r * ldb + col0 + lb_c);
    }
    CP_COMMIT();

    for (int ct = 0; ct < ntiles; ct++) {
        if (ct + 1 < ntiles) {
            int k0 = (ct + 1) << 4;
            int st = (ct + 1) & 1;
            const float* ap = Xb + (size_t)(k0 + la_k) * NT + n0 + la_n;
            cp16(&As2[st][la_k][la_n], ap);
            cp16(&As2[st][la_k][la_n + 4], ap + 4);
            cp16(&Bs[st][lb_r][lb_c], B + (size_t)(k0 + lb_r) * ldb + col0 + lb_c);
        }
        CP_COMMIT();
        CP_WAIT1();
        __syncthreads();
        const int st = ct & 1;
        #pragma unroll
        for (int ks = 0; ks < 2; ks++) {
            const int k8 = ks * 8;
            uint32_t a[2][4], bf[4][2];
            #pragma unroll
            for (int mi = 0; mi < 2; mi++) {
                int r = warp_m * 32 + mi * 16 + g;
                a[mi][0] = f2tf(As2[st][k8 + tg][r]);
                a[mi][1] = f2tf(As2[st][k8 + tg][r + 8]);
                a[mi][2] = f2tf(As2[st][k8 + tg + 4][r]);
                a[mi][3] = f2tf(As2[st][k8 + tg + 4][r + 8]);
            }
            #pragma unroll
            for (int ni = 0; ni < 4; ni++) {
                int c = warp_n * 32 + ni * 8 + g;
                bf[ni][0] = f2tf(Bs[st][k8 + tg][c]);
                bf[ni][1] = f2tf(Bs[st][k8 + tg + 4][c]);
            }
            #pragma unroll
            for (int mi = 0; mi < 2; mi++)
                #pragma unroll
                for (int ni = 0; ni < 4; ni++)
                    mma_tf32(acc[mi][ni], a[mi], bf[ni]);
        }
        __syncthreads();
    }

    #pragma unroll
    for (int mi = 0; mi < 2; mi++)
        #pragma unroll
        for (int ni = 0; ni < 4; ni++) {
            int r = row0 + warp_m * 32 + mi * 16 + g;
            int c = col0 + warp_n * 32 + ni * 8 + 2 * tg;
            float b0 = bias ? bias[c] : 0.f;
            float b1 = bias ? bias[c + 1] : 0.f;
            C[(size_t)r * ldc + c] = acc[mi][ni][0] + b0;
            C[(size_t)r * ldc + c + 1] = acc[mi][ni][1] + b1;
            C[(size_t)(r + 8) * ldc + c] = acc[mi][ni][2] + b0;
            C[(size_t)(r + 8) * ldc + c + 1] = acc[mi][ni][3] + b1;
        }
}

// ---------------- tf32 GEMM row-major A --------------------------------
// kvmode: 0 plain fp32; 1 K^T bf16 scatter [b][h][d][n]; 2 V bf16 scatter
__global__ void gemm_tf32(const float* __restrict__ A, int lda,
                          const float* __restrict__ B, int ldb,
                          const float* __restrict__ bias,
                          float* __restrict__ C, bf16* __restrict__ Ch,
                          int ldc, int K, int kvmode) {
    __shared__ float As[2][128][20];
    __shared__ float Bs[2][16][68];
    const int tid = threadIdx.x;
    const int wid = tid >> 5, lane = tid & 31;
    const int g = lane >> 2, tg = lane & 3;
    const int warp_m = wid >> 1, warp_n = wid & 1;
    const int row0 = blockIdx.y * 128;
    const int col0 = blockIdx.x * 64;

    const int la_r = tid >> 1;
    const int la_c = (tid & 1) * 8;
    const int lb_r = tid >> 4;
    const int lb_c = (tid & 15) * 4;

    float acc[2][4][4];
    #pragma unroll
    for (int mi = 0; mi < 2; mi++)
        #pragma unroll
        for (int ni = 0; ni < 4; ni++)
            #pragma unroll
            for (int j = 0; j < 4; j++) acc[mi][ni][j] = 0.f;

    const int ntiles = K >> 4;
    {
        const float* ap = A + (size_t)(row0 + la_r) * lda + la_c;
        cp16(&As[0][la_r][la_c], ap);
        cp16(&As[0][la_r][la_c + 4], ap + 4);
        cp16(&Bs[0][lb_r][lb_c], B + (size_t)lb_r * ldb + col0 + lb_c);
    }
    CP_COMMIT();

    for (int ct = 0; ct < ntiles; ct++) {
        if (ct + 1 < ntiles) {
            int k0 = (ct + 1) << 4;
            int st = (ct + 1) & 1;
            const float* ap = A + (size_t)(row0 + la_r) * lda + k0 + la_c;
            cp16(&As[st][la_r][la_c], ap);
            cp16(&As[st][la_r][la_c + 4], ap + 4);
            cp16(&Bs[st][lb_r][lb_c], B + (size_t)(k0 + lb_r) * ldb + col0 + lb_c);
        }
        CP_COMMIT();
        CP_WAIT1();
        __syncthreads();
        const int st = ct & 1;
        #pragma unroll
        for (int ks = 0; ks < 2; ks++) {
            const int k8 = ks * 8;
            uint32_t a[2][4], bf[4][2];
            #pragma unroll
            for (int mi = 0; mi < 2; mi++) {
                int r = warp_m * 32 + mi * 16 + g;
                a[mi][0] = f2tf(As[st][r][k8 + tg]);
                a[mi][1] = f2tf(As[st][r + 8][k8 + tg]);
                a[mi][2] = f2tf(As[st][r][k8 + tg + 4]);
                a[mi][3] = f2tf(As[st][r + 8][k8 + tg + 4]);
            }
            #pragma unroll
            for (int ni = 0; ni < 4; ni++) {
                int c = warp_n * 32 + ni * 8 + g;
                bf[ni][0] = f2tf(Bs[st][k8 + tg][c]);
                bf[ni][1] = f2tf(Bs[st][k8 + tg + 4][c]);
            }
            #pragma unroll
            for (int mi = 0; mi < 2; mi++)
                #pragma unroll
                for (int ni = 0; ni < 4; ni++)
                    mma_tf32(acc[mi][ni], a[mi], bf[ni]);
        }
        __syncthreads();
    }

    #pragma unroll
    for (int mi = 0; mi < 2; mi++) {
        #pragma unroll
        for (int ni = 0; ni < 4; ni++) {
            int r = row0 + warp_m * 32 + mi * 16 + g;
            int c = col0 + warp_n * 32 + ni * 8 + 2 * tg;
            float b0 = bias ? bias[c] : 0.f;
            float b1 = bias ? bias[c + 1] : 0.f;
            float v00 = acc[mi][ni][0] + b0, v01 = acc[mi][ni][1] + b1;
            float v10 = acc[mi][ni][2] + b0, v11 = acc[mi][ni][3] + b1;
            #pragma unroll
            for (int rr = 0; rr < 2; rr++) {
                int row = r + rr * 8;
                float va = rr ? v10 : v00;
                float vb = rr ? v11 : v01;
                if (kvmode == 0) {
                    C[(size_t)row * ldc + c] = va;
                    C[(size_t)row * ldc + c + 1] = vb;
                } else if (kvmode == 1) {
                    int b = row >> 10, n = row & 1023;
                    int h0 = c >> 6, d0 = c & 63;
                    int h1 = (c + 1) >> 6, d1 = (c + 1) & 63;
                    Ch[(((size_t)(b * NH + h0)) * HD + d0) * NT + n] = __float2bfloat16(va);
                    Ch[(((size_t)(b * NH + h1)) * HD + d1) * NT + n] = __float2bfloat16(vb);
                } else {
                    int b = row >> 10, n = row & 1023;
                    int h0 = c >> 6, d0 = c & 63;
                    int h1 = (c + 1) >> 6, d1 = (c + 1) & 63;
                    Ch[((((size_t)b * NH + h0) << 10) + n) * HD + d0] = __float2bfloat16(va);
                    Ch[((((size_t)b * NH + h1) << 10) + n) * HD + d1] = __float2bfloat16(vb);
                }
            }
        }
    }
}

// ---------------- row LayerNorm ----------------
__global__ void ln_rows(float* __restrict__ X, int L,
                        const float* __restrict__ g, const float* __restrict__ b) {
    int row = blockIdx.x;
    float* xp = X + (size_t)row * L;
    float s = 0.f;
    for (int i = threadIdx.x; i < L; i += blockDim.x) s += xp[i];
    s = blockReduceSum(s);
    float m = s / L;
    float v = 0.f;
    for (int i = threadIdx.x; i < L; i += blockDim.x) { float d = xp[i] - m; v += d * d; }
    v = blockReduceSum(v);
    float inv = rsqrtf(v / L + 1e-5f);
    for (int i = threadIdx.x; i < L; i += blockDim.x)
        xp[i] = (xp[i] - m) * inv * g[i] + b[i];
}

__global__ void make_bqq(const float* __restrict__ b_q, const float* __restrict__ W_in,
                         const float* __restrict__ b_in) {
    int j = blockIdx.x * blockDim.x + threadIdx.x;
    if (j >= NE) return;
    float s = b_in[j];
    for (int k = 0; k < NE; k++) s += b_q[k] * W_in[(size_t)k * (3 * NE) + j];
    buf_bqq[j] = s;
}

__global__ void init_state(const float* __restrict__ start) {
    int i = blockIdx.x * blockDim.x + threadIdx.x;
    if (i < NB * ND) buf_act[i] = start[i & (ND - 1)];
    if (i < NB * NA_) {
        buf_aA[i] = 0.f; buf_bA[i] = 0.f;
        buf_aO[i] = 0.f; buf_bO[i] = 0.f;
    }
}

// -------- one-time: split fp32 W[K][N] into hi/lo bf16 k-pair-packed -----
__global__ void split_w(const float* __restrict__ W, int N,
                        bf162* __restrict__ hi, bf162* __restrict__ lo, int totalPairs) {
    int i = blockIdx.x * 256 + threadIdx.x;
    if (i >= totalPairs) return;
    int kk = i / N, c = i - kk * N;
    float a0 = W[(size_t)(2 * kk) * N + c];
    float a1 = W[(size_t)(2 * kk + 1) * N + c];
    bf16 h0 = __float2bfloat16(a0);
    bf16 h1 = __float2bfloat16(a1);
    bf16 l0 = __float2bfloat16(a0 - __bfloat162float(h0));
    bf16 l1 = __float2bfloat16(a1 - __bfloat162float(h1));
    hi[i] = __halves2bfloat162(h0, h1);
    lo[i] = __halves2bfloat162(l0, l1);
}

// ======================================================================
// bf16x3 emulated-fp32 skinny GEMM on tensor cores.
// ======================================================================
__global__ void skinny_mma(const float* __restrict__ A0, int K0,
                           const float* __restrict__ A1, int K1,
                           const bf162* __restrict__ Bhi, const bf162* __restrict__ Blo,
                           int ldb,
                           float* __restrict__ partout, int Nout) {
    __shared__ bf162 Ah[32][132];
    __shared__ bf162 Al[32][132];
    __shared__ bf162 Bs[3][2][8][68];
    const int tid = threadIdx.x;
    const int wid = tid >> 5, lane = tid & 31;
    const int g = lane >> 2, tg = lane & 3;
    const int col0 = blockIdx.x * 64;
    const int kstart = blockIdx.y * 256;
    const int khalf = kstart >> 1;
    const int ntiles = 16;

    const int bp = tid >> 7;
    const int br = (tid >> 4) & 7;
    const int bc = (tid & 15) * 4;
    const bf162* bsrc = bp ? Blo : Bhi;
    #pragma unroll
    for (int pt = 0; pt < 2; pt++) {
        cp16(&Bs[pt][bp][br][bc], bsrc + (size_t)(khalf + pt * 8 + br) * ldb + col0 + bc);
        CP_COMMIT();
    }

    for (int e = tid; e < 32 * 128; e += 256) {
        int r = e >> 7, kk = e & 127;
        int k = kstart + 2 * kk;
        float a0, a1;
        if (k < K0) {
            a0 = A0[(size_t)r * K0 + k];
            a1 = A0[(size_t)r * K0 + k + 1];
        } else {
            a0 = A1[(size_t)r * K1 + (k - K0)];
            a1 = A1[(size_t)r * K1 + (k - K0) + 1];
        }
        bf16 h0 = __float2bfloat16(a0);
        bf16 h1 = __float2bfloat16(a1);
        bf16 l0 = __float2bfloat16(a0 - __bfloat162float(h0));
        bf16 l1 = __float2bfloat16(a1 - __bfloat162float(h1));
        Ah[r][kk] = __halves2bfloat162(h0, h1);
        Al[r][kk] = __halves2bfloat162(l0, l1);
    }
    __syncthreads();

    float acc[2][4];
    #pragma unroll
    for (int mt = 0; mt < 2; mt++)
        #pragma unroll
        for (int j = 0; j < 4; j++) acc[mt][j] = 0.f;

    const int cw = wid * 8 + g;

    for (int ct = 0; ct < ntiles; ct++) {
        CP_WAIT1();
        __syncthreads();
        const int st = ct % 3;
        const int base = ct * 8;

        uint32_t ah[2][4], al[2][4], bh[2], bl[2];
        #pragma unroll
        for (int mt = 0; mt < 2; mt++) {
            int r = mt * 16 + g;
            ah[mt][0] = *(const uint32_t*)&Ah[r][base + tg];
            ah[mt][1] = *(const uint32_t*)&Ah[r + 8][base + tg];
            ah[mt][2] = *(const uint32_t*)&Ah[r][base + tg + 4];
            ah[mt][3] = *(const uint32_t*)&Ah[r + 8][base + tg + 4];
            al[mt][0] = *(const uint32_t*)&Al[r][base + tg];
            al[mt][1] = *(const uint32_t*)&Al[r + 8][base + tg];
            al[mt][2] = *(const uint32_t*)&Al[r][base + tg + 4];
            al[mt][3] = *(const uint32_t*)&Al[r + 8][base + tg + 4];
        }
        bh[0] = *(const uint32_t*)&Bs[st][0][tg][cw];
        bh[1] = *(const uint32_t*)&Bs[st][0][tg + 4][cw];
        bl[0] = *(const uint32_t*)&Bs[st][1][tg][cw];
        bl[1] = *(const uint32_t*)&Bs[st][1][tg + 4][cw];

        #pragma unroll
        for (int mt = 0; mt < 2; mt++) {
            mma_bf16(acc[mt], ah[mt], bh);
            mma_bf16(acc[mt], ah[mt], bl);
            mma_bf16(acc[mt], al[mt], bh);
        }

        int nt = ct + 2;
        if (nt < ntiles)
            cp16(&Bs[nt % 3][bp][br][bc], bsrc + (size_t)(khalf + nt * 8 + br) * ldb + col0 + bc);
        CP_COMMIT();
    }

    float* po = partout + ((size_t)blockIdx.y * 32) * Nout;
    #pragma unroll
    for (int mt = 0; mt < 2; mt++) {
        int r = mt * 16 + g;
        int c = col0 + wid * 8 + 2 * tg;
        po[(size_t)r * Nout + c]           = acc[mt][0];
        po[(size_t)r * Nout + c + 1]       = acc[mt][1];
        po[(size_t)(r + 8) * Nout + c]     = acc[mt][2];
        po[(size_t)(r + 8) * Nout + c + 1] = acc[mt][3];
    }
}

// ======================================================================
// Fused light skinny GEMM (fp32 B).
// modes: 1 = syncA update; 2 = attention combine; 5 = syncO update
// ======================================================================
#define SKS 4
__global__ void skinny_fused(int mode,
                             const float* __restrict__ A0, int lda,
                             const int* __restrict__ idx, const float* __restrict__ decay,
                             const float* __restrict__ st_a_in, const float* __restrict__ st_b_in,
                             float* __restrict__ st_a_out, float* __restrict__ st_b_out,
                             float* __restrict__ sync_final,
                             const float* __restrict__ B, int ldb,
                             float* __restrict__ partout, int Nout, int Kper) {
    __shared__ float As[32][129];
    __shared__ float Bs[SKS][16][64];
    __shared__ float wno[32][8];
    __shared__ float Tinv[32];
    const int tid = threadIdx.x;
    const int col0 = blockIdx.x * 64;
    const int kstart = blockIdx.y * Kper;
    const int ntiles = Kper >> 4;
    const int kshift = (Kper == 64) ? 6 : 7;

    const int bkk = tid >> 4, bc = (tid & 15) * 4;
    int bcol = col0 + bc;
    if (bcol > Nout - 4) bcol = Nout - 4;
    #pragma unroll
    for (int pt = 0; pt < SKS - 1; pt++) {
        if (pt < ntiles)
            cp16(&Bs[pt][bkk][bc], B + (size_t)(kstart + pt * 16 + bkk) * ldb + bcol);
        CP_COMMIT();
    }

    if (mode == 2) {
        if (tid < 32) {
            int h = kstart >> 6, b = tid;
            float M = -1e30f;
            #pragma unroll
            for (int c = 0; c < 8; c++) M = fmaxf(M, buf_pm[(b * NH + h) * 8 + c]);
            float T = 0.f;
            #pragma unroll
            for (int c = 0; c < 8; c++) {
                float w = expf(buf_pm[(b * NH + h) * 8 + c] - M);
                wno[b][c] = w;
                T += buf_ps[(b * NH + h) * 8 + c] * w;
            }
            Tinv[b] = 1.f / T;
        }
        __syncthreads();
    }

    // ---- A build ----
    for (int e = tid; e < 32 * Kper; e += 256) {
        int r = e >> kshift;
        int j = e & (Kper - 1);
        int k = kstart + j;
        float v;
        if (mode == 2) {
            int h = kstart >> 6;
            const float* pvp = buf_pv + ((size_t)(r * NH + h) * 8) * HD + j;
            float acc = 0.f;
            #pragma unroll
            for (int c = 0; c < 8; c++) acc += pvp[c * HD] * wno[r][c];
            v = acc * Tinv[r];
        } else {
            float rr = expf(-fminf(fmaxf(decay[k], 0.f), 15.f));
            float sel = A0[(size_t)r * lda + idx[k]];
            float a = rr * st_a_in[r * 512 + k] + sel * sel;
            float bb = rr * st_b_in[r * 512 + k] + 1.f;
            st_a_out[r * 512 + k] = a;
            st_b_out[r * 512 + k] = bb;
            v = a * rsqrtf(bb);
            if (sync_final) sync_final[r * 512 + k] = v;
        }
        As[r][j] = v;
    }
    __syncthreads();

    // ---- B streaming + FMA ----
    const int c4 = (tid & 15) * 4;
    const int r0 = (tid >> 4) * 2;
    float acc0[4] = {0.f, 0.f, 0.f, 0.f};
    float acc1[4] = {0.f, 0.f, 0.f, 0.f};

    for (int ct = 0; ct < ntiles; ct++) {
        CP_WAIT2();
        __syncthreads();
        const int st = ct & (SKS - 1);
        const float* a0p = &As[r0][ct * 16];
        const float* a1p = &As[r0 + 1][ct * 16];
        #pragma unroll
        for (int kk = 0; kk < 16; kk++) {
            float4 bv = *(const float4*)&Bs[st][kk][c4];
            float a0 = a0p[kk], a1 = a1p[kk];
            acc0[0] += a0 * bv.x; acc0[1] += a0 * bv.y;
            acc0[2] += a0 * bv.z; acc0[3] += a0 * bv.w;
            acc1[0] += a1 * bv.x; acc1[1] += a1 * bv.y;
            acc1[2] += a1 * bv.z; acc1[3] += a1 * bv.w;
        }
        __syncthreads();
        int nt = ct + SKS - 1;
        if (nt < ntiles)
            cp16(&Bs[nt & (SKS - 1)][bkk][bc], B + (size_t)(kstart + nt * 16 + bkk) * ldb + bcol);
        CP_COMMIT();
    }

    float* po = partout + ((size_t)blockIdx.y * 32 + r0) * Nout;
    #pragma unroll
    for (int j = 0; j < 4; j++) {
        int c = col0 + c4 + j;
        if (c < Nout) {
            po[c] = acc0[j];
            po[Nout + c] = acc1[j];
        }
    }
}

// ---------------- split-K reduce ----------------
__global__ void reduce_rows(const float* __restrict__ part, const float* __restrict__ bias,
                            float* __restrict__ out, int Nout, int nsplit, int relu) {
    int i = blockIdx.x * 256 + threadIdx.x;
    if (i >= 32 * Nout) return;
    int r = i / Nout, c = i - r * Nout;
    float s = bias[c];
    for (int k = 0; k < nsplit; k++) s += part[((size_t)k * 32 + r) * Nout + c];
    out[i] = relu ? fmaxf(s, 0.f) : s;
}

// ---------------- attention partial (vectorized bf162 K and V) ----------
__global__ void attn_partial() {
    const int bh = blockIdx.x >> 3;
    const int chunk = blockIdx.x & 7;
    const int b = bh >> 3, h = bh & 7;
    const int tid = threadIdx.x;
    __shared__ float qs[64];
    __shared__ float sc4[4][128];
    __shared__ float ev[128];
    __shared__ float red[8][64];

    if (tid < 64) {
        float q = buf_bqq[h * HD + tid];
        #pragma unroll
        for (int s = 0; s < 8; s++) q += buf_qpart[((size_t)s * 32 + b) * NE + h * HD + tid];
        qs[tid] = q;
    }
    __syncthreads();

    {
        const int n0 = (tid & 63) * 2;
        const int dh = tid >> 6;
        const bf16* KT = buf_Kh + ((size_t)bh * HD + dh * 16) * NT + (chunk << 7) + n0;
        float px = 0.f, py = 0.f;
        #pragma unroll
        for (int d = 0; d < 16; d++) {
            float2 kf = __bfloat1622float2(*(const bf162*)(KT + (size_t)d * NT));
            float qv = qs[dh * 16 + d];
            px += qv * kf.x;
            py += qv * kf.y;
        }
        sc4[dh][n0] = px;
        sc4[dh][n0 + 1] = py;
    }
    __syncthreads();

    const int n = tid & 127;
    float score = (tid < 128)
        ? (sc4[0][n] + sc4[1][n] + sc4[2][n] + sc4[3][n]) * 0.125f
        : -1e30f;
    float m = blockReduceMax(score);
    float e = (tid < 128) ? expf(score - m) : 0.f;
    float s = blockReduceSum(e);
    if (tid < 128) ev[n] = e;
    __syncthreads();

    {
        const int d0 = (tid & 31) * 2;
        const int grp = tid >> 5;
        const bf16* Vb = buf_Vh + (((size_t)bh << 10) + (chunk << 7) + grp * 16) * HD + d0;
        float ax = 0.f, ay = 0.f;
        #pragma unroll
        for (int nn = 0; nn < 16; nn++) {
            float2 vf = __bfloat1622float2(*(const bf162*)(Vb + (size_t)nn * HD));
            float w = ev[grp * 16 + nn];
            ax += w * vf.x;
            ay += w * vf.y;
        }
        red[grp][d0] = ax;
        red[grp][d0 + 1] = ay;
    }
    __syncthreads();
    if (tid < 64) {
        float v = 0.f;
        #pragma unroll
        for (int g = 0; g < 8; g++) v += red[g][tid];
        buf_pv[(size_t)blockIdx.x * HD + tid] = v;
        if (tid == 0) { buf_pm[blockIdx.x] = m; buf_ps[blockIdx.x] = s; }
    }
}

// ---------------- fused 10-split reduce + GLU + double LN ----------------
__global__ void glu_ln_ln(const float* __restrict__ b_syn,
                          const float* __restrict__ g_syn, const float* __restrict__ be_syn,
                          const float* __restrict__ g_pm, const float* __restrict__ be_pm) {
    int b = blockIdx.x, tid = threadIdx.x;
    float v[8];
    #pragma unroll
    for (int j = 0; j < 8; j++) {
        int d = tid + j * 256;
        float a = b_syn[d], gg = b_syn[ND + d];
        #pragma unroll
        for (int s = 0; s < 10; s++) {
            const float* hp = buf_hpart + ((size_t)s * 32 + b) * (2 * ND);
            a += hp[d];
            gg += hp[ND + d];
        }
        v[j] = a * (1.f / (1.f + expf(-gg)));
    }
    float s = 0.f;
    #pragma unroll
    for (int j = 0; j < 8; j++) s += v[j];
    s = blockReduceSum(s);
    float m = s / ND;
    float var = 0.f;
    #pragma unroll
    for (int j = 0; j < 8; j++) { float d = v[j] - m; var += d * d; }
    var = blockReduceSum(var);
    float inv = rsqrtf(var / ND + 1e-5f);
    #pragma unroll
    for (int j = 0; j < 8; j++) {
        int d = tid + j * 256;
        v[j] = (v[j] - m) * inv * g_syn[d] + be_syn[d];
    }
    s = 0.f;
    #pragma unroll
    for (int j = 0; j < 8; j++) s += v[j];
    s = blockReduceSum(s);
    float m2 = s / ND;
    var = 0.f;
    #pragma unroll
    for (int j = 0; j < 8; j++) { float d = v[j] - m2; var += d * d; }
    var = blockReduceSum(var);
    float inv2 = rsqrtf(var / ND + 1e-5f);
    #pragma unroll
    for (int j = 0; j < 8; j++) {
        int d = tid + j * 256;
        buf_hpm[(size_t)b * ND + d] = (v[j] - m2) * inv2 * g_pm[d] + be_pm[d];
    }
}

// ---------------- pred reduce + entropy + writes ----------------
__global__ void entropy_write(const float* __restrict__ b_out, float* __restrict__ dout, int t) {
    int b = blockIdx.x, tid = threadIdx.x;
    __shared__ float sp[NOUT];
    for (int i = tid; i < NOUT; i += 256) {
        float v = b_out[i];
        #pragma unroll
        for (int s = 0; s < 4; s++) v += buf_predpart[((size_t)s * 32 + b) * NOUT + i];
        sp[i] = v;
    }
    __syncthreads();
    float m = -1e30f;
    for (int i = tid; i < NOUT; i += 256) m = fmaxf(m, sp[i]);
    m = blockReduceMax(m);
    float s = 0.f;
    for (int i = tid; i < NOUT; i += 256) s += expf(sp[i] - m);
    s = blockReduceSum(s);
    float lse = m + logf(s);
    float ent = 0.f;
    for (int i = tid; i < NOUT; i += 256) {
        float pv = sp[i];
        float lp = pv - lse;
        ent += expf(lp) * lp;
        dout[(size_t)b * NOUT * NSTEP + (size_t)i * NSTEP + t] = pv;
    }
    ent = blockReduceSum(ent);
    if (tid == 0) {
        float ne = -ent / logf((float)NOUT);
        dout[CERT_BASE + b * (2 * NSTEP) + t] = ne;
        dout[CERT_BASE + b * (2 * NSTEP) + NSTEP + t] = 1.f - ne;
    }
}

// ---------------- launch ----------------
extern "C" void kernel_launch(void* const* d_in, const int* in_sizes, int n_in,
                              void* d_out, int out_size) {
    const float* x     = (const float*)d_in[0];
    const float* W_kv  = (const float*)d_in[1];
    const float* b_kv  = (const float*)d_in[2];
    const float* g_kv  = (const float*)d_in[3];
    const float* be_kv = (const float*)d_in[4];
    const float* W_q   = (const float*)d_in[5];
    const float* b_q   = (const float*)d_in[6];
    const float* W_in  = (const float*)d_in[7];
    const float* b_in  = (const float*)d_in[8];
    const float* W_ao  = (const float*)d_in[9];
    const float* b_ao  = (const float*)d_in[10];
    const float* W_syn = (const float*)d_in[11];
    const float* b_syn = (const float*)d_in[12];
    const float* g_syn = (const float*)d_in[13];
    const float* be_syn= (const float*)d_in[14];
    const float* g_pm  = (const float*)d_in[15];
    const float* be_pm = (const float*)d_in[16];
    const float* W1    = (const float*)d_in[17];
    const float* b1    = (const float*)d_in[18];
    const float* W2    = (const float*)d_in[19];
    const float* b2    = (const float*)d_in[20];
    const float* start = (const float*)d_in[21];
    const float* dec_a = (const float*)d_in[22];
    const float* dec_o = (const float*)d_in[23];
    const float* W_out = (const float*)d_in[24];
    const float* b_out = (const float*)d_in[25];
    const int*   idx_a = (const int*)d_in[26];
    const int*   idx_o = (const int*)d_in[27];
    float* out = (float*)d_out;

    float *p_kv, *p_Wqq, *p_act, *p_hpm, *p_t1, *p_attno;
    bf16 *p_Kh, *p_Vh;
    bf162 *p_syn_hi, *p_syn_lo, *p_w1_hi, *p_w1_lo, *p_w2_hi, *p_w2_lo;
    float *p_aA, *p_bA, *p_aO, *p_bO;
    float *p_qpart, *p_attnopart, *p_hpart, *p_w1part, *p_w2part, *p_predpart;
    cudaGetSymbolAddress((void**)&p_kv,    buf_kv);
    cudaGetSymbolAddress((void**)&p_Kh,    buf_Kh);
    cudaGetSymbolAddress((void**)&p_Vh,    buf_Vh);
    cudaGetSymbolAddress((void**)&p_Wqq,   buf_Wqq);
    cudaGetSymbolAddress((void**)&p_act,   buf_act);
    cudaGetSymbolAddress((void**)&p_hpm,   buf_hpm);
    cudaGetSymbolAddress((void**)&p_t1,    buf_t1);
    cudaGetSymbolAddress((void**)&p_attno, buf_attno);
    cudaGetSymbolAddress((void**)&p_aA,    buf_aA);
    cudaGetSymbolAddress((void**)&p_bA,    buf_bA);
    cudaGetSymbolAddress((void**)&p_aO,    buf_aO);
    cudaGetSymbolAddress((void**)&p_bO,    buf_bO);
    cudaGetSymbolAddress((void**)&p_syn_hi, w_syn_hi);
    cudaGetSymbolAddress((void**)&p_syn_lo, w_syn_lo);
    cudaGetSymbolAddress((void**)&p_w1_hi,  w_1_hi);
    cudaGetSymbolAddress((void**)&p_w1_lo,  w_1_lo);
    cudaGetSymbolAddress((void**)&p_w2_hi,  w_2_hi);
    cudaGetSymbolAddress((void**)&p_w2_lo,  w_2_lo);
    cudaGetSymbolAddress((void**)&p_qpart,     buf_qpart);
    cudaGetSymbolAddress((void**)&p_attnopart, buf_attnopart);
    cudaGetSymbolAddress((void**)&p_hpart,     buf_hpart);
    cudaGetSymbolAddress((void**)&p_w1part,    buf_w1part);
    cudaGetSymbolAddress((void**)&p_w2part,    buf_w2part);
    cudaGetSymbolAddress((void**)&p_predpart,  buf_predpart);

    // ---- precompute ----
    gemm_at_tf32<<<dim3(NE / 64, (NB * NT) / 128), 256>>>(x, W_kv, NE, b_kv, p_kv, NE, NC);
    ln_rows<<<NB * NT, 256>>>(p_kv, NE, g_kv, be_kv);
    gemm_tf32<<<dim3(NE / 64, (NB * NT) / 128), 256>>>(p_kv, NE, W_in + NE,     3 * NE, b_in + NE,
                                                       (float*)0, p_Kh, NE, NE, 1);
    gemm_tf32<<<dim3(NE / 64, (NB * NT) / 128), 256>>>(p_kv, NE, W_in + 2 * NE, 3 * NE, b_in + 2 * NE,
                                                       (float*)0, p_Vh, NE, NE, 2);
    gemm_tf32<<<dim3(NE / 64, NE / 128), 256>>>(W_q, NE, W_in, 3 * NE, (const float*)0,
                                                p_Wqq, (bf16*)0, NE, NE, 0);
    make_bqq<<<2, 256>>>(b_q, W_in, b_in);
    init_state<<<(NB * ND + 255) / 256, 256>>>(start);
    {
        int n1 = ((NE + ND) / 2) * (2 * ND);
        split_w<<<(n1 + 255) / 256, 256>>>(W_syn, 2 * ND, p_syn_hi, p_syn_lo, n1);
        int n2 = (ND / 2) * ND;
        split_w<<<(n2 + 255) / 256, 256>>>(W1, ND, p_w1_hi, p_w1_lo, n2);
        split_w<<<(n2 + 255) / 256, 256>>>(W2, ND, p_w2_hi, p_w2_lo, n2);
    }

    // ---- recurrent loop: 12 nodes/step, single stream ----
    for (int t = 0; t < NSTEP; t++) {
        const int pi = (t & 1) * NB * 512, po = ((t + 1) & 1) * NB * 512;
        // 1. q partials (fused syncA)
        skinny_fused<<<dim3(8, 8), 256>>>(1, p_act, ND, idx_a, dec_a,
                                          p_aA + pi, p_bA + pi, p_aA + po, p_bA + po,
                                          (float*)0, p_Wqq, NE, p_qpart, NE, 64);
        // 2. attention partials (vectorized bf162)
        attn_partial<<<NB * NH * 8, 256>>>();
        // 3. attno partials (fused combine)
        skinny_fused<<<dim3(8, 8), 256>>>(2, (const float*)0, 0, (const int*)0, (const float*)0,
                                          (const float*)0, (const float*)0, (float*)0, (float*)0,
                                          (float*)0, W_ao, NE, p_attnopart, NE, 64);
        // 4. attno reduce
        reduce_rows<<<(32 * NE + 255) / 256, 256>>>(p_attnopart, b_ao, p_attno, NE, 8, 0);
        // 5. h partials: [attno|act] @ W_syn   (bf16x3 tensor-core, 10 splits)
        skinny_mma<<<dim3((2 * ND) / 64, 10), 256>>>(p_attno, NE, p_act, ND,
                                                     p_syn_hi, p_syn_lo, 2 * ND,
                                                     p_hpart, 2 * ND);
        // 6. GLU + double LN (10-way reduce)
        glu_ln_ln<<<NB, 256>>>(b_syn, g_syn, be_syn, g_pm, be_pm);
        // 7. W1 partials (bf16x3, 8 splits)
        skinny_mma<<<dim3(ND / 64, 8), 256>>>(p_hpm, ND, (const float*)0, 0,
                                              p_w1_hi, p_w1_lo, ND,
                                              p_w1part, ND);
        // 8. W1 reduce + relu
        reduce_rows<<<(32 * ND + 255) / 256, 256>>>(p_w1part, b1, p_t1, ND, 8, 1);
        // 9. W2 partials (bf16x3, 8 splits)
        skinny_mma<<<dim3(ND / 64, 8), 256>>>(p_t1, ND, (const float*)0, 0,
                                              p_w2_hi, p_w2_lo, ND,
                                              p_w2part, ND);
        // 10. W2 reduce + relu -> act
        reduce_rows<<<(32 * ND + 255) / 256, 256>>>(p_w2part, b2, p_act, ND, 8, 1);
        // 11. pred partials (fused syncO)
        skinny_fused<<<dim3(16, 4), 256>>>(5, p_act, ND, idx_o, dec_o,
                                           p_aO + pi, p_bO + pi, p_aO + po, p_bO + po,
                                           (t == NSTEP - 1) ? (out + SYNC_BASE) : (float*)0,
                                           W_out, NOUT, p_predpart, NOUT, 128);
        // 12. entropy + prediction writes
        entropy_write<<<NB, 256>>>(b_out, out, t);
    }
}

// round 15
// speedup vs baseline: 1.3225x; 1.0062x over previous
#include <cuda_runtime.h>
#include <cuda_bf16.h>
#include <math.h>
#include <stdint.h>

// ---------------- problem dims ----------------
#define NB 32
#define NC 512
#define NT 1024
#define NE 512
#define ND 2048
#define NH 8
#define HD 64
#define NSTEP 50
#define NOUT 1000
#define NA_ 512
#define NO_ 512

#define PRED_ELEMS (NB*NOUT*NSTEP)
#define CERT_BASE  PRED_ELEMS
#define SYNC_BASE  (CERT_BASE + NB*2*NSTEP)

typedef __nv_bfloat16 bf16;
typedef __nv_bfloat162 bf162;

// ---------------- device scratch ----------------
__device__ float buf_kv   [NB*NT*NE];
__device__ bf16  buf_Kh   [NB*NT*NE];   // K^T head-major bf16: [b][h][d][n]
__device__ bf16  buf_Vh   [NB*NT*NE];   // V head-major bf16: [b][h][n][d]
__device__ float buf_act  [NB*ND];
__device__ float buf_aA   [2*NB*NA_];
__device__ float buf_bA   [2*NB*NA_];
__device__ float buf_aO   [2*NB*NO_];
__device__ float buf_bO   [2*NB*NO_];
__device__ float buf_attno[NB*NE];
__device__ float buf_hpm  [NB*ND];
__device__ float buf_t1   [NB*ND];
__device__ float buf_Wqq  [NE*NE];
__device__ float buf_bqq  [NE];
// bf16x2 (hi/lo) packed weight planes: [K/2][N] of bf162 (k-pairs packed)
__device__ bf162 w_syn_hi[((NE+ND)/2)*(2*ND)];
__device__ bf162 w_syn_lo[((NE+ND)/2)*(2*ND)];
__device__ bf162 w_1_hi  [(ND/2)*ND];
__device__ bf162 w_1_lo  [(ND/2)*ND];
__device__ bf162 w_2_hi  [(ND/2)*ND];
__device__ bf162 w_2_lo  [(ND/2)*ND];
// split-K partials
__device__ float buf_qpart    [8*32*NE];
__device__ float buf_attnopart[8*32*NE];
__device__ float buf_hpart    [10*32*2*ND];
__device__ float buf_w1part   [8*32*ND];
__device__ float buf_w2part   [8*32*ND];
__device__ float buf_predpart [4*32*NOUT];
// attention partials
__device__ float buf_pv[NB*NH*8*HD];
__device__ float buf_pm[NB*NH*8];
__device__ float buf_ps[NB*NH*8];

// ---------------- cp.async helpers ----------------
__device__ __forceinline__ void cp16(void* smem, const void* gmem) {
    uint32_t s = (uint32_t)__cvta_generic_to_shared(smem);
    asm volatile("cp.async.cg.shared.global [%0], [%1], 16;\n" :: "r"(s), "l"(gmem));
}
#define CP_COMMIT() asm volatile("cp.async.commit_group;\n" ::: "memory")
#define CP_WAIT2()  asm volatile("cp.async.wait_group 2;\n" ::: "memory")
#define CP_WAIT1()  asm volatile("cp.async.wait_group 1;\n" ::: "memory")

// ---------------- mma helpers ----------------
// tf32 mma ignores the low 13 mantissa bits: pass raw fp32 bits (RZ rounding).
__device__ __forceinline__ uint32_t f2tf(float x) {
    return __float_as_uint(x);
}
__device__ __forceinline__ void mma_tf32(float* c, const uint32_t* a, const uint32_t* b) {
    asm volatile(
        "mma.sync.aligned.m16n8k8.row.col.f32.tf32.tf32.f32 "
        "{%0,%1,%2,%3},{%4,%5,%6,%7},{%8,%9},{%0,%1,%2,%3};"
        : "+f"(c[0]), "+f"(c[1]), "+f"(c[2]), "+f"(c[3])
        : "r"(a[0]), "r"(a[1]), "r"(a[2]), "r"(a[3]), "r"(b[0]), "r"(b[1]));
}
__device__ __forceinline__ void mma_bf16(float* c, const uint32_t* a, const uint32_t* b) {
    asm volatile(
        "mma.sync.aligned.m16n8k16.row.col.f32.bf16.bf16.f32 "
        "{%0,%1,%2,%3},{%4,%5,%6,%7},{%8,%9},{%0,%1,%2,%3};"
        : "+f"(c[0]), "+f"(c[1]), "+f"(c[2]), "+f"(c[3])
        : "r"(a[0]), "r"(a[1]), "r"(a[2]), "r"(a[3]), "r"(b[0]), "r"(b[1]));
}

// ---------------- block reductions ----------------
__device__ __forceinline__ float blockReduceSum(float v) {
    __shared__ float shs[32];
    int lane = threadIdx.x & 31, w = threadIdx.x >> 5;
    #pragma unroll
    for (int o = 16; o; o >>= 1) v += __shfl_xor_sync(0xffffffffu, v, o);
    if (lane == 0) shs[w] = v;
    __syncthreads();
    float r = 0.f;
    int nw = (blockDim.x + 31) >> 5;
    if (threadIdx.x < nw) r = shs[threadIdx.x];
    if (w == 0) {
        #pragma unroll
        for (int o = 16; o; o >>= 1) r += __shfl_xor_sync(0xffffffffu, r, o);
        if (lane == 0) shs[0] = r;
    }
    __syncthreads();
    float out = shs[0];
    __syncthreads();
    return out;
}
__device__ __forceinline__ float blockReduceMax(float v) {
    __shared__ float shm[32];
    int lane = threadIdx.x & 31, w = threadIdx.x >> 5;
    #pragma unroll
    for (int o = 16; o; o >>= 1) v = fmaxf(v, __shfl_xor_sync(0xffffffffu, v, o));
    if (lane == 0) shm[w] = v;
    __syncthreads();
    float r = -1e30f;
    int nw = (blockDim.x + 31) >> 5;
    if (threadIdx.x < nw) r = shm[threadIdx.x];
    if (w == 0) {
        #pragma unroll
        for (int o = 16; o; o >>= 1) r = fmaxf(r, __shfl_xor_sync(0xffffffffu, r, o));
        if (lane == 0) shm[0] = r;
    }
    __syncthreads();
    float out = shm[0];
    __syncthreads();
    return out;
}

// ======================================================================
// tf32 GEMM, A transposed in gmem (fuses (B,C,N)->(B,N,C) transpose).
// 3-stage cp.async pipeline, ONE __syncthreads per k-tile.
// ======================================================================
__global__ void gemm_at_tf32(const float* __restrict__ X,
                             const float* __restrict__ B, int ldb,
                             const float* __restrict__ bias,
                             float* __restrict__ C, int ldc, int K) {
    __shared__ float As2[3][16][136];
    __shared__ float Bs[3][16][68];
    const int tid = threadIdx.x;
    const int wid = tid >> 5, lane = tid & 31;
    const int g = lane >> 2, tg = lane & 3;
    const int warp_m = wid >> 1, warp_n = wid & 1;
    const int row0 = blockIdx.y * 128;
    const int col0 = blockIdx.x * 64;
    const int bb_ = row0 >> 10, n0 = row0 & 1023;
    const float* Xb = X + (size_t)bb_ * NC * NT;

    const int la_k = tid >> 4;
    const int la_n = (tid & 15) * 8;
    const int lb_r = tid >> 4;
    const int lb_c = (tid & 15) * 4;

    float acc[2][4][4];
    #pragma unroll
    for (int mi = 0; mi < 2; mi++)
        #pragma unroll
        for (int ni = 0; ni < 4; ni++)
            #pragma unroll
            for (int j = 0; j < 4; j++) acc[mi][ni][j] = 0.f;

    const int ntiles = K >> 4;
    // prologue: tiles 0,1
    #pragma unroll
    for (int pt = 0; pt < 2; pt++) {
        if (pt < ntiles) {
            int k0 = pt << 4;
            const float* ap = Xb + (size_t)(k0 + la_k) * NT + n0 + la_n;
            cp16(&As2[pt][la_k][la_n], ap);
            cp16(&As2[pt][la_k][la_n + 4], ap + 4);
            cp16(&Bs[pt][lb_r][lb_c], B + (size_t)(k0 + lb_r) * ldb + col0 + lb_c);
        }
        CP_COMMIT();
    }

    for (int ct = 0; ct < ntiles; ct++) {
        CP_WAIT1();
        __syncthreads();
        const int st = ct % 3;
        #pragma unroll
        for (int ks = 0; ks < 2; ks++) {
            const int k8 = ks * 8;
            uint32_t a[2][4], bf[4][2];
            #pragma unroll
            for (int mi = 0; mi < 2; mi++) {
                int r = warp_m * 32 + mi * 16 + g;
                a[mi][0] = f2tf(As2[st][k8 + tg][r]);
                a[mi][1] = f2tf(As2[st][k8 + tg][r + 8]);
                a[mi][2] = f2tf(As2[st][k8 + tg + 4][r]);
                a[mi][3] = f2tf(As2[st][k8 + tg + 4][r + 8]);
            }
            #pragma unroll
            for (int ni = 0; ni < 4; ni++) {
                int c = warp_n * 32 + ni * 8 + g;
                bf[ni][0] = f2tf(Bs[st][k8 + tg][c]);
                bf[ni][1] = f2tf(Bs[st][k8 + tg + 4][c]);
            }
            #pragma unroll
            for (int mi = 0; mi < 2; mi++)
                #pragma unroll
                for (int ni = 0; ni < 4; ni++)
                    mma_tf32(acc[mi][ni], a[mi], bf[ni]);
        }
        int nt = ct + 2;
        if (nt < ntiles) {
            int k0 = nt << 4;
            int st2 = nt % 3;
            const float* ap = Xb + (size_t)(k0 + la_k) * NT + n0 + la_n;
            cp16(&As2[st2][la_k][la_n], ap);
            cp16(&As2[st2][la_k][la_n + 4], ap + 4);
            cp16(&Bs[st2][lb_r][lb_c], B + (size_t)(k0 + lb_r) * ldb + col0 + lb_c);
        }
        CP_COMMIT();
    }

    #pragma unroll
    for (int mi = 0; mi < 2; mi++)
        #pragma unroll
        for (int ni = 0; ni < 4; ni++) {
            int r = row0 + warp_m * 32 + mi * 16 + g;
            int c = col0 + warp_n * 32 + ni * 8 + 2 * tg;
            float b0 = bias ? bias[c] : 0.f;
            float b1 = bias ? bias[c + 1] : 0.f;
            C[(size_t)r * ldc + c] = acc[mi][ni][0] + b0;
            C[(size_t)r * ldc + c + 1] = acc[mi][ni][1] + b1;
            C[(size_t)(r + 8) * ldc + c] = acc[mi][ni][2] + b0;
            C[(size_t)(r + 8) * ldc + c + 1] = acc[mi][ni][3] + b1;
        }
}

// ---------------- tf32 GEMM row-major A (3-stage, single sync) ----------
// kvmode: 0 plain fp32; 1 K^T bf16 scatter [b][h][d][n]; 2 V bf16 scatter
__global__ void gemm_tf32(const float* __restrict__ A, int lda,
                          const float* __restrict__ B, int ldb,
                          const float* __restrict__ bias,
                          float* __restrict__ C, bf16* __restrict__ Ch,
                          int ldc, int K, int kvmode) {
    __shared__ float As[3][128][20];
    __shared__ float Bs[3][16][68];
    const int tid = threadIdx.x;
    const int wid = tid >> 5, lane = tid & 31;
    const int g = lane >> 2, tg = lane & 3;
    const int warp_m = wid >> 1, warp_n = wid & 1;
    const int row0 = blockIdx.y * 128;
    const int col0 = blockIdx.x * 64;

    const int la_r = tid >> 1;
    const int la_c = (tid & 1) * 8;
    const int lb_r = tid >> 4;
    const int lb_c = (tid & 15) * 4;

    float acc[2][4][4];
    #pragma unroll
    for (int mi = 0; mi < 2; mi++)
        #pragma unroll
        for (int ni = 0; ni < 4; ni++)
            #pragma unroll
            for (int j = 0; j < 4; j++) acc[mi][ni][j] = 0.f;

    const int ntiles = K >> 4;
    #pragma unroll
    for (int pt = 0; pt < 2; pt++) {
        if (pt < ntiles) {
            int k0 = pt << 4;
            const float* ap = A + (size_t)(row0 + la_r) * lda + k0 + la_c;
            cp16(&As[pt][la_r][la_c], ap);
            cp16(&As[pt][la_r][la_c + 4], ap + 4);
            cp16(&Bs[pt][lb_r][lb_c], B + (size_t)(k0 + lb_r) * ldb + col0 + lb_c);
        }
        CP_COMMIT();
    }

    for (int ct = 0; ct < ntiles; ct++) {
        CP_WAIT1();
        __syncthreads();
        const int st = ct % 3;
        #pragma unroll
        for (int ks = 0; ks < 2; ks++) {
            const int k8 = ks * 8;
            uint32_t a[2][4], bf[4][2];
            #pragma unroll
            for (int mi = 0; mi < 2; mi++) {
                int r = warp_m * 32 + mi * 16 + g;
                a[mi][0] = f2tf(As[st][r][k8 + tg]);
                a[mi][1] = f2tf(As[st][r + 8][k8 + tg]);
                a[mi][2] = f2tf(As[st][r][k8 + tg + 4]);
                a[mi][3] = f2tf(As[st][r + 8][k8 + tg + 4]);
            }
            #pragma unroll
            for (int ni = 0; ni < 4; ni++) {
                int c = warp_n * 32 + ni * 8 + g;
                bf[ni][0] = f2tf(Bs[st][k8 + tg][c]);
                bf[ni][1] = f2tf(Bs[st][k8 + tg + 4][c]);
            }
            #pragma unroll
            for (int mi = 0; mi < 2; mi++)
                #pragma unroll
                for (int ni = 0; ni < 4; ni++)
                    mma_tf32(acc[mi][ni], a[mi], bf[ni]);
        }
        int nt = ct + 2;
        if (nt < ntiles) {
            int k0 = nt << 4;
            int st2 = nt % 3;
            const float* ap = A + (size_t)(row0 + la_r) * lda + k0 + la_c;
            cp16(&As[st2][la_r][la_c], ap);
            cp16(&As[st2][la_r][la_c + 4], ap + 4);
            cp16(&Bs[st2][lb_r][lb_c], B + (size_t)(k0 + lb_r) * ldb + col0 + lb_c);
        }
        CP_COMMIT();
    }

    #pragma unroll
    for (int mi = 0; mi < 2; mi++) {
        #pragma unroll
        for (int ni = 0; ni < 4; ni++) {
            int r = row0 + warp_m * 32 + mi * 16 + g;
            int c = col0 + warp_n * 32 + ni * 8 + 2 * tg;
            float b0 = bias ? bias[c] : 0.f;
            float b1 = bias ? bias[c + 1] : 0.f;
            float v00 = acc[mi][ni][0] + b0, v01 = acc[mi][ni][1] + b1;
            float v10 = acc[mi][ni][2] + b0, v11 = acc[mi][ni][3] + b1;
            #pragma unroll
            for (int rr = 0; rr < 2; rr++) {
                int row = r + rr * 8;
                float va = rr ? v10 : v00;
                float vb = rr ? v11 : v01;
                if (kvmode == 0) {
                    C[(size_t)row * ldc + c] = va;
                    C[(size_t)row * ldc + c + 1] = vb;
                } else if (kvmode == 1) {
                    int b = row >> 10, n = row & 1023;
                    int h0 = c >> 6, d0 = c & 63;
                    int h1 = (c + 1) >> 6, d1 = (c + 1) & 63;
                    Ch[(((size_t)(b * NH + h0)) * HD + d0) * NT + n] = __float2bfloat16(va);
                    Ch[(((size_t)(b * NH + h1)) * HD + d1) * NT + n] = __float2bfloat16(vb);
                } else {
                    int b = row >> 10, n = row & 1023;
                    int h0 = c >> 6, d0 = c & 63;
                    int h1 = (c + 1) >> 6, d1 = (c + 1) & 63;
                    Ch[((((size_t)b * NH + h0) << 10) + n) * HD + d0] = __float2bfloat16(va);
                    Ch[((((size_t)b * NH + h1) << 10) + n) * HD + d1] = __float2bfloat16(vb);
                }
            }
        }
    }
}

// ---------------- row LayerNorm ----------------
__global__ void ln_rows(float* __restrict__ X, int L,
                        const float* __restrict__ g, const float* __restrict__ b) {
    int row = blockIdx.x;
    float* xp = X + (size_t)row * L;
    float s = 0.f;
    for (int i = threadIdx.x; i < L; i += blockDim.x) s += xp[i];
    s = blockReduceSum(s);
    float m = s / L;
    float v = 0.f;
    for (int i = threadIdx.x; i < L; i += blockDim.x) { float d = xp[i] - m; v += d * d; }
    v = blockReduceSum(v);
    float inv = rsqrtf(v / L + 1e-5f);
    for (int i = threadIdx.x; i < L; i += blockDim.x)
        xp[i] = (xp[i] - m) * inv * g[i] + b[i];
}

__global__ void make_bqq(const float* __restrict__ b_q, const float* __restrict__ W_in,
                         const float* __restrict__ b_in) {
    int j = blockIdx.x * blockDim.x + threadIdx.x;
    if (j >= NE) return;
    float s = b_in[j];
    for (int k = 0; k < NE; k++) s += b_q[k] * W_in[(size_t)k * (3 * NE) + j];
    buf_bqq[j] = s;
}

__global__ void init_state(const float* __restrict__ start) {
    int i = blockIdx.x * blockDim.x + threadIdx.x;
    if (i < NB * ND) buf_act[i] = start[i & (ND - 1)];
    if (i < NB * NA_) {
        buf_aA[i] = 0.f; buf_bA[i] = 0.f;
        buf_aO[i] = 0.f; buf_bO[i] = 0.f;
    }
}

// -------- one-time: split fp32 W[K][N] into hi/lo bf16 k-pair-packed -----
__global__ void split_w(const float* __restrict__ W, int N,
                        bf162* __restrict__ hi, bf162* __restrict__ lo, int totalPairs) {
    int i = blockIdx.x * 256 + threadIdx.x;
    if (i >= totalPairs) return;
    int kk = i / N, c = i - kk * N;
    float a0 = W[(size_t)(2 * kk) * N + c];
    float a1 = W[(size_t)(2 * kk + 1) * N + c];
    bf16 h0 = __float2bfloat16(a0);
    bf16 h1 = __float2bfloat16(a1);
    bf16 l0 = __float2bfloat16(a0 - __bfloat162float(h0));
    bf16 l1 = __float2bfloat16(a1 - __bfloat162float(h1));
    hi[i] = __halves2bfloat162(h0, h1);
    lo[i] = __halves2bfloat162(l0, l1);
}

// ======================================================================
// bf16x3 emulated-fp32 skinny GEMM on tensor cores (single sync per tile).
// ======================================================================
__global__ void skinny_mma(const float* __restrict__ A0, int K0,
                           const float* __restrict__ A1, int K1,
                           const bf162* __restrict__ Bhi, const bf162* __restrict__ Blo,
                           int ldb,
                           float* __restrict__ partout, int Nout) {
    __shared__ bf162 Ah[32][132];
    __shared__ bf162 Al[32][132];
    __shared__ bf162 Bs[3][2][8][68];
    const int tid = threadIdx.x;
    const int wid = tid >> 5, lane = tid & 31;
    const int g = lane >> 2, tg = lane & 3;
    const int col0 = blockIdx.x * 64;
    const int kstart = blockIdx.y * 256;
    const int khalf = kstart >> 1;
    const int ntiles = 16;

    const int bp = tid >> 7;
    const int br = (tid >> 4) & 7;
    const int bc = (tid & 15) * 4;
    const bf162* bsrc = bp ? Blo : Bhi;
    #pragma unroll
    for (int pt = 0; pt < 2; pt++) {
        cp16(&Bs[pt][bp][br][bc], bsrc + (size_t)(khalf + pt * 8 + br) * ldb + col0 + bc);
        CP_COMMIT();
    }

    for (int e = tid; e < 32 * 128; e += 256) {
        int r = e >> 7, kk = e & 127;
        int k = kstart + 2 * kk;
        float a0, a1;
        if (k < K0) {
            a0 = A0[(size_t)r * K0 + k];
            a1 = A0[(size_t)r * K0 + k + 1];
        } else {
            a0 = A1[(size_t)r * K1 + (k - K0)];
            a1 = A1[(size_t)r * K1 + (k - K0) + 1];
        }
        bf16 h0 = __float2bfloat16(a0);
        bf16 h1 = __float2bfloat16(a1);
        bf16 l0 = __float2bfloat16(a0 - __bfloat162float(h0));
        bf16 l1 = __float2bfloat16(a1 - __bfloat162float(h1));
        Ah[r][kk] = __halves2bfloat162(h0, h1);
        Al[r][kk] = __halves2bfloat162(l0, l1);
    }
    __syncthreads();

    float acc[2][4];
    #pragma unroll
    for (int mt = 0; mt < 2; mt++)
        #pragma unroll
        for (int j = 0; j < 4; j++) acc[mt][j] = 0.f;

    const int cw = wid * 8 + g;

    for (int ct = 0; ct < ntiles; ct++) {
        CP_WAIT1();
        __syncthreads();
        const int st = ct % 3;
        const int base = ct * 8;

        uint32_t ah[2][4], al[2][4], bh[2], bl[2];
        #pragma unroll
        for (int mt = 0; mt < 2; mt++) {
            int r = mt * 16 + g;
            ah[mt][0] = *(const uint32_t*)&Ah[r][base + tg];
            ah[mt][1] = *(const uint32_t*)&Ah[r + 8][base + tg];
            ah[mt][2] = *(const uint32_t*)&Ah[r][base + tg + 4];
            ah[mt][3] = *(const uint32_t*)&Ah[r + 8][base + tg + 4];
            al[mt][0] = *(const uint32_t*)&Al[r][base + tg];
            al[mt][1] = *(const uint32_t*)&Al[r + 8][base + tg];
            al[mt][2] = *(const uint32_t*)&Al[r][base + tg + 4];
            al[mt][3] = *(const uint32_t*)&Al[r + 8][base + tg + 4];
        }
        bh[0] = *(const uint32_t*)&Bs[st][0][tg][cw];
        bh[1] = *(const uint32_t*)&Bs[st][0][tg + 4][cw];
        bl[0] = *(const uint32_t*)&Bs[st][1][tg][cw];
        bl[1] = *(const uint32_t*)&Bs[st][1][tg + 4][cw];

        #pragma unroll
        for (int mt = 0; mt < 2; mt++) {
            mma_bf16(acc[mt], ah[mt], bh);
            mma_bf16(acc[mt], ah[mt], bl);
            mma_bf16(acc[mt], al[mt], bh);
        }

        int nt = ct + 2;
        if (nt < ntiles)
            cp16(&Bs[nt % 3][bp][br][bc], bsrc + (size_t)(khalf + nt * 8 + br) * ldb + col0 + bc);
        CP_COMMIT();
    }

    float* po = partout + ((size_t)blockIdx.y * 32) * Nout;
    #pragma unroll
    for (int mt = 0; mt < 2; mt++) {
        int r = mt * 16 + g;
        int c = col0 + wid * 8 + 2 * tg;
        po[(size_t)r * Nout + c]           = acc[mt][0];
        po[(size_t)r * Nout + c + 1]       = acc[mt][1];
        po[(size_t)(r + 8) * Nout + c]     = acc[mt][2];
        po[(size_t)(r + 8) * Nout + c + 1] = acc[mt][3];
    }
}

// ======================================================================
// Fused light skinny GEMM (fp32 B), 4-stage, single sync per tile.
// modes: 1 = syncA update; 2 = attention combine; 5 = syncO update
// ======================================================================
#define SKS 4
__global__ void skinny_fused(int mode,
                             const float* __restrict__ A0, int lda,
                             const int* __restrict__ idx, const float* __restrict__ decay,
                             const float* __restrict__ st_a_in, const float* __restrict__ st_b_in,
                             float* __restrict__ st_a_out, float* __restrict__ st_b_out,
                             float* __restrict__ sync_final,
                             const float* __restrict__ B, int ldb,
                             float* __restrict__ partout, int Nout, int Kper) {
    __shared__ float As[32][129];
    __shared__ float Bs[SKS][16][64];
    __shared__ float wno[32][8];
    __shared__ float Tinv[32];
    const int tid = threadIdx.x;
    const int col0 = blockIdx.x * 64;
    const int kstart = blockIdx.y * Kper;
    const int ntiles = Kper >> 4;
    const int kshift = (Kper == 64) ? 6 : 7;

    const int bkk = tid >> 4, bc = (tid & 15) * 4;
    int bcol = col0 + bc;
    if (bcol > Nout - 4) bcol = Nout - 4;
    #pragma unroll
    for (int pt = 0; pt < SKS - 1; pt++) {
        if (pt < ntiles)
            cp16(&Bs[pt][bkk][bc], B + (size_t)(kstart + pt * 16 + bkk) * ldb + bcol);
        CP_COMMIT();
    }

    if (mode == 2) {
        if (tid < 32) {
            int h = kstart >> 6, b = tid;
            float M = -1e30f;
            #pragma unroll
            for (int c = 0; c < 8; c++) M = fmaxf(M, buf_pm[(b * NH + h) * 8 + c]);
            float T = 0.f;
            #pragma unroll
            for (int c = 0; c < 8; c++) {
                float w = expf(buf_pm[(b * NH + h) * 8 + c] - M);
                wno[b][c] = w;
                T += buf_ps[(b * NH + h) * 8 + c] * w;
            }
            Tinv[b] = 1.f / T;
        }
        __syncthreads();
    }

    // ---- A build ----
    for (int e = tid; e < 32 * Kper; e += 256) {
        int r = e >> kshift;
        int j = e & (Kper - 1);
        int k = kstart + j;
        float v;
        if (mode == 2) {
            int h = kstart >> 6;
            const float* pvp = buf_pv + ((size_t)(r * NH + h) * 8) * HD + j;
            float acc = 0.f;
            #pragma unroll
            for (int c = 0; c < 8; c++) acc += pvp[c * HD] * wno[r][c];
            v = acc * Tinv[r];
        } else {
            float rr = expf(-fminf(fmaxf(decay[k], 0.f), 15.f));
            float sel = A0[(size_t)r * lda + idx[k]];
            float a = rr * st_a_in[r * 512 + k] + sel * sel;
            float bb = rr * st_b_in[r * 512 + k] + 1.f;
            st_a_out[r * 512 + k] = a;
            st_b_out[r * 512 + k] = bb;
            v = a * rsqrtf(bb);
            if (sync_final) sync_final[r * 512 + k] = v;
        }
        As[r][j] = v;
    }
    __syncthreads();

    // ---- B streaming + FMA (single sync per tile) ----
    const int c4 = (tid & 15) * 4;
    const int r0 = (tid >> 4) * 2;
    float acc0[4] = {0.f, 0.f, 0.f, 0.f};
    float acc1[4] = {0.f, 0.f, 0.f, 0.f};

    for (int ct = 0; ct < ntiles; ct++) {
        CP_WAIT2();
        __syncthreads();
        const int st = ct & (SKS - 1);
        const float* a0p = &As[r0][ct * 16];
        const float* a1p = &As[r0 + 1][ct * 16];
        #pragma unroll
        for (int kk = 0; kk < 16; kk++) {
            float4 bv = *(const float4*)&Bs[st][kk][c4];
            float a0 = a0p[kk], a1 = a1p[kk];
            acc0[0] += a0 * bv.x; acc0[1] += a0 * bv.y;
            acc0[2] += a0 * bv.z; acc0[3] += a0 * bv.w;
            acc1[0] += a1 * bv.x; acc1[1] += a1 * bv.y;
            acc1[2] += a1 * bv.z; acc1[3] += a1 * bv.w;
        }
        int nt = ct + SKS - 1;
        if (nt < ntiles)
            cp16(&Bs[nt & (SKS - 1)][bkk][bc], B + (size_t)(kstart + nt * 16 + bkk) * ldb + bcol);
        CP_COMMIT();
    }

    float* po = partout + ((size_t)blockIdx.y * 32 + r0) * Nout;
    #pragma unroll
    for (int j = 0; j < 4; j++) {
        int c = col0 + c4 + j;
        if (c < Nout) {
            po[c] = acc0[j];
            po[Nout + c] = acc1[j];
        }
    }
}

// ---------------- split-K reduce ----------------
__global__ void reduce_rows(const float* __restrict__ part, const float* __restrict__ bias,
                            float* __restrict__ out, int Nout, int nsplit, int relu) {
    int i = blockIdx.x * 256 + threadIdx.x;
    if (i >= 32 * Nout) return;
    int r = i / Nout, c = i - r * Nout;
    float s = bias[c];
    for (int k = 0; k < nsplit; k++) s += part[((size_t)k * 32 + r) * Nout + c];
    out[i] = relu ? fmaxf(s, 0.f) : s;
}

// ---------------- attention partial (vectorized bf162 K and V) ----------
__global__ void attn_partial() {
    const int bh = blockIdx.x >> 3;
    const int chunk = blockIdx.x & 7;
    const int b = bh >> 3, h = bh & 7;
    const int tid = threadIdx.x;
    __shared__ float qs[64];
    __shared__ float sc4[4][128];
    __shared__ float ev[128];
    __shared__ float red[8][64];

    if (tid < 64) {
        float q = buf_bqq[h * HD + tid];
        #pragma unroll
        for (int s = 0; s < 8; s++) q += buf_qpart[((size_t)s * 32 + b) * NE + h * HD + tid];
        qs[tid] = q;
    }
    __syncthreads();

    {
        const int n0 = (tid & 63) * 2;
        const int dh = tid >> 6;
        const bf16* KT = buf_Kh + ((size_t)bh * HD + dh * 16) * NT + (chunk << 7) + n0;
        float px = 0.f, py = 0.f;
        #pragma unroll
        for (int d = 0; d < 16; d++) {
            float2 kf = __bfloat1622float2(*(const bf162*)(KT + (size_t)d * NT));
            float qv = qs[dh * 16 + d];
            px += qv * kf.x;
            py += qv * kf.y;
        }
        sc4[dh][n0] = px;
        sc4[dh][n0 + 1] = py;
    }
    __syncthreads();

    const int n = tid & 127;
    float score = (tid < 128)
        ? (sc4[0][n] + sc4[1][n] + sc4[2][n] + sc4[3][n]) * 0.125f
        : -1e30f;
    float m = blockReduceMax(score);
    float e = (tid < 128) ? expf(score - m) : 0.f;
    float s = blockReduceSum(e);
    if (tid < 128) ev[n] = e;
    __syncthreads();

    {
        const int d0 = (tid & 31) * 2;
        const int grp = tid >> 5;
        const bf16* Vb = buf_Vh + (((size_t)bh << 10) + (chunk << 7) + grp * 16) * HD + d0;
        float ax = 0.f, ay = 0.f;
        #pragma unroll
        for (int nn = 0; nn < 16; nn++) {
            float2 vf = __bfloat1622float2(*(const bf162*)(Vb + (size_t)nn * HD));
            float w = ev[grp * 16 + nn];
            ax += w * vf.x;
            ay += w * vf.y;
        }
        red[grp][d0] = ax;
        red[grp][d0 + 1] = ay;
    }
    __syncthreads();
    if (tid < 64) {
        float v = 0.f;
        #pragma unroll
        for (int g = 0; g < 8; g++) v += red[g][tid];
        buf_pv[(size_t)blockIdx.x * HD + tid] = v;
        if (tid == 0) { buf_pm[blockIdx.x] = m; buf_ps[blockIdx.x] = s; }
    }
}

// ---------------- fused 10-split reduce + GLU + double LN ----------------
__global__ void glu_ln_ln(const float* __restrict__ b_syn,
                          const float* __restrict__ g_syn, const float* __restrict__ be_syn,
                          const float* __restrict__ g_pm, const float* __restrict__ be_pm) {
    int b = blockIdx.x, tid = threadIdx.x;
    float v[8];
    #pragma unroll
    for (int j = 0; j < 8; j++) {
        int d = tid + j * 256;
        float a = b_syn[d], gg = b_syn[ND + d];
        #pragma unroll
        for (int s = 0; s < 10; s++) {
            const float* hp = buf_hpart + ((size_t)s * 32 + b) * (2 * ND);
            a += hp[d];
            gg += hp[ND + d];
        }
        v[j] = a * (1.f / (1.f + expf(-gg)));
    }
    float s = 0.f;
    #pragma unroll
    for (int j = 0; j < 8; j++) s += v[j];
    s = blockReduceSum(s);
    float m = s / ND;
    float var = 0.f;
    #pragma unroll
    for (int j = 0; j < 8; j++) { float d = v[j] - m; var += d * d; }
    var = blockReduceSum(var);
    float inv = rsqrtf(var / ND + 1e-5f);
    #pragma unroll
    for (int j = 0; j < 8; j++) {
        int d = tid + j * 256;
        v[j] = (v[j] - m) * inv * g_syn[d] + be_syn[d];
    }
    s = 0.f;
    #pragma unroll
    for (int j = 0; j < 8; j++) s += v[j];
    s = blockReduceSum(s);
    float m2 = s / ND;
    var = 0.f;
    #pragma unroll
    for (int j = 0; j < 8; j++) { float d = v[j] - m2; var += d * d; }
    var = blockReduceSum(var);
    float inv2 = rsqrtf(var / ND + 1e-5f);
    #pragma unroll
    for (int j = 0; j < 8; j++) {
        int d = tid + j * 256;
        buf_hpm[(size_t)b * ND + d] = (v[j] - m2) * inv2 * g_pm[d] + be_pm[d];
    }
}

// ---------------- pred reduce + entropy + writes ----------------
__global__ void entropy_write(const float* __restrict__ b_out, float* __restrict__ dout, int t) {
    int b = blockIdx.x, tid = threadIdx.x;
    __shared__ float sp[NOUT];
    for (int i = tid; i < NOUT; i += 256) {
        float v = b_out[i];
        #pragma unroll
        for (int s = 0; s < 4; s++) v += buf_predpart[((size_t)s * 32 + b) * NOUT + i];
        sp[i] = v;
    }
    __syncthreads();
    float m = -1e30f;
    for (int i = tid; i < NOUT; i += 256) m = fmaxf(m, sp[i]);
    m = blockReduceMax(m);
    float s = 0.f;
    for (int i = tid; i < NOUT; i += 256) s += expf(sp[i] - m);
    s = blockReduceSum(s);
    float lse = m + logf(s);
    float ent = 0.f;
    for (int i = tid; i < NOUT; i += 256) {
        float pv = sp[i];
        float lp = pv - lse;
        ent += expf(lp) * lp;
        dout[(size_t)b * NOUT * NSTEP + (size_t)i * NSTEP + t] = pv;
    }
    ent = blockReduceSum(ent);
    if (tid == 0) {
        float ne = -ent / logf((float)NOUT);
        dout[CERT_BASE + b * (2 * NSTEP) + t] = ne;
        dout[CERT_BASE + b * (2 * NSTEP) + NSTEP + t] = 1.f - ne;
    }
}

// ---------------- launch ----------------
extern "C" void kernel_launch(void* const* d_in, const int* in_sizes, int n_in,
                              void* d_out, int out_size) {
    const float* x     = (const float*)d_in[0];
    const float* W_kv  = (const float*)d_in[1];
    const float* b_kv  = (const float*)d_in[2];
    const float* g_kv  = (const float*)d_in[3];
    const float* be_kv = (const float*)d_in[4];
    const float* W_q   = (const float*)d_in[5];
    const float* b_q   = (const float*)d_in[6];
    const float* W_in  = (const float*)d_in[7];
    const float* b_in  = (const float*)d_in[8];
    const float* W_ao  = (const float*)d_in[9];
    const float* b_ao  = (const float*)d_in[10];
    const float* W_syn = (const float*)d_in[11];
    const float* b_syn = (const float*)d_in[12];
    const float* g_syn = (const float*)d_in[13];
    const float* be_syn= (const float*)d_in[14];
    const float* g_pm  = (const float*)d_in[15];
    const float* be_pm = (const float*)d_in[16];
    const float* W1    = (const float*)d_in[17];
    const float* b1    = (const float*)d_in[18];
    const float* W2    = (const float*)d_in[19];
    const float* b2    = (const float*)d_in[20];
    const float* start = (const float*)d_in[21];
    const float* dec_a = (const float*)d_in[22];
    const float* dec_o = (const float*)d_in[23];
    const float* W_out = (const float*)d_in[24];
    const float* b_out = (const float*)d_in[25];
    const int*   idx_a = (const int*)d_in[26];
    const int*   idx_o = (const int*)d_in[27];
    float* out = (float*)d_out;

    float *p_kv, *p_Wqq, *p_act, *p_hpm, *p_t1, *p_attno;
    bf16 *p_Kh, *p_Vh;
    bf162 *p_syn_hi, *p_syn_lo, *p_w1_hi, *p_w1_lo, *p_w2_hi, *p_w2_lo;
    float *p_aA, *p_bA, *p_aO, *p_bO;
    float *p_qpart, *p_attnopart, *p_hpart, *p_w1part, *p_w2part, *p_predpart;
    cudaGetSymbolAddress((void**)&p_kv,    buf_kv);
    cudaGetSymbolAddress((void**)&p_Kh,    buf_Kh);
    cudaGetSymbolAddress((void**)&p_Vh,    buf_Vh);
    cudaGetSymbolAddress((void**)&p_Wqq,   buf_Wqq);
    cudaGetSymbolAddress((void**)&p_act,   buf_act);
    cudaGetSymbolAddress((void**)&p_hpm,   buf_hpm);
    cudaGetSymbolAddress((void**)&p_t1,    buf_t1);
    cudaGetSymbolAddress((void**)&p_attno, buf_attno);
    cudaGetSymbolAddress((void**)&p_aA,    buf_aA);
    cudaGetSymbolAddress((void**)&p_bA,    buf_bA);
    cudaGetSymbolAddress((void**)&p_aO,    buf_aO);
    cudaGetSymbolAddress((void**)&p_bO,    buf_bO);
    cudaGetSymbolAddress((void**)&p_syn_hi, w_syn_hi);
    cudaGetSymbolAddress((void**)&p_syn_lo, w_syn_lo);
    cudaGetSymbolAddress((void**)&p_w1_hi,  w_1_hi);
    cudaGetSymbolAddress((void**)&p_w1_lo,  w_1_lo);
    cudaGetSymbolAddress((void**)&p_w2_hi,  w_2_hi);
    cudaGetSymbolAddress((void**)&p_w2_lo,  w_2_lo);
    cudaGetSymbolAddress((void**)&p_qpart,     buf_qpart);
    cudaGetSymbolAddress((void**)&p_attnopart, buf_attnopart);
    cudaGetSymbolAddress((void**)&p_hpart,     buf_hpart);
    cudaGetSymbolAddress((void**)&p_w1part,    buf_w1part);
    cudaGetSymbolAddress((void**)&p_w2part,    buf_w2part);
    cudaGetSymbolAddress((void**)&p_predpart,  buf_predpart);

    // ---- precompute ----
    gemm_at_tf32<<<dim3(NE / 64, (NB * NT) / 128), 256>>>(x, W_kv, NE, b_kv, p_kv, NE, NC);
    ln_rows<<<NB * NT, 256>>>(p_kv, NE, g_kv, be_kv);
    gemm_tf32<<<dim3(NE / 64, (NB * NT) / 128), 256>>>(p_kv, NE, W_in + NE,     3 * NE, b_in + NE,
                                                       (float*)0, p_Kh, NE, NE, 1);
    gemm_tf32<<<dim3(NE / 64, (NB * NT) / 128), 256>>>(p_kv, NE, W_in + 2 * NE, 3 * NE, b_in + 2 * NE,
                                                       (float*)0, p_Vh, NE, NE, 2);
    gemm_tf32<<<dim3(NE / 64, NE / 128), 256>>>(W_q, NE, W_in, 3 * NE, (const float*)0,
                                                p_Wqq, (bf16*)0, NE, NE, 0);
    make_bqq<<<2, 256>>>(b_q, W_in, b_in);
    init_state<<<(NB * ND + 255) / 256, 256>>>(start);
    {
        int n1 = ((NE + ND) / 2) * (2 * ND);
        split_w<<<(n1 + 255) / 256, 256>>>(W_syn, 2 * ND, p_syn_hi, p_syn_lo, n1);
        int n2 = (ND / 2) * ND;
        split_w<<<(n2 + 255) / 256, 256>>>(W1, ND, p_w1_hi, p_w1_lo, n2);
        split_w<<<(n2 + 255) / 256, 256>>>(W2, ND, p_w2_hi, p_w2_lo, n2);
    }

    // ---- recurrent loop: 12 nodes/step, single stream ----
    for (int t = 0; t < NSTEP; t++) {
        const int pi = (t & 1) * NB * 512, po = ((t + 1) & 1) * NB * 512;
        // 1. q partials (fused syncA)
        skinny_fused<<<dim3(8, 8), 256>>>(1, p_act, ND, idx_a, dec_a,
                                          p_aA + pi, p_bA + pi, p_aA + po, p_bA + po,
                                          (float*)0, p_Wqq, NE, p_qpart, NE, 64);
        // 2. attention partials (vectorized bf162)
        attn_partial<<<NB * NH * 8, 256>>>();
        // 3. attno partials (fused combine)
        skinny_fused<<<dim3(8, 8), 256>>>(2, (const float*)0, 0, (const int*)0, (const float*)0,
                                          (const float*)0, (const float*)0, (float*)0, (float*)0,
                                          (float*)0, W_ao, NE, p_attnopart, NE, 64);
        // 4. attno reduce
        reduce_rows<<<(32 * NE + 255) / 256, 256>>>(p_attnopart, b_ao, p_attno, NE, 8, 0);
        // 5. h partials: [attno|act] @ W_syn   (bf16x3 tensor-core, 10 splits)
        skinny_mma<<<dim3((2 * ND) / 64, 10), 256>>>(p_attno, NE, p_act, ND,
                                                     p_syn_hi, p_syn_lo, 2 * ND,
                                                     p_hpart, 2 * ND);
        // 6. GLU + double LN (10-way reduce)
        glu_ln_ln<<<NB, 256>>>(b_syn, g_syn, be_syn, g_pm, be_pm);
        // 7. W1 partials (bf16x3, 8 splits)
        skinny_mma<<<dim3(ND / 64, 8), 256>>>(p_hpm, ND, (const float*)0, 0,
                                              p_w1_hi, p_w1_lo, ND,
                                              p_w1part, ND);
        // 8. W1 reduce + relu
        reduce_rows<<<(32 * ND + 255) / 256, 256>>>(p_w1part, b1, p_t1, ND, 8, 1);
        // 9. W2 partials (bf16x3, 8 splits)
        skinny_mma<<<dim3(ND / 64, 8), 256>>>(p_t1, ND, (const float*)0, 0,
                                              p_w2_hi, p_w2_lo, ND,
                                              p_w2part, ND);
        // 10. W2 reduce + relu -> act
        reduce_rows<<<(32 * ND + 255) / 256, 256>>>(p_w2part, b2, p_act, ND, 8, 1);
        // 11. pred partials (fused syncO)
        skinny_fused<<<dim3(16, 4), 256>>>(5, p_act, ND, idx_o, dec_o,
                                           p_aO + pi, p_bO + pi, p_aO + po, p_bO + po,
                                           (t == NSTEP - 1) ? (out + SYNC_BASE) : (float*)0,
                                           W_out, NOUT, p_predpart, NOUT, 128);
        // 12. entropy + prediction writes
        entropy_write<<<NB, 256>>>(b_out, out, t);
    }
}